// round 1
// baseline (speedup 1.0000x reference)
#include <cuda_runtime.h>
#include <cuda_bf16.h>

// Problem constants (fixed by the reference)
#define B_   2
#define T_   2048
#define C_   1024
#define H_   16
#define HS_  64
#define C3_  3072
#define BT_  (B_*T_)          // 4096 rows

// Scratch (device globals — no runtime allocation allowed)
__device__ float g_qkv[(size_t)BT_ * C3_];  // [B*T, 3C] : rows = [q | k | v]
__device__ float g_y  [(size_t)BT_ * C_];   // attention output, [B*T, C]

// ---------------------------------------------------------------------------
// SGEMM: C[M,N] = A[M,K] @ B[K,N] (+ bias). Row-major everywhere.
// 128x128 tile, BK=8, 8x8 per-thread micro-tile, 256 threads.
// Dims are exact multiples of tiles for this problem — no bounds checks.
// ---------------------------------------------------------------------------
template<bool BIAS>
__global__ __launch_bounds__(256)
void sgemm128(const float* __restrict__ A, const float* __restrict__ Bm,
              const float* __restrict__ bias, float* __restrict__ Cc,
              int M, int N, int K)
{
    constexpr int BM = 128, BN = 128, BK = 8, TM = 8, TN = 8;
    __shared__ float As[BK][BM];
    __shared__ float Bs[BK][BN];

    const int tid = threadIdx.x;
    const int bx = blockIdx.x, by = blockIdx.y;

    const int tx = tid % (BN / TN);   // 0..15
    const int ty = tid / (BN / TN);   // 0..15

    // A-tile loader: 128 rows x 8 cols -> one float4 per thread along K
    const int arow  = tid >> 1;             // 0..127
    const int acol4 = (tid & 1) * 4;        // 0 or 4
    // B-tile loader: 8 rows x 128 cols -> one float4 per thread along N
    const int brow  = tid >> 5;             // 0..7
    const int bcol4 = (tid & 31) * 4;       // 0..124

    const float* Ap = A  + (size_t)(by * BM + arow) * K + acol4;
    const float* Bp = Bm + (size_t)brow * N + bx * BN + bcol4;

    float acc[TM][TN] = {};

    for (int k0 = 0; k0 < K; k0 += BK) {
        float4 av = *(const float4*)(Ap + k0);
        As[acol4 + 0][arow] = av.x;
        As[acol4 + 1][arow] = av.y;
        As[acol4 + 2][arow] = av.z;
        As[acol4 + 3][arow] = av.w;
        *(float4*)&Bs[brow][bcol4] = *(const float4*)(Bp + (size_t)k0 * N);
        __syncthreads();

        #pragma unroll
        for (int k = 0; k < BK; k++) {
            float am[TM], bn[TN];
            #pragma unroll
            for (int i = 0; i < TM; i++) am[i] = As[k][ty * TM + i];
            #pragma unroll
            for (int j = 0; j < TN; j++) bn[j] = Bs[k][tx * TN + j];
            #pragma unroll
            for (int i = 0; i < TM; i++)
                #pragma unroll
                for (int j = 0; j < TN; j++)
                    acc[i][j] += am[i] * bn[j];
        }
        __syncthreads();
    }

    #pragma unroll
    for (int i = 0; i < TM; i++) {
        const int row = by * BM + ty * TM + i;
        #pragma unroll
        for (int j = 0; j < TN; j += 4) {
            const int col = bx * BN + tx * TN + j;
            float4 v;
            v.x = acc[i][j + 0]; v.y = acc[i][j + 1];
            v.z = acc[i][j + 2]; v.w = acc[i][j + 3];
            if (BIAS) {
                v.x += bias[col + 0]; v.y += bias[col + 1];
                v.z += bias[col + 2]; v.w += bias[col + 3];
            }
            *(float4*)&Cc[(size_t)row * N + col] = v;
        }
    }
}

// ---------------------------------------------------------------------------
// Causal flash attention (fp32, online softmax).
// One CTA per (b, h, q-tile of 64). 64 threads; thread = one q row.
// q[64] and O[64] live in registers; K/V tiles (64x64) + S scores in smem.
// Smem reads in the hot loops are warp-broadcast (all lanes read the same
// K/V row element) -> conflict-free. S buffer padded to stride 65.
// ---------------------------------------------------------------------------
__global__ __launch_bounds__(64)
void attn_kernel(const float* __restrict__ qkv, float* __restrict__ y)
{
    extern __shared__ float sm[];
    float* Ks = sm;                 // 64*64
    float* Vs = sm + 64 * 64;       // 64*64
    float* Ss = sm + 2 * 64 * 64;   // 64*65 (padded)

    const int qt  = gridDim.x - 1 - blockIdx.x;  // heavy tiles first
    const int h   = blockIdx.y;
    const int b   = blockIdx.z;
    const int tid = threadIdx.x;                 // 0..63
    const int r   = qt * 64 + tid;               // global q row in [0,T)

    const float* base = qkv + (size_t)b * T_ * C3_ + h * HS_;

    // Load q row, pre-scaled by 1/sqrt(hs) = 1/8
    float q[64];
    #pragma unroll
    for (int d = 0; d < 64; d += 4) {
        float4 v = *(const float4*)(base + (size_t)r * C3_ + d);
        q[d + 0] = v.x * 0.125f; q[d + 1] = v.y * 0.125f;
        q[d + 2] = v.z * 0.125f; q[d + 3] = v.w * 0.125f;
    }

    float O[64];
    #pragma unroll
    for (int d = 0; d < 64; d++) O[d] = 0.f;
    float m = -1e30f, l = 0.f;

    for (int kt = 0; kt <= qt; kt++) {
        // Stage K and V tiles: thread tid loads row tid (16 float4 each)
        const float* kp = base + (size_t)(kt * 64 + tid) * C3_ + C_;
        const float* vp = kp + C_;
        #pragma unroll
        for (int d = 0; d < 64; d += 4) {
            *(float4*)&Ks[tid * 64 + d] = *(const float4*)(kp + d);
            *(float4*)&Vs[tid * 64 + d] = *(const float4*)(vp + d);
        }
        __syncthreads();

        const int jmax = (kt == qt) ? tid : 63;   // causal bound

        // Pass 1: scores + tile max
        float tmax = -1e30f;
        for (int j = 0; j <= jmax; j++) {
            const float4* kr = (const float4*)(Ks + j * 64);
            float s = 0.f;
            #pragma unroll
            for (int d4 = 0; d4 < 16; d4++) {
                float4 kv = kr[d4];
                s += q[4*d4+0]*kv.x + q[4*d4+1]*kv.y
                   + q[4*d4+2]*kv.z + q[4*d4+3]*kv.w;
            }
            Ss[tid * 65 + j] = s;
            tmax = fmaxf(tmax, s);
        }

        // Online-softmax rescale
        const float mn    = fmaxf(m, tmax);
        const float alpha = __expf(m - mn);
        m = mn;
        l *= alpha;
        #pragma unroll
        for (int d = 0; d < 64; d++) O[d] *= alpha;

        // Pass 2: P @ V accumulation
        for (int j = 0; j <= jmax; j++) {
            const float p = __expf(Ss[tid * 65 + j] - mn);
            l += p;
            const float4* vr = (const float4*)(Vs + j * 64);
            #pragma unroll
            for (int d4 = 0; d4 < 16; d4++) {
                float4 vv = vr[d4];
                O[4*d4+0] += p * vv.x; O[4*d4+1] += p * vv.y;
                O[4*d4+2] += p * vv.z; O[4*d4+3] += p * vv.w;
            }
        }
        __syncthreads();
    }

    const float inv = 1.f / l;
    float* yp = y + (size_t)(b * T_ + r) * C_ + h * HS_;
    #pragma unroll
    for (int d = 0; d < 64; d += 4) {
        float4 v;
        v.x = O[d+0]*inv; v.y = O[d+1]*inv; v.z = O[d+2]*inv; v.w = O[d+3]*inv;
        *(float4*)&yp[d] = v;
    }
}

// ---------------------------------------------------------------------------
extern "C" void kernel_launch(void* const* d_in, const int* in_sizes, int n_in,
                              void* d_out, int out_size)
{
    const float* x     = (const float*)d_in[0];   // (B,T,C)
    const float* wkqv  = (const float*)d_in[1];   // (C,3C)
    const float* wproj = (const float*)d_in[2];   // (C,C)
    const float* bproj = (const float*)d_in[3];   // (C,)
    float* out = (float*)d_out;                   // (B,T,C)

    float *qkv_ptr = nullptr, *y_ptr = nullptr;
    cudaGetSymbolAddress((void**)&qkv_ptr, g_qkv);
    cudaGetSymbolAddress((void**)&y_ptr,   g_y);

    // 1) QKV GEMM: [4096,1024] @ [1024,3072] -> [4096,3072]
    {
        dim3 grid(C3_ / 128, BT_ / 128);
        sgemm128<false><<<grid, 256>>>(x, wkqv, nullptr, qkv_ptr, BT_, C3_, C_);
    }

    // 2) Causal flash attention -> g_y [4096, 1024]
    {
        const int smem = (2 * 64 * 64 + 64 * 65) * (int)sizeof(float); // 49408
        static bool attr_set = false;
        // idempotent & cheap; safe during capture (host-side attribute only)
        cudaFuncSetAttribute(attn_kernel,
                             cudaFuncAttributeMaxDynamicSharedMemorySize, smem);
        (void)attr_set;
        dim3 grid(T_ / 64, H_, B_);
        attn_kernel<<<grid, 64, smem>>>(qkv_ptr, y_ptr);
    }

    // 3) Projection: [4096,1024] @ [1024,1024] + bias -> out
    {
        dim3 grid(C_ / 128, BT_ / 128);
        sgemm128<true><<<grid, 256>>>(y_ptr, wproj, bproj, out, BT_, C_, C_);
    }
}

// round 4
// speedup vs baseline: 1.4321x; 1.4321x over previous
#include <cuda_runtime.h>
#include <cuda_bf16.h>
#include <cstdint>

// Problem constants (fixed by the reference)
#define B_   2
#define T_   2048
#define C_   1024
#define H_   16
#define HS_  64
#define C3_  3072
#define BT_  (B_*T_)          // 4096 rows
#define KK_  (3*C_)           // expanded K (hi/hi/lo folding) = 3072

// ---------------------------------------------------------------------------
// Scratch (device globals — no runtime allocation allowed)
// ---------------------------------------------------------------------------
__device__ float g_qkv[(size_t)BT_ * C3_];            // [B*T, 3C] fp32
__device__ float g_y  [(size_t)BT_ * C_];             // attention out fp32

__device__ __nv_bfloat16 g_xexp[(size_t)BT_ * KK_];   // [Ahi|Ahi|Alo] of x
__device__ __nv_bfloat16 g_yexp[(size_t)BT_ * KK_];   // [Ahi|Ahi|Alo] of y
__device__ __nv_bfloat16 g_w1e [(size_t)C3_ * KK_];   // W_kqv^T [Bhi|Blo|Bhi]
__device__ __nv_bfloat16 g_w2e [(size_t)C_  * KK_];   // W_proj^T [Bhi|Blo|Bhi]

// ---------------------------------------------------------------------------
// PTX helpers (NO 'a'-gated instructions: mma.sync / ldmatrix / cp.async only)
// ---------------------------------------------------------------------------
__device__ __forceinline__ uint32_t smem_u32(const void* p) {
    uint32_t a;
    asm("{ .reg .u64 t; cvta.to.shared.u64 t, %1; cvt.u32.u64 %0, t; }"
        : "=r"(a) : "l"(p));
    return a;
}

#define CP_ASYNC16(dst, src) \
    asm volatile("cp.async.cg.shared.global [%0], [%1], 16;" \
                 :: "r"(dst), "l"(src) : "memory")
#define CP_COMMIT() asm volatile("cp.async.commit_group;" ::: "memory")
#define CP_WAIT0()  asm volatile("cp.async.wait_group 0;" ::: "memory")
#define CP_WAIT1()  asm volatile("cp.async.wait_group 1;" ::: "memory")

#define LDSM_X4(r0, r1, r2, r3, addr) \
    asm volatile("ldmatrix.sync.aligned.m8n8.x4.shared.b16 {%0,%1,%2,%3}, [%4];" \
                 : "=r"(r0), "=r"(r1), "=r"(r2), "=r"(r3) : "r"(addr))

#define MMA16816(c, a, b0, b1) \
    asm volatile("mma.sync.aligned.m16n8k16.row.col.f32.bf16.bf16.f32 " \
                 "{%0,%1,%2,%3}, {%4,%5,%6,%7}, {%8,%9}, {%0,%1,%2,%3};" \
                 : "+f"((c)[0]), "+f"((c)[1]), "+f"((c)[2]), "+f"((c)[3]) \
                 : "r"((a)[0]), "r"((a)[1]), "r"((a)[2]), "r"((a)[3]), \
                   "r"(b0), "r"(b1))

// ---------------------------------------------------------------------------
// Prep 1: x fp32 [R, C] -> xexp bf16 [R, 3C] = [hi | hi | lo]
// ---------------------------------------------------------------------------
__global__ __launch_bounds__(256)
void split3(const float* __restrict__ in, __nv_bfloat16* __restrict__ out,
            int total4)   // total4 = R*C/4
{
    int i = blockIdx.x * blockDim.x + threadIdx.x;
    if (i >= total4) return;
    const int c4_per_row = C_ / 4;
    int r = i / c4_per_row, c = (i % c4_per_row) * 4;
    float4 v = reinterpret_cast<const float4*>(in)[i];

    __nv_bfloat16 h[4], l[4];
    float vv[4] = {v.x, v.y, v.z, v.w};
    #pragma unroll
    for (int j = 0; j < 4; j++) {
        h[j] = __float2bfloat16(vv[j]);
        l[j] = __float2bfloat16(vv[j] - __bfloat162float(h[j]));
    }
    uint2 hu, lu;
    hu.x = (uint32_t)__bfloat16_as_ushort(h[0]) | ((uint32_t)__bfloat16_as_ushort(h[1]) << 16);
    hu.y = (uint32_t)__bfloat16_as_ushort(h[2]) | ((uint32_t)__bfloat16_as_ushort(h[3]) << 16);
    lu.x = (uint32_t)__bfloat16_as_ushort(l[0]) | ((uint32_t)__bfloat16_as_ushort(l[1]) << 16);
    lu.y = (uint32_t)__bfloat16_as_ushort(l[2]) | ((uint32_t)__bfloat16_as_ushort(l[3]) << 16);

    __nv_bfloat16* row = out + (size_t)r * KK_;
    *reinterpret_cast<uint2*>(row + c)           = hu;  // seg 0: hi
    *reinterpret_cast<uint2*>(row + C_ + c)      = hu;  // seg 1: hi
    *reinterpret_cast<uint2*>(row + 2 * C_ + c)  = lu;  // seg 2: lo
}

// ---------------------------------------------------------------------------
// Prep 2: W fp32 [K, N] -> Wexp bf16 [N, 3K] = [hi | lo | hi] (transposed)
// ---------------------------------------------------------------------------
__global__ __launch_bounds__(256)
void tsplit3(const float* __restrict__ W, __nv_bfloat16* __restrict__ out,
             int K, int N)
{
    __shared__ float t[32][33];
    const int n0 = blockIdx.x * 32, k0 = blockIdx.y * 32;
    const int tx = threadIdx.x, ty = threadIdx.y;   // block (32, 8)
    #pragma unroll
    for (int r = 0; r < 4; r++)
        t[ty + 8 * r][tx] = W[(size_t)(k0 + ty + 8 * r) * N + n0 + tx];
    __syncthreads();
    #pragma unroll
    for (int r = 0; r < 4; r++) {
        float v = t[tx][ty + 8 * r];          // = W[k0+tx][n0+ty+8r]
        __nv_bfloat16 h = __float2bfloat16(v);
        __nv_bfloat16 l = __float2bfloat16(v - __bfloat162float(h));
        const int n = n0 + ty + 8 * r, k = k0 + tx;
        __nv_bfloat16* row = out + (size_t)n * (3 * K);
        row[k]         = h;   // seg 0: hi
        row[K + k]     = l;   // seg 1: lo
        row[2 * K + k] = h;   // seg 2: hi
    }
}

// ---------------------------------------------------------------------------
// bf16 mma.sync GEMM: C[M,N] = Aexp[M,KK] @ Bexp[N,KK]^T  (+ bias)
// CTA tile 128x128, BK=64, 8 warps (4x2), warp tile 32x64.
// SW128 xor swizzle, cp.async double-buffered, ldmatrix fragments.
// ---------------------------------------------------------------------------
#define GBM 128
#define GBN 128
#define GBK 64
#define STAGE_BYTES 32768   // A 16KB + B 16KB
#define SMEM_TOTAL  (2 * STAGE_BYTES)

__device__ __forceinline__ void load_tile_async(
    uint32_t s_base, const __nv_bfloat16* __restrict__ g,
    int ld, int row0, int k0, int tid)
{
    #pragma unroll
    for (int it = 0; it < 4; it++) {
        int i = tid + it * 256;                 // 0..1023
        int row = i >> 3, c = i & 7;            // 128 rows x 8 chunks of 16B
        uint32_t dst = s_base + row * 128 + (((c ^ (row & 7))) << 4);
        const __nv_bfloat16* src = g + (size_t)(row0 + row) * ld + k0 + c * 8;
        CP_ASYNC16(dst, src);
    }
}

template<bool BIAS>
__global__ __launch_bounds__(256)
void gemm_mma(const __nv_bfloat16* __restrict__ A,
              const __nv_bfloat16* __restrict__ Bt,
              const float* __restrict__ bias, float* __restrict__ C,
              int M, int N, int KK)
{
    extern __shared__ char sm[];
    const uint32_t sbase = smem_u32(sm);
    const int tid = threadIdx.x;
    const int wid = tid >> 5, lane = tid & 31;
    const int wm = wid >> 1, wn = wid & 1;        // 4 x 2 warp grid
    const int m0 = blockIdx.y * GBM, n0 = blockIdx.x * GBN;

    float acc[2][8][4];
    #pragma unroll
    for (int mt = 0; mt < 2; mt++)
        #pragma unroll
        for (int nt = 0; nt < 8; nt++)
            #pragma unroll
            for (int j = 0; j < 4; j++) acc[mt][nt][j] = 0.f;

    const int nchunks = KK / GBK;   // 48

    // Prologue: stage 0
    load_tile_async(sbase,         A,  KK, m0, 0, tid);
    load_tile_async(sbase + 16384, Bt, KK, n0, 0, tid);
    CP_COMMIT();

    // Per-lane ldmatrix offsets (stage-independent)
    // A frag (mt): lanes 0-15 -> rows m0..15 (k+0), lanes 16-31 -> same rows (k+8)
    const int a_row  = wm * 32 + (lane & 15);
    const int a_cadd = (lane >> 4);
    // B frag (ntp): lanes 0-7 n0-7/k+0, 8-15 n0-7/k+8, 16-23 n8-15/k+0, 24-31 n8-15/k+8
    const int b_row  = wn * 64 + (lane & 7) + ((lane >> 4) << 3);
    const int b_cadd = (lane >> 3) & 1;

    for (int ch = 0; ch < nchunks; ch++) {
        if (ch + 1 < nchunks) {
            const uint32_t nb = sbase + ((ch + 1) & 1) * STAGE_BYTES;
            load_tile_async(nb,         A,  KK, m0, (ch + 1) * GBK, tid);
            load_tile_async(nb + 16384, Bt, KK, n0, (ch + 1) * GBK, tid);
            CP_COMMIT();
            CP_WAIT1();
        } else {
            CP_WAIT0();
        }
        __syncthreads();

        const uint32_t sA = sbase + (ch & 1) * STAGE_BYTES;
        const uint32_t sB = sA + 16384;

        #pragma unroll
        for (int ks = 0; ks < 4; ks++) {
            uint32_t a[2][4];
            #pragma unroll
            for (int mt = 0; mt < 2; mt++) {
                const int row = a_row + mt * 16;
                const int c16 = ks * 2 + a_cadd;
                const uint32_t addr = sA + row * 128 + ((c16 ^ (row & 7)) << 4);
                LDSM_X4(a[mt][0], a[mt][1], a[mt][2], a[mt][3], addr);
            }
            uint32_t b[4][4];
            #pragma unroll
            for (int ntp = 0; ntp < 4; ntp++) {
                const int row = b_row + ntp * 16;
                const int c16 = ks * 2 + b_cadd;
                const uint32_t addr = sB + row * 128 + ((c16 ^ (row & 7)) << 4);
                // NOTE: non-trans — B stored [N,K] K-major already matches the
                // mma row.col B fragment (lane L: k=(L%4)*2+e, n=L/4).
                LDSM_X4(b[ntp][0], b[ntp][1], b[ntp][2], b[ntp][3], addr);
            }
            #pragma unroll
            for (int mt = 0; mt < 2; mt++)
                #pragma unroll
                for (int nt = 0; nt < 8; nt++)
                    MMA16816(acc[mt][nt], a[mt],
                             b[nt >> 1][(nt & 1) * 2],
                             b[nt >> 1][(nt & 1) * 2 + 1]);
        }
        __syncthreads();
    }

    // Epilogue
    const int gid = lane >> 2, tig = lane & 3;
    #pragma unroll
    for (int mt = 0; mt < 2; mt++) {
        #pragma unroll
        for (int nt = 0; nt < 8; nt++) {
            const int col = n0 + wn * 64 + nt * 8 + tig * 2;
            float bx = 0.f, by = 0.f;
            if (BIAS) { bx = bias[col]; by = bias[col + 1]; }
            const int r0 = m0 + wm * 32 + mt * 16 + gid;
            float2 v0 = { acc[mt][nt][0] + bx, acc[mt][nt][1] + by };
            float2 v1 = { acc[mt][nt][2] + bx, acc[mt][nt][3] + by };
            *reinterpret_cast<float2*>(&C[(size_t)r0 * N + col])       = v0;
            *reinterpret_cast<float2*>(&C[(size_t)(r0 + 8) * N + col]) = v1;
        }
    }
}

// ---------------------------------------------------------------------------
// Causal flash attention (fp32, online softmax) — unchanged (known good).
// ---------------------------------------------------------------------------
__global__ __launch_bounds__(64)
void attn_kernel(const float* __restrict__ qkv, float* __restrict__ y)
{
    extern __shared__ float smf[];
    float* Ks = smf;
    float* Vs = smf + 64 * 64;
    float* Ss = smf + 2 * 64 * 64;   // stride 65

    const int qt  = gridDim.x - 1 - blockIdx.x;
    const int h   = blockIdx.y;
    const int b   = blockIdx.z;
    const int tid = threadIdx.x;
    const int r   = qt * 64 + tid;

    const float* base = qkv + (size_t)b * T_ * C3_ + h * HS_;

    float q[64];
    #pragma unroll
    for (int d = 0; d < 64; d += 4) {
        float4 v = *(const float4*)(base + (size_t)r * C3_ + d);
        q[d + 0] = v.x * 0.125f; q[d + 1] = v.y * 0.125f;
        q[d + 2] = v.z * 0.125f; q[d + 3] = v.w * 0.125f;
    }

    float O[64];
    #pragma unroll
    for (int d = 0; d < 64; d++) O[d] = 0.f;
    float m = -1e30f, l = 0.f;

    for (int kt = 0; kt <= qt; kt++) {
        const float* kp = base + (size_t)(kt * 64 + tid) * C3_ + C_;
        const float* vp = kp + C_;
        #pragma unroll
        for (int d = 0; d < 64; d += 4) {
            *(float4*)&Ks[tid * 64 + d] = *(const float4*)(kp + d);
            *(float4*)&Vs[tid * 64 + d] = *(const float4*)(vp + d);
        }
        __syncthreads();

        const int jmax = (kt == qt) ? tid : 63;

        float tmax = -1e30f;
        for (int j = 0; j <= jmax; j++) {
            const float4* kr = (const float4*)(Ks + j * 64);
            float s = 0.f;
            #pragma unroll
            for (int d4 = 0; d4 < 16; d4++) {
                float4 kv = kr[d4];
                s += q[4*d4+0]*kv.x + q[4*d4+1]*kv.y
                   + q[4*d4+2]*kv.z + q[4*d4+3]*kv.w;
            }
            Ss[tid * 65 + j] = s;
            tmax = fmaxf(tmax, s);
        }

        const float mn    = fmaxf(m, tmax);
        const float alpha = __expf(m - mn);
        m = mn;
        l *= alpha;
        #pragma unroll
        for (int d = 0; d < 64; d++) O[d] *= alpha;

        for (int j = 0; j <= jmax; j++) {
            const float p = __expf(Ss[tid * 65 + j] - mn);
            l += p;
            const float4* vr = (const float4*)(Vs + j * 64);
            #pragma unroll
            for (int d4 = 0; d4 < 16; d4++) {
                float4 vv = vr[d4];
                O[4*d4+0] += p * vv.x; O[4*d4+1] += p * vv.y;
                O[4*d4+2] += p * vv.z; O[4*d4+3] += p * vv.w;
            }
        }
        __syncthreads();
    }

    const float inv = 1.f / l;
    float* yp = y + (size_t)(b * T_ + r) * C_ + h * HS_;
    #pragma unroll
    for (int d = 0; d < 64; d += 4) {
        float4 v;
        v.x = O[d+0]*inv; v.y = O[d+1]*inv; v.z = O[d+2]*inv; v.w = O[d+3]*inv;
        *(float4*)&yp[d] = v;
    }
}

// ---------------------------------------------------------------------------
extern "C" void kernel_launch(void* const* d_in, const int* in_sizes, int n_in,
                              void* d_out, int out_size)
{
    const float* x     = (const float*)d_in[0];   // (B,T,C)
    const float* wkqv  = (const float*)d_in[1];   // (C,3C)
    const float* wproj = (const float*)d_in[2];   // (C,C)
    const float* bproj = (const float*)d_in[3];   // (C,)
    float* out = (float*)d_out;                   // (B,T,C)

    float *qkv_p, *y_p;
    __nv_bfloat16 *xe, *ye, *w1e, *w2e;
    cudaGetSymbolAddress((void**)&qkv_p, g_qkv);
    cudaGetSymbolAddress((void**)&y_p,   g_y);
    cudaGetSymbolAddress((void**)&xe,    g_xexp);
    cudaGetSymbolAddress((void**)&ye,    g_yexp);
    cudaGetSymbolAddress((void**)&w1e,   g_w1e);
    cudaGetSymbolAddress((void**)&w2e,   g_w2e);

    cudaFuncSetAttribute(gemm_mma<false>,
                         cudaFuncAttributeMaxDynamicSharedMemorySize, SMEM_TOTAL);
    cudaFuncSetAttribute(gemm_mma<true>,
                         cudaFuncAttributeMaxDynamicSharedMemorySize, SMEM_TOTAL);

    // Prep: expanded bf16 operands
    split3<<<(BT_ * C_ / 4 + 255) / 256, 256>>>(x, xe, BT_ * C_ / 4);
    tsplit3<<<dim3(C3_ / 32, C_ / 32), dim3(32, 8)>>>(wkqv, w1e, C_, C3_);
    tsplit3<<<dim3(C_ / 32, C_ / 32), dim3(32, 8)>>>(wproj, w2e, C_, C_);

    // 1) QKV GEMM: [4096,3072] expanded-K bf16 -> fp32
    {
        dim3 grid(C3_ / GBN, BT_ / GBM);   // (24, 32)
        gemm_mma<false><<<grid, 256, SMEM_TOTAL>>>(xe, w1e, nullptr, qkv_p,
                                                   BT_, C3_, KK_);
    }

    // 2) Causal flash attention -> g_y
    {
        const int smem = (2 * 64 * 64 + 64 * 65) * (int)sizeof(float);
        cudaFuncSetAttribute(attn_kernel,
                             cudaFuncAttributeMaxDynamicSharedMemorySize, smem);
        dim3 grid(T_ / 64, H_, B_);
        attn_kernel<<<grid, 64, smem>>>(qkv_p, y_p);
    }

    // 3) Split y, proj GEMM + bias -> out
    split3<<<(BT_ * C_ / 4 + 255) / 256, 256>>>(y_p, ye, BT_ * C_ / 4);
    {
        dim3 grid(C_ / GBN, BT_ / GBM);    // (8, 32)
        gemm_mma<true><<<grid, 256, SMEM_TOTAL>>>(ye, w2e, bproj, out,
                                                  BT_, C_, KK_);
    }
}

// round 5
// speedup vs baseline: 4.1968x; 2.9306x over previous
#include <cuda_runtime.h>
#include <cuda_bf16.h>
#include <cstdint>
#include <cstring>

// Problem constants (fixed by the reference)
#define B_   2
#define T_   2048
#define C_   1024
#define H_   16
#define HS_  64
#define C3_  3072
#define BT_  (B_*T_)          // 4096 rows
#define KK_  (3*C_)           // expanded K (hi/hi/lo folding) = 3072

// ---------------------------------------------------------------------------
// Scratch (device globals — no runtime allocation allowed)
// ---------------------------------------------------------------------------
__device__ float g_qkv[(size_t)BT_ * C3_];            // [B*T, 3C] fp32
__device__ float g_y  [(size_t)BT_ * C_];             // attention out fp32

__device__ __nv_bfloat16 g_xexp[(size_t)BT_ * KK_];   // [Ahi|Ahi|Alo] of x
__device__ __nv_bfloat16 g_yexp[(size_t)BT_ * KK_];   // [Ahi|Ahi|Alo] of y
__device__ __nv_bfloat16 g_w1e [(size_t)C3_ * KK_];   // W_kqv^T [Bhi|Blo|Bhi]
__device__ __nv_bfloat16 g_w2e [(size_t)C_  * KK_];   // W_proj^T [Bhi|Blo|Bhi]

// per-head attention operands [B, H, T, 64] bf16
#define NHE ((size_t)B_ * H_ * T_ * 64)
__device__ __nv_bfloat16 g_qhi[NHE], g_qlo[NHE];
__device__ __nv_bfloat16 g_khi[NHE], g_klo[NHE];
__device__ __nv_bfloat16 g_vhi[NHE], g_vlo[NHE];

// ---------------------------------------------------------------------------
// PTX helpers (NO 'a'-gated instructions: mma.sync / ldmatrix / cp.async only)
// ---------------------------------------------------------------------------
__device__ __forceinline__ uint32_t smem_u32(const void* p) {
    uint32_t a;
    asm("{ .reg .u64 t; cvta.to.shared.u64 t, %1; cvt.u32.u64 %0, t; }"
        : "=r"(a) : "l"(p));
    return a;
}

#define CP_ASYNC16(dst, src) \
    asm volatile("cp.async.cg.shared.global [%0], [%1], 16;" \
                 :: "r"(dst), "l"(src) : "memory")
#define CP_COMMIT() asm volatile("cp.async.commit_group;" ::: "memory")
#define CP_WAIT0()  asm volatile("cp.async.wait_group 0;" ::: "memory")
#define CP_WAIT1()  asm volatile("cp.async.wait_group 1;" ::: "memory")

#define LDSM_X4(r0, r1, r2, r3, addr) \
    asm volatile("ldmatrix.sync.aligned.m8n8.x4.shared.b16 {%0,%1,%2,%3}, [%4];" \
                 : "=r"(r0), "=r"(r1), "=r"(r2), "=r"(r3) : "r"(addr))
#define LDSM_X4T(r0, r1, r2, r3, addr) \
    asm volatile("ldmatrix.sync.aligned.m8n8.x4.trans.shared.b16 {%0,%1,%2,%3}, [%4];" \
                 : "=r"(r0), "=r"(r1), "=r"(r2), "=r"(r3) : "r"(addr))

#define MMA16816(c, a, b0, b1) \
    asm volatile("mma.sync.aligned.m16n8k16.row.col.f32.bf16.bf16.f32 " \
                 "{%0,%1,%2,%3}, {%4,%5,%6,%7}, {%8,%9}, {%0,%1,%2,%3};" \
                 : "+f"((c)[0]), "+f"((c)[1]), "+f"((c)[2]), "+f"((c)[3]) \
                 : "r"((a)[0]), "r"((a)[1]), "r"((a)[2]), "r"((a)[3]), \
                   "r"(b0), "r"(b1))

// ---------------------------------------------------------------------------
// Prep 1: x fp32 [R, C] -> xexp bf16 [R, 3C] = [hi | hi | lo]
// ---------------------------------------------------------------------------
__global__ __launch_bounds__(256)
void split3(const float* __restrict__ in, __nv_bfloat16* __restrict__ out,
            int total4)
{
    int i = blockIdx.x * blockDim.x + threadIdx.x;
    if (i >= total4) return;
    const int c4_per_row = C_ / 4;
    int r = i / c4_per_row, c = (i % c4_per_row) * 4;
    float4 v = reinterpret_cast<const float4*>(in)[i];

    __nv_bfloat16 h[4], l[4];
    float vv[4] = {v.x, v.y, v.z, v.w};
    #pragma unroll
    for (int j = 0; j < 4; j++) {
        h[j] = __float2bfloat16(vv[j]);
        l[j] = __float2bfloat16(vv[j] - __bfloat162float(h[j]));
    }
    uint2 hu, lu;
    hu.x = (uint32_t)__bfloat16_as_ushort(h[0]) | ((uint32_t)__bfloat16_as_ushort(h[1]) << 16);
    hu.y = (uint32_t)__bfloat16_as_ushort(h[2]) | ((uint32_t)__bfloat16_as_ushort(h[3]) << 16);
    lu.x = (uint32_t)__bfloat16_as_ushort(l[0]) | ((uint32_t)__bfloat16_as_ushort(l[1]) << 16);
    lu.y = (uint32_t)__bfloat16_as_ushort(l[2]) | ((uint32_t)__bfloat16_as_ushort(l[3]) << 16);

    __nv_bfloat16* row = out + (size_t)r * KK_;
    *reinterpret_cast<uint2*>(row + c)           = hu;
    *reinterpret_cast<uint2*>(row + C_ + c)      = hu;
    *reinterpret_cast<uint2*>(row + 2 * C_ + c)  = lu;
}

// ---------------------------------------------------------------------------
// Prep 2: W fp32 [K, N] -> Wexp bf16 [N, 3K] = [hi | lo | hi] (transposed)
// ---------------------------------------------------------------------------
__global__ __launch_bounds__(256)
void tsplit3(const float* __restrict__ W, __nv_bfloat16* __restrict__ out,
             int K, int N)
{
    __shared__ float t[32][33];
    const int n0 = blockIdx.x * 32, k0 = blockIdx.y * 32;
    const int tx = threadIdx.x, ty = threadIdx.y;
    #pragma unroll
    for (int r = 0; r < 4; r++)
        t[ty + 8 * r][tx] = W[(size_t)(k0 + ty + 8 * r) * N + n0 + tx];
    __syncthreads();
    #pragma unroll
    for (int r = 0; r < 4; r++) {
        float v = t[tx][ty + 8 * r];
        __nv_bfloat16 h = __float2bfloat16(v);
        __nv_bfloat16 l = __float2bfloat16(v - __bfloat162float(h));
        const int n = n0 + ty + 8 * r, k = k0 + tx;
        __nv_bfloat16* row = out + (size_t)n * (3 * K);
        row[k]         = h;
        row[K + k]     = l;
        row[2 * K + k] = h;
    }
}

// ---------------------------------------------------------------------------
// Prep 3: g_qkv fp32 -> per-head bf16 hi/lo arrays [B,H,T,64]; q scaled 1/8.
// ---------------------------------------------------------------------------
__device__ __forceinline__ void split4(float4 v, float s, uint2& hu, uint2& lu) {
    float vv[4] = {v.x * s, v.y * s, v.z * s, v.w * s};
    __nv_bfloat16 h[4], l[4];
    #pragma unroll
    for (int j = 0; j < 4; j++) {
        h[j] = __float2bfloat16(vv[j]);
        l[j] = __float2bfloat16(vv[j] - __bfloat162float(h[j]));
    }
    hu.x = (uint32_t)__bfloat16_as_ushort(h[0]) | ((uint32_t)__bfloat16_as_ushort(h[1]) << 16);
    hu.y = (uint32_t)__bfloat16_as_ushort(h[2]) | ((uint32_t)__bfloat16_as_ushort(h[3]) << 16);
    lu.x = (uint32_t)__bfloat16_as_ushort(l[0]) | ((uint32_t)__bfloat16_as_ushort(l[1]) << 16);
    lu.y = (uint32_t)__bfloat16_as_ushort(l[2]) | ((uint32_t)__bfloat16_as_ushort(l[3]) << 16);
}

__global__ __launch_bounds__(256)
void qkv_split(const float* __restrict__ qkv,
               __nv_bfloat16* __restrict__ qhi, __nv_bfloat16* __restrict__ qlo,
               __nv_bfloat16* __restrict__ khi, __nv_bfloat16* __restrict__ klo,
               __nv_bfloat16* __restrict__ vhi, __nv_bfloat16* __restrict__ vlo)
{
    int idx = blockIdx.x * blockDim.x + threadIdx.x;   // < 2^20
    int d4 = idx & 15;
    int hh = (idx >> 4) & 15;
    int t  = (idx >> 8) & 2047;
    int bb = idx >> 19;

    const float* src = qkv + ((size_t)(bb * T_ + t)) * C3_ + hh * 64 + d4 * 4;
    float4 q = *reinterpret_cast<const float4*>(src);
    float4 k = *reinterpret_cast<const float4*>(src + C_);
    float4 v = *reinterpret_cast<const float4*>(src + 2 * C_);

    size_t o4 = ((((size_t)(bb * H_ + hh)) * T_ + t) * 64 + d4 * 4) / 4;
    uint2 hu, lu;
    split4(q, 0.125f, hu, lu);
    reinterpret_cast<uint2*>(qhi)[o4 / 1] = hu;   // o4 counts float4 groups of 4 elems
    // NOTE: uint2 = 4 bf16 elems; index = element_offset/4
    reinterpret_cast<uint2*>(qlo)[o4] = lu;
    reinterpret_cast<uint2*>(qhi)[o4] = hu;
    split4(k, 1.0f, hu, lu);
    reinterpret_cast<uint2*>(khi)[o4] = hu;
    reinterpret_cast<uint2*>(klo)[o4] = lu;
    split4(v, 1.0f, hu, lu);
    reinterpret_cast<uint2*>(vhi)[o4] = hu;
    reinterpret_cast<uint2*>(vlo)[o4] = lu;
}

// ---------------------------------------------------------------------------
// bf16 mma.sync GEMM (unchanged from Round 4 — verified correct/fast)
// ---------------------------------------------------------------------------
#define GBM 128
#define GBN 128
#define GBK 64
#define STAGE_BYTES 32768
#define SMEM_TOTAL  (2 * STAGE_BYTES)

__device__ __forceinline__ void load_tile_async(
    uint32_t s_base, const __nv_bfloat16* __restrict__ g,
    int ld, int row0, int k0, int tid)
{
    #pragma unroll
    for (int it = 0; it < 4; it++) {
        int i = tid + it * 256;
        int row = i >> 3, c = i & 7;
        uint32_t dst = s_base + row * 128 + (((c ^ (row & 7))) << 4);
        const __nv_bfloat16* src = g + (size_t)(row0 + row) * ld + k0 + c * 8;
        CP_ASYNC16(dst, src);
    }
}

template<bool BIAS>
__global__ __launch_bounds__(256)
void gemm_mma(const __nv_bfloat16* __restrict__ A,
              const __nv_bfloat16* __restrict__ Bt,
              const float* __restrict__ bias, float* __restrict__ C,
              int M, int N, int KK)
{
    extern __shared__ char sm[];
    const uint32_t sbase = smem_u32(sm);
    const int tid = threadIdx.x;
    const int wid = tid >> 5, lane = tid & 31;
    const int wm = wid >> 1, wn = wid & 1;
    const int m0 = blockIdx.y * GBM, n0 = blockIdx.x * GBN;

    float acc[2][8][4];
    #pragma unroll
    for (int mt = 0; mt < 2; mt++)
        #pragma unroll
        for (int nt = 0; nt < 8; nt++)
            #pragma unroll
            for (int j = 0; j < 4; j++) acc[mt][nt][j] = 0.f;

    const int nchunks = KK / GBK;

    load_tile_async(sbase,         A,  KK, m0, 0, tid);
    load_tile_async(sbase + 16384, Bt, KK, n0, 0, tid);
    CP_COMMIT();

    const int a_row  = wm * 32 + (lane & 15);
    const int a_cadd = (lane >> 4);
    const int b_row  = wn * 64 + (lane & 7) + ((lane >> 4) << 3);
    const int b_cadd = (lane >> 3) & 1;

    for (int ch = 0; ch < nchunks; ch++) {
        if (ch + 1 < nchunks) {
            const uint32_t nb = sbase + ((ch + 1) & 1) * STAGE_BYTES;
            load_tile_async(nb,         A,  KK, m0, (ch + 1) * GBK, tid);
            load_tile_async(nb + 16384, Bt, KK, n0, (ch + 1) * GBK, tid);
            CP_COMMIT();
            CP_WAIT1();
        } else {
            CP_WAIT0();
        }
        __syncthreads();

        const uint32_t sA = sbase + (ch & 1) * STAGE_BYTES;
        const uint32_t sB = sA + 16384;

        #pragma unroll
        for (int ks = 0; ks < 4; ks++) {
            uint32_t a[2][4];
            #pragma unroll
            for (int mt = 0; mt < 2; mt++) {
                const int row = a_row + mt * 16;
                const int c16 = ks * 2 + a_cadd;
                const uint32_t addr = sA + row * 128 + ((c16 ^ (row & 7)) << 4);
                LDSM_X4(a[mt][0], a[mt][1], a[mt][2], a[mt][3], addr);
            }
            uint32_t b[4][4];
            #pragma unroll
            for (int ntp = 0; ntp < 4; ntp++) {
                const int row = b_row + ntp * 16;
                const int c16 = ks * 2 + b_cadd;
                const uint32_t addr = sB + row * 128 + ((c16 ^ (row & 7)) << 4);
                LDSM_X4(b[ntp][0], b[ntp][1], b[ntp][2], b[ntp][3], addr);
            }
            #pragma unroll
            for (int mt = 0; mt < 2; mt++)
                #pragma unroll
                for (int nt = 0; nt < 8; nt++)
                    MMA16816(acc[mt][nt], a[mt],
                             b[nt >> 1][(nt & 1) * 2],
                             b[nt >> 1][(nt & 1) * 2 + 1]);
        }
        __syncthreads();
    }

    const int gid = lane >> 2, tig = lane & 3;
    #pragma unroll
    for (int mt = 0; mt < 2; mt++) {
        #pragma unroll
        for (int nt = 0; nt < 8; nt++) {
            const int col = n0 + wn * 64 + nt * 8 + tig * 2;
            float bx = 0.f, by = 0.f;
            if (BIAS) { bx = bias[col]; by = bias[col + 1]; }
            const int r0 = m0 + wm * 32 + mt * 16 + gid;
            float2 v0 = { acc[mt][nt][0] + bx, acc[mt][nt][1] + by };
            float2 v1 = { acc[mt][nt][2] + bx, acc[mt][nt][3] + by };
            *reinterpret_cast<float2*>(&C[(size_t)r0 * N + col])       = v0;
            *reinterpret_cast<float2*>(&C[(size_t)(r0 + 8) * N + col]) = v1;
        }
    }
}

// ---------------------------------------------------------------------------
// MMA flash attention: CTA = 128 q rows x (b,h); 8 warps x 16 rows; key tile 64.
// hi/lo 3-pass on QK and PV. Online softmax in registers.
// smem: Qhi 16K | Qlo 16K | Khi 8K | Klo 8K | Vhi 8K | Vlo 8K = 64KB
// ---------------------------------------------------------------------------
#define ATT_SMEM 65536

__global__ __launch_bounds__(256, 1)
void attn_mma(const __nv_bfloat16* __restrict__ qhi, const __nv_bfloat16* __restrict__ qlo,
              const __nv_bfloat16* __restrict__ khi, const __nv_bfloat16* __restrict__ klo,
              const __nv_bfloat16* __restrict__ vhi, const __nv_bfloat16* __restrict__ vlo,
              float* __restrict__ y)
{
    extern __shared__ char sm[];
    const uint32_t sb = smem_u32(sm);
    const uint32_t sQhi = sb,          sQlo = sb + 16384;
    const uint32_t sKhi = sb + 32768,  sKlo = sb + 40960;
    const uint32_t sVhi = sb + 49152,  sVlo = sb + 57344;

    const int tid = threadIdx.x, wid = tid >> 5, lane = tid & 31;
    const int qt = gridDim.x - 1 - blockIdx.x;    // heavy q-tiles first
    const int h = blockIdx.y, b = blockIdx.z;
    const size_t hb = ((size_t)(b * H_ + h)) * T_ * 64;

    // Stage Q tiles (hi+lo): 128 rows x 8 x 16B each
    #pragma unroll
    for (int it = 0; it < 8; it++) {
        int i = tid + (it & 3) * 256;            // 0..1023
        int row = i >> 3, c = i & 7;
        uint32_t dst = (it < 4 ? sQhi : sQlo) + row * 128 + ((c ^ (row & 7)) << 4);
        const __nv_bfloat16* src = (it < 4 ? qhi : qlo)
                                 + hb + (size_t)(qt * 128 + row) * 64 + c * 8;
        CP_ASYNC16(dst, src);
    }
    CP_COMMIT();

    const int gid = lane >> 2, tig = lane & 3;
    const int arow   = wid * 16 + (lane & 15);
    const int acadd  = lane >> 4;
    const int kbrow  = (lane & 7) + ((lane >> 4) << 3);
    const int kbcadd = (lane >> 3) & 1;
    const int vbrow  = (lane & 7) + (((lane >> 3) & 1) << 3);
    const int vbcadd = lane >> 4;

    float m0 = -1e30f, m1 = -1e30f, l0 = 0.f, l1 = 0.f;
    float O[8][4];
    #pragma unroll
    for (int d = 0; d < 8; d++)
        #pragma unroll
        for (int j = 0; j < 4; j++) O[d][j] = 0.f;

    const int rg0 = qt * 128 + wid * 16 + gid;    // this thread's first q row
    const int ktmax = 2 * (qt + 1);

    for (int kt = 0; kt < ktmax; kt++) {
        // Stage K/V tiles (4 arrays x 64 rows x 8 x 16B)
        #pragma unroll
        for (int it = 0; it < 8; it++) {
            int i = tid + (it & 1) * 256;        // 0..511
            int row = i >> 3, c = i & 7;
            uint32_t dsts = (it < 2) ? sKhi : (it < 4) ? sKlo : (it < 6) ? sVhi : sVlo;
            const __nv_bfloat16* g = (it < 2) ? khi : (it < 4) ? klo : (it < 6) ? vhi : vlo;
            uint32_t dst = dsts + row * 128 + ((c ^ (row & 7)) << 4);
            CP_ASYNC16(dst, g + hb + (size_t)(kt * 64 + row) * 64 + c * 8);
        }
        CP_COMMIT();
        CP_WAIT0();
        __syncthreads();

        // Warp-tile fully above diagonal? (first key > warp's max row)
        const bool active = (kt * 64) <= (qt * 128 + wid * 16 + 15);
        if (active) {
            // ---- S = QK^T, 3-pass hi/lo ----
            float S[8][4];
            #pragma unroll
            for (int nt = 0; nt < 8; nt++)
                #pragma unroll
                for (int j = 0; j < 4; j++) S[nt][j] = 0.f;

            #pragma unroll
            for (int ks = 0; ks < 4; ks++) {
                const int c16 = ks * 2;
                uint32_t aqh[4], aql[4];
                {
                    uint32_t ad = sQhi + arow * 128
                                + (((c16 + acadd) ^ (arow & 7)) << 4);
                    LDSM_X4(aqh[0], aqh[1], aqh[2], aqh[3], ad);
                    ad = sQlo + arow * 128 + (((c16 + acadd) ^ (arow & 7)) << 4);
                    LDSM_X4(aql[0], aql[1], aql[2], aql[3], ad);
                }
                uint32_t bh[4][4], bl[4][4];
                #pragma unroll
                for (int jn = 0; jn < 4; jn++) {
                    const int row = jn * 16 + kbrow;
                    const int cc  = c16 + kbcadd;
                    uint32_t ad = sKhi + row * 128 + ((cc ^ (row & 7)) << 4);
                    LDSM_X4(bh[jn][0], bh[jn][1], bh[jn][2], bh[jn][3], ad);
                    ad = sKlo + row * 128 + ((cc ^ (row & 7)) << 4);
                    LDSM_X4(bl[jn][0], bl[jn][1], bl[jn][2], bl[jn][3], ad);
                }
                #pragma unroll
                for (int nt = 0; nt < 8; nt++) {
                    const int jn = nt >> 1, s = (nt & 1) * 2;
                    MMA16816(S[nt], aqh, bh[jn][s], bh[jn][s + 1]);
                    MMA16816(S[nt], aqh, bl[jn][s], bl[jn][s + 1]);
                    MMA16816(S[nt], aql, bh[jn][s], bh[jn][s + 1]);
                }
            }

            // ---- causal mask (diagonal tiles only) ----
            if (kt >= 2 * qt) {
                #pragma unroll
                for (int nt = 0; nt < 8; nt++) {
                    const int jg = kt * 64 + nt * 8 + tig * 2;
                    if (jg     > rg0)     S[nt][0] = -1e30f;
                    if (jg + 1 > rg0)     S[nt][1] = -1e30f;
                    if (jg     > rg0 + 8) S[nt][2] = -1e30f;
                    if (jg + 1 > rg0 + 8) S[nt][3] = -1e30f;
                }
            }

            // ---- online softmax ----
            float t0 = -1e30f, t1 = -1e30f;
            #pragma unroll
            for (int nt = 0; nt < 8; nt++) {
                t0 = fmaxf(t0, fmaxf(S[nt][0], S[nt][1]));
                t1 = fmaxf(t1, fmaxf(S[nt][2], S[nt][3]));
            }
            t0 = fmaxf(t0, __shfl_xor_sync(0xffffffffu, t0, 1));
            t0 = fmaxf(t0, __shfl_xor_sync(0xffffffffu, t0, 2));
            t1 = fmaxf(t1, __shfl_xor_sync(0xffffffffu, t1, 1));
            t1 = fmaxf(t1, __shfl_xor_sync(0xffffffffu, t1, 2));
            const float mn0 = fmaxf(m0, t0), mn1 = fmaxf(m1, t1);
            const float a0 = __expf(m0 - mn0), a1 = __expf(m1 - mn1);
            m0 = mn0; m1 = mn1;
            l0 *= a0;  l1 *= a1;
            #pragma unroll
            for (int d = 0; d < 8; d++) {
                O[d][0] *= a0; O[d][1] *= a0;
                O[d][2] *= a1; O[d][3] *= a1;
            }

            // ---- P = exp(S-m), split hi/lo, build A-fragments ----
            uint32_t phi[4][4], plo[4][4];
            #pragma unroll
            for (int nt = 0; nt < 8; nt++) {
                const float p0 = __expf(S[nt][0] - m0);
                const float p1 = __expf(S[nt][1] - m0);
                const float p2 = __expf(S[nt][2] - m1);
                const float p3 = __expf(S[nt][3] - m1);
                l0 += p0 + p1;
                l1 += p2 + p3;
                __nv_bfloat162 h01 = __floats2bfloat162_rn(p0, p1);
                __nv_bfloat162 h23 = __floats2bfloat162_rn(p2, p3);
                __nv_bfloat162 e01 = __floats2bfloat162_rn(
                    p0 - __bfloat162float(h01.x), p1 - __bfloat162float(h01.y));
                __nv_bfloat162 e23 = __floats2bfloat162_rn(
                    p2 - __bfloat162float(h23.x), p3 - __bfloat162float(h23.y));
                const int jb = nt >> 1, o = (nt & 1) * 2;
                phi[jb][o]     = *reinterpret_cast<uint32_t*>(&h01);
                phi[jb][o + 1] = *reinterpret_cast<uint32_t*>(&h23);
                plo[jb][o]     = *reinterpret_cast<uint32_t*>(&e01);
                plo[jb][o + 1] = *reinterpret_cast<uint32_t*>(&e23);
            }

            // ---- O += P @ V, 3-pass hi/lo ----
            #pragma unroll
            for (int jb = 0; jb < 4; jb++) {
                #pragma unroll
                for (int dp = 0; dp < 4; dp++) {
                    const int row = jb * 16 + vbrow;
                    const int cc  = dp * 2 + vbcadd;
                    uint32_t vh[4], vl[4];
                    uint32_t ad = sVhi + row * 128 + ((cc ^ (row & 7)) << 4);
                    LDSM_X4T(vh[0], vh[1], vh[2], vh[3], ad);
                    ad = sVlo + row * 128 + ((cc ^ (row & 7)) << 4);
                    LDSM_X4T(vl[0], vl[1], vl[2], vl[3], ad);
                    const int d0 = dp * 2;
                    MMA16816(O[d0],     phi[jb], vh[0], vh[1]);
                    MMA16816(O[d0],     phi[jb], vl[0], vl[1]);
                    MMA16816(O[d0],     plo[jb], vh[0], vh[1]);
                    MMA16816(O[d0 + 1], phi[jb], vh[2], vh[3]);
                    MMA16816(O[d0 + 1], phi[jb], vl[2], vl[3]);
                    MMA16816(O[d0 + 1], plo[jb], vh[2], vh[3]);
                }
            }
        }
        __syncthreads();
    }

    // ---- epilogue: row-sum reduce + normalize + store ----
    l0 += __shfl_xor_sync(0xffffffffu, l0, 1);
    l0 += __shfl_xor_sync(0xffffffffu, l0, 2);
    l1 += __shfl_xor_sync(0xffffffffu, l1, 1);
    l1 += __shfl_xor_sync(0xffffffffu, l1, 2);
    const float inv0 = 1.f / l0, inv1 = 1.f / l1;

    float* y0 = y + (size_t)(b * T_ + rg0) * C_ + h * 64;
    float* y1 = y0 + (size_t)8 * C_;
    #pragma unroll
    for (int d = 0; d < 8; d++) {
        float2 v0 = { O[d][0] * inv0, O[d][1] * inv0 };
        float2 v1 = { O[d][2] * inv1, O[d][3] * inv1 };
        *reinterpret_cast<float2*>(y0 + d * 8 + tig * 2) = v0;
        *reinterpret_cast<float2*>(y1 + d * 8 + tig * 2) = v1;
    }
}

// ---------------------------------------------------------------------------
extern "C" void kernel_launch(void* const* d_in, const int* in_sizes, int n_in,
                              void* d_out, int out_size)
{
    const float* x     = (const float*)d_in[0];
    const float* wkqv  = (const float*)d_in[1];
    const float* wproj = (const float*)d_in[2];
    const float* bproj = (const float*)d_in[3];
    float* out = (float*)d_out;

    float *qkv_p, *y_p;
    __nv_bfloat16 *xe, *ye, *w1e, *w2e;
    __nv_bfloat16 *qh, *ql, *kh, *kl, *vh, *vl;
    cudaGetSymbolAddress((void**)&qkv_p, g_qkv);
    cudaGetSymbolAddress((void**)&y_p,   g_y);
    cudaGetSymbolAddress((void**)&xe,    g_xexp);
    cudaGetSymbolAddress((void**)&ye,    g_yexp);
    cudaGetSymbolAddress((void**)&w1e,   g_w1e);
    cudaGetSymbolAddress((void**)&w2e,   g_w2e);
    cudaGetSymbolAddress((void**)&qh,    g_qhi);
    cudaGetSymbolAddress((void**)&ql,    g_qlo);
    cudaGetSymbolAddress((void**)&kh,    g_khi);
    cudaGetSymbolAddress((void**)&kl,    g_klo);
    cudaGetSymbolAddress((void**)&vh,    g_vhi);
    cudaGetSymbolAddress((void**)&vl,    g_vlo);

    cudaFuncSetAttribute(gemm_mma<false>,
                         cudaFuncAttributeMaxDynamicSharedMemorySize, SMEM_TOTAL);
    cudaFuncSetAttribute(gemm_mma<true>,
                         cudaFuncAttributeMaxDynamicSharedMemorySize, SMEM_TOTAL);
    cudaFuncSetAttribute(attn_mma,
                         cudaFuncAttributeMaxDynamicSharedMemorySize, ATT_SMEM);

    // Prep: expanded bf16 operands for GEMMs
    split3<<<(BT_ * C_ / 4 + 255) / 256, 256>>>(x, xe, BT_ * C_ / 4);
    tsplit3<<<dim3(C3_ / 32, C_ / 32), dim3(32, 8)>>>(wkqv, w1e, C_, C3_);
    tsplit3<<<dim3(C_ / 32, C_ / 32), dim3(32, 8)>>>(wproj, w2e, C_, C_);

    // 1) QKV GEMM
    {
        dim3 grid(C3_ / GBN, BT_ / GBM);
        gemm_mma<false><<<grid, 256, SMEM_TOTAL>>>(xe, w1e, nullptr, qkv_p,
                                                   BT_, C3_, KK_);
    }

    // 2) Split qkv into per-head bf16 hi/lo (q pre-scaled by 1/8)
    qkv_split<<<(B_ * T_ * H_ * 16) / 256, 256>>>(qkv_p, qh, ql, kh, kl, vh, vl);

    // 3) MMA flash attention -> g_y
    {
        dim3 grid(T_ / 128, H_, B_);   // (16, 16, 2)
        attn_mma<<<grid, 256, ATT_SMEM>>>(qh, ql, kh, kl, vh, vl, y_p);
    }

    // 4) Split y, proj GEMM + bias -> out
    split3<<<(BT_ * C_ / 4 + 255) / 256, 256>>>(y_p, ye, BT_ * C_ / 4);
    {
        dim3 grid(C_ / GBN, BT_ / GBM);
        gemm_mma<true><<<grid, 256, SMEM_TOTAL>>>(ye, w2e, bproj, out,
                                                  BT_, C_, KK_);
    }
}

// round 6
// speedup vs baseline: 4.3507x; 1.0367x over previous
#include <cuda_runtime.h>
#include <cuda_bf16.h>
#include <cuda_fp16.h>
#include <cstdint>

// Problem constants (fixed by the reference)
#define B_   2
#define T_   2048
#define C_   1024
#define H_   16
#define HS_  64
#define C3_  3072
#define BT_  (B_*T_)          // 4096 rows
#define KK_  (3*C_)           // QKV expanded K (hi/hi/lo folding) = 3072
#define KP_  (2*C_)           // proj expanded K (hi/lo, fp16) = 2048

// ---------------------------------------------------------------------------
// Scratch (device globals — no runtime allocation allowed)
// ---------------------------------------------------------------------------
__device__ __nv_bfloat16 g_xexp[(size_t)BT_ * KK_];   // [Ahi|Ahi|Alo] of x
__device__ __nv_bfloat16 g_w1e [(size_t)C3_ * KK_];   // W_kqv^T [Bhi|Blo|Bhi] bf16
__device__ __half        g_yexp[(size_t)BT_ * KP_];   // attn out [hi|lo] fp16
__device__ __half        g_w2h [(size_t)C_  * KP_];   // W_proj^T [W|W] fp16

// per-head attention operands [B, H, T, 64] bf16
#define NHE ((size_t)B_ * H_ * T_ * 64)
__device__ __nv_bfloat16 g_qhi[NHE], g_qlo[NHE];
__device__ __nv_bfloat16 g_khi[NHE], g_klo[NHE];
__device__ __nv_bfloat16 g_vhi[NHE], g_vlo[NHE];

// ---------------------------------------------------------------------------
// PTX helpers (no 'a'-gated instructions)
// ---------------------------------------------------------------------------
__device__ __forceinline__ uint32_t smem_u32(const void* p) {
    uint32_t a;
    asm("{ .reg .u64 t; cvta.to.shared.u64 t, %1; cvt.u32.u64 %0, t; }"
        : "=r"(a) : "l"(p));
    return a;
}

#define CP_ASYNC16(dst, src) \
    asm volatile("cp.async.cg.shared.global [%0], [%1], 16;" \
                 :: "r"(dst), "l"(src) : "memory")
#define CP_COMMIT() asm volatile("cp.async.commit_group;" ::: "memory")
#define CP_WAIT0()  asm volatile("cp.async.wait_group 0;" ::: "memory")
#define CP_WAIT1()  asm volatile("cp.async.wait_group 1;" ::: "memory")
#define CP_WAIT2()  asm volatile("cp.async.wait_group 2;" ::: "memory")

#define LDSM_X4(r0, r1, r2, r3, addr) \
    asm volatile("ldmatrix.sync.aligned.m8n8.x4.shared.b16 {%0,%1,%2,%3}, [%4];" \
                 : "=r"(r0), "=r"(r1), "=r"(r2), "=r"(r3) : "r"(addr))
#define LDSM_X4T(r0, r1, r2, r3, addr) \
    asm volatile("ldmatrix.sync.aligned.m8n8.x4.trans.shared.b16 {%0,%1,%2,%3}, [%4];" \
                 : "=r"(r0), "=r"(r1), "=r"(r2), "=r"(r3) : "r"(addr))

template<bool HALF>
__device__ __forceinline__ void mma_any(float* c, const uint32_t* a,
                                        uint32_t b0, uint32_t b1) {
    if (HALF)
        asm volatile("mma.sync.aligned.m16n8k16.row.col.f32.f16.f16.f32 "
                     "{%0,%1,%2,%3}, {%4,%5,%6,%7}, {%8,%9}, {%0,%1,%2,%3};"
                     : "+f"(c[0]), "+f"(c[1]), "+f"(c[2]), "+f"(c[3])
                     : "r"(a[0]), "r"(a[1]), "r"(a[2]), "r"(a[3]), "r"(b0), "r"(b1));
    else
        asm volatile("mma.sync.aligned.m16n8k16.row.col.f32.bf16.bf16.f32 "
                     "{%0,%1,%2,%3}, {%4,%5,%6,%7}, {%8,%9}, {%0,%1,%2,%3};"
                     : "+f"(c[0]), "+f"(c[1]), "+f"(c[2]), "+f"(c[3])
                     : "r"(a[0]), "r"(a[1]), "r"(a[2]), "r"(a[3]), "r"(b0), "r"(b1));
}
#define MMA16816(c, a, b0, b1) \
    asm volatile("mma.sync.aligned.m16n8k16.row.col.f32.bf16.bf16.f32 " \
                 "{%0,%1,%2,%3}, {%4,%5,%6,%7}, {%8,%9}, {%0,%1,%2,%3};" \
                 : "+f"((c)[0]), "+f"((c)[1]), "+f"((c)[2]), "+f"((c)[3]) \
                 : "r"((a)[0]), "r"((a)[1]), "r"((a)[2]), "r"((a)[3]), \
                   "r"(b0), "r"(b1))

__device__ __forceinline__ uint32_t pack_bf16(float a, float b) {
    __nv_bfloat162 t = __floats2bfloat162_rn(a, b);
    return *reinterpret_cast<uint32_t*>(&t);
}

// ---------------------------------------------------------------------------
// Prep 1: x fp32 [R, C] -> xexp bf16 [R, 3C] = [hi | hi | lo]
// ---------------------------------------------------------------------------
__global__ __launch_bounds__(256)
void split3(const float* __restrict__ in, __nv_bfloat16* __restrict__ out,
            int total4)
{
    int i = blockIdx.x * blockDim.x + threadIdx.x;
    if (i >= total4) return;
    const int c4_per_row = C_ / 4;
    int r = i / c4_per_row, c = (i % c4_per_row) * 4;
    float4 v = reinterpret_cast<const float4*>(in)[i];

    __nv_bfloat16 h[4], l[4];
    float vv[4] = {v.x, v.y, v.z, v.w};
    #pragma unroll
    for (int j = 0; j < 4; j++) {
        h[j] = __float2bfloat16(vv[j]);
        l[j] = __float2bfloat16(vv[j] - __bfloat162float(h[j]));
    }
    uint2 hu, lu;
    hu.x = (uint32_t)__bfloat16_as_ushort(h[0]) | ((uint32_t)__bfloat16_as_ushort(h[1]) << 16);
    hu.y = (uint32_t)__bfloat16_as_ushort(h[2]) | ((uint32_t)__bfloat16_as_ushort(h[3]) << 16);
    lu.x = (uint32_t)__bfloat16_as_ushort(l[0]) | ((uint32_t)__bfloat16_as_ushort(l[1]) << 16);
    lu.y = (uint32_t)__bfloat16_as_ushort(l[2]) | ((uint32_t)__bfloat16_as_ushort(l[3]) << 16);

    __nv_bfloat16* row = out + (size_t)r * KK_;
    *reinterpret_cast<uint2*>(row + c)          = hu;
    *reinterpret_cast<uint2*>(row + C_ + c)     = hu;
    *reinterpret_cast<uint2*>(row + 2 * C_ + c) = lu;
}

// ---------------------------------------------------------------------------
// Prep 2a: W_kqv fp32 [K,N] -> [N,3K] bf16 = [hi | lo | hi] (transposed)
// ---------------------------------------------------------------------------
__global__ __launch_bounds__(256)
void tsplit3(const float* __restrict__ W, __nv_bfloat16* __restrict__ out,
             int K, int N)
{
    __shared__ float t[32][33];
    const int n0 = blockIdx.x * 32, k0 = blockIdx.y * 32;
    const int tx = threadIdx.x, ty = threadIdx.y;
    #pragma unroll
    for (int r = 0; r < 4; r++)
        t[ty + 8 * r][tx] = W[(size_t)(k0 + ty + 8 * r) * N + n0 + tx];
    __syncthreads();
    #pragma unroll
    for (int r = 0; r < 4; r++) {
        float v = t[tx][ty + 8 * r];
        __nv_bfloat16 h = __float2bfloat16(v);
        __nv_bfloat16 l = __float2bfloat16(v - __bfloat162float(h));
        const int n = n0 + ty + 8 * r, k = k0 + tx;
        __nv_bfloat16* row = out + (size_t)n * (3 * K);
        row[k]         = h;
        row[K + k]     = l;
        row[2 * K + k] = h;
    }
}

// ---------------------------------------------------------------------------
// Prep 2b: W_proj fp32 [K,N] -> [N,2K] fp16 = [W | W] (transposed, duplicated)
// ---------------------------------------------------------------------------
__global__ __launch_bounds__(256)
void tsplit2h(const float* __restrict__ W, __half* __restrict__ out,
              int K, int N)
{
    __shared__ float t[32][33];
    const int n0 = blockIdx.x * 32, k0 = blockIdx.y * 32;
    const int tx = threadIdx.x, ty = threadIdx.y;
    #pragma unroll
    for (int r = 0; r < 4; r++)
        t[ty + 8 * r][tx] = W[(size_t)(k0 + ty + 8 * r) * N + n0 + tx];
    __syncthreads();
    #pragma unroll
    for (int r = 0; r < 4; r++) {
        __half h = __float2half(t[tx][ty + 8 * r]);
        const int n = n0 + ty + 8 * r, k = k0 + tx;
        __half* row = out + (size_t)n * (2 * K);
        row[k]     = h;
        row[K + k] = h;
    }
}

// ---------------------------------------------------------------------------
// mma.sync GEMM, 3-stage cp.async pipeline, templated dtype + epilogue.
// EPI 1: QKV — split accumulators into per-head bf16 hi/lo arrays (q x 1/8)
// EPI 2: proj — add bias, fp32 store
// ---------------------------------------------------------------------------
#define GBM 128
#define GBN 128
#define GBK 64
#define STAGE_BYTES 32768
#define SMEM_TOTAL  (3 * STAGE_BYTES)

__device__ __forceinline__ void load_tile_async(
    uint32_t s_base, const uint16_t* __restrict__ g,
    int ld, int row0, int k0, int tid)
{
    #pragma unroll
    for (int it = 0; it < 4; it++) {
        int i = tid + it * 256;
        int row = i >> 3, c = i & 7;
        uint32_t dst = s_base + row * 128 + (((c ^ (row & 7))) << 4);
        const uint16_t* src = g + (size_t)(row0 + row) * ld + k0 + c * 8;
        CP_ASYNC16(dst, src);
    }
}

template<int EPI, bool HALF>
__global__ __launch_bounds__(256)
void gemm_mma(const uint16_t* __restrict__ A,
              const uint16_t* __restrict__ Bt,
              const float* __restrict__ bias, float* __restrict__ C,
              __nv_bfloat16* __restrict__ qhi, __nv_bfloat16* __restrict__ qlo,
              __nv_bfloat16* __restrict__ khi, __nv_bfloat16* __restrict__ klo,
              __nv_bfloat16* __restrict__ vhi, __nv_bfloat16* __restrict__ vlo,
              int M, int N, int KK)
{
    extern __shared__ char sm[];
    const uint32_t sbase = smem_u32(sm);
    const int tid = threadIdx.x;
    const int wid = tid >> 5, lane = tid & 31;
    const int wm = wid >> 1, wn = wid & 1;
    const int m0 = blockIdx.y * GBM, n0 = blockIdx.x * GBN;

    float acc[2][8][4];
    #pragma unroll
    for (int mt = 0; mt < 2; mt++)
        #pragma unroll
        for (int nt = 0; nt < 8; nt++)
            #pragma unroll
            for (int j = 0; j < 4; j++) acc[mt][nt][j] = 0.f;

    const int nchunks = KK / GBK;

    // Prologue: stages 0,1
    load_tile_async(sbase,         A,  KK, m0, 0, tid);
    load_tile_async(sbase + 16384, Bt, KK, n0, 0, tid);
    CP_COMMIT();
    {
        const uint32_t nb = sbase + STAGE_BYTES;
        load_tile_async(nb,         A,  KK, m0, GBK, tid);
        load_tile_async(nb + 16384, Bt, KK, n0, GBK, tid);
    }
    CP_COMMIT();

    const int a_row  = wm * 32 + (lane & 15);
    const int a_cadd = (lane >> 4);
    const int b_row  = wn * 64 + (lane & 7) + ((lane >> 4) << 3);
    const int b_cadd = (lane >> 3) & 1;

    for (int ch = 0; ch < nchunks; ch++) {
        CP_WAIT1();
        __syncthreads();

        const uint32_t sA = sbase + (ch % 3) * STAGE_BYTES;
        const uint32_t sB = sA + 16384;

        #pragma unroll
        for (int ks = 0; ks < 4; ks++) {
            uint32_t a[2][4];
            #pragma unroll
            for (int mt = 0; mt < 2; mt++) {
                const int row = a_row + mt * 16;
                const int c16 = ks * 2 + a_cadd;
                const uint32_t addr = sA + row * 128 + ((c16 ^ (row & 7)) << 4);
                LDSM_X4(a[mt][0], a[mt][1], a[mt][2], a[mt][3], addr);
            }
            uint32_t b[4][4];
            #pragma unroll
            for (int ntp = 0; ntp < 4; ntp++) {
                const int row = b_row + ntp * 16;
                const int c16 = ks * 2 + b_cadd;
                const uint32_t addr = sB + row * 128 + ((c16 ^ (row & 7)) << 4);
                LDSM_X4(b[ntp][0], b[ntp][1], b[ntp][2], b[ntp][3], addr);
            }
            #pragma unroll
            for (int mt = 0; mt < 2; mt++)
                #pragma unroll
                for (int nt = 0; nt < 8; nt++)
                    mma_any<HALF>(acc[mt][nt], a[mt],
                                  b[nt >> 1][(nt & 1) * 2],
                                  b[nt >> 1][(nt & 1) * 2 + 1]);
        }

        if (ch + 2 < nchunks) {
            const uint32_t nb = sbase + ((ch + 2) % 3) * STAGE_BYTES;
            load_tile_async(nb,         A,  KK, m0, (ch + 2) * GBK, tid);
            load_tile_async(nb + 16384, Bt, KK, n0, (ch + 2) * GBK, tid);
        }
        CP_COMMIT();
    }

    const int gid = lane >> 2, tig = lane & 3;

    if (EPI == 2) {
        #pragma unroll
        for (int mt = 0; mt < 2; mt++) {
            #pragma unroll
            for (int nt = 0; nt < 8; nt++) {
                const int col = n0 + wn * 64 + nt * 8 + tig * 2;
                const float bx = bias[col], by = bias[col + 1];
                const int r0 = m0 + wm * 32 + mt * 16 + gid;
                float2 v0 = { acc[mt][nt][0] + bx, acc[mt][nt][1] + by };
                float2 v1 = { acc[mt][nt][2] + bx, acc[mt][nt][3] + by };
                *reinterpret_cast<float2*>(&C[(size_t)r0 * N + col])       = v0;
                *reinterpret_cast<float2*>(&C[(size_t)(r0 + 8) * N + col]) = v1;
            }
        }
    } else {  // EPI == 1: QKV split epilogue
        #pragma unroll
        for (int mt = 0; mt < 2; mt++) {
            #pragma unroll
            for (int nt = 0; nt < 8; nt++) {
                const int col   = n0 + wn * 64 + nt * 8 + tig * 2;
                const int which = col >> 10;            // 0=q 1=k 2=v
                const int hh    = (col >> 6) & 15;
                const int d     = col & 63;
                const float sc  = (which == 0) ? 0.125f : 1.0f;
                __nv_bfloat16* hp = (which == 0) ? qhi : (which == 1) ? khi : vhi;
                __nv_bfloat16* lp = (which == 0) ? qlo : (which == 1) ? klo : vlo;
                #pragma unroll
                for (int rr = 0; rr < 2; rr++) {
                    const int r  = m0 + wm * 32 + mt * 16 + gid + rr * 8;
                    const int bb = r >> 11, t = r & 2047;
                    const size_t off = (((size_t)(bb * 16 + hh)) * 2048 + t) * 64 + d;
                    const float v0 = acc[mt][nt][rr * 2 + 0] * sc;
                    const float v1 = acc[mt][nt][rr * 2 + 1] * sc;
                    const __nv_bfloat16 h0 = __float2bfloat16(v0);
                    const __nv_bfloat16 h1 = __float2bfloat16(v1);
                    const float e0 = v0 - __bfloat162float(h0);
                    const float e1 = v1 - __bfloat162float(h1);
                    uint32_t hw = (uint32_t)__bfloat16_as_ushort(h0)
                                | ((uint32_t)__bfloat16_as_ushort(h1) << 16);
                    uint32_t lw = (uint32_t)__bfloat16_as_ushort(__float2bfloat16(e0))
                                | ((uint32_t)__bfloat16_as_ushort(__float2bfloat16(e1)) << 16);
                    *reinterpret_cast<uint32_t*>(hp + off) = hw;
                    *reinterpret_cast<uint32_t*>(lp + off) = lw;
                }
            }
        }
    }
}

// ---------------------------------------------------------------------------
// MMA flash attention, 3-stage cp.async K/V pipeline, Q fragments hoisted.
// Output written directly as fp16 [hi | lo] expanded operand for proj GEMM.
// smem: Qhi 16K | Qlo 16K | 3 x (Khi 8K, Klo 8K, Vhi 8K, Vlo 8K) = 128KB
// ---------------------------------------------------------------------------
#define ATT_SMEM (32768 + 3 * 32768)

__device__ __forceinline__ void kv_load(uint32_t sb,
    const __nv_bfloat16* __restrict__ khi, const __nv_bfloat16* __restrict__ klo,
    const __nv_bfloat16* __restrict__ vhi, const __nv_bfloat16* __restrict__ vlo,
    size_t hb, int kt, int tid)
{
    const uint32_t stage = sb + 32768 + (kt % 3) * 32768;
    #pragma unroll
    for (int it = 0; it < 8; it++) {
        int i = tid + (it & 1) * 256;            // 0..511
        int row = i >> 3, c = i & 7;
        const __nv_bfloat16* g = (it < 2) ? khi : (it < 4) ? klo
                               : (it < 6) ? vhi : vlo;
        uint32_t dst = stage + (it >> 1) * 8192 + row * 128 + ((c ^ (row & 7)) << 4);
        CP_ASYNC16(dst, g + hb + (size_t)(kt * 64 + row) * 64 + c * 8);
    }
}

__global__ __launch_bounds__(256, 1)
void attn_mma(const __nv_bfloat16* __restrict__ qhi, const __nv_bfloat16* __restrict__ qlo,
              const __nv_bfloat16* __restrict__ khi, const __nv_bfloat16* __restrict__ klo,
              const __nv_bfloat16* __restrict__ vhi, const __nv_bfloat16* __restrict__ vlo,
              __half* __restrict__ yexp)
{
    extern __shared__ char sm[];
    const uint32_t sb = smem_u32(sm);
    const uint32_t sQhi = sb, sQlo = sb + 16384;

    const int tid = threadIdx.x, wid = tid >> 5, lane = tid & 31;
    const int qt = gridDim.x - 1 - blockIdx.x;    // heavy q-tiles first
    const int h = blockIdx.y, b = blockIdx.z;
    const size_t hb = ((size_t)(b * H_ + h)) * T_ * 64;
    const int ktmax = 2 * (qt + 1);               // >= 2

    // Stage Q tiles (hi+lo)
    #pragma unroll
    for (int it = 0; it < 8; it++) {
        int i = tid + (it & 3) * 256;
        int row = i >> 3, c = i & 7;
        uint32_t dst = (it < 4 ? sQhi : sQlo) + row * 128 + ((c ^ (row & 7)) << 4);
        const __nv_bfloat16* src = (it < 4 ? qhi : qlo)
                                 + hb + (size_t)(qt * 128 + row) * 64 + c * 8;
        CP_ASYNC16(dst, src);
    }
    CP_COMMIT();                                   // g0: Q
    kv_load(sb, khi, klo, vhi, vlo, hb, 0, tid);
    CP_COMMIT();                                   // g1: KV0
    kv_load(sb, khi, klo, vhi, vlo, hb, 1, tid);
    CP_COMMIT();                                   // g2: KV1

    const int gid = lane >> 2, tig = lane & 3;
    const int arow   = wid * 16 + (lane & 15);
    const int acadd  = lane >> 4;
    const int kbrow  = (lane & 7) + ((lane >> 4) << 3);
    const int kbcadd = (lane >> 3) & 1;
    const int vbrow  = (lane & 7) + (((lane >> 3) & 1) << 3);
    const int vbcadd = lane >> 4;

    // Q fragments (loop-invariant) — wait for g0, then hoist into registers
    CP_WAIT2();
    __syncthreads();
    uint32_t aqh[4][4], aql[4][4];
    #pragma unroll
    for (int ks = 0; ks < 4; ks++) {
        const int c16 = ks * 2 + acadd;
        uint32_t ad = sQhi + arow * 128 + ((c16 ^ (arow & 7)) << 4);
        LDSM_X4(aqh[ks][0], aqh[ks][1], aqh[ks][2], aqh[ks][3], ad);
        ad = sQlo + arow * 128 + ((c16 ^ (arow & 7)) << 4);
        LDSM_X4(aql[ks][0], aql[ks][1], aql[ks][2], aql[ks][3], ad);
    }

    float m0 = -1e30f, m1 = -1e30f, l0 = 0.f, l1 = 0.f;
    float O[8][4];
    #pragma unroll
    for (int d = 0; d < 8; d++)
        #pragma unroll
        for (int j = 0; j < 4; j++) O[d][j] = 0.f;

    const int rg0 = qt * 128 + wid * 16 + gid;

    for (int kt = 0; kt < ktmax; kt++) {
        CP_WAIT1();
        __syncthreads();

        const uint32_t stage = sb + 32768 + (kt % 3) * 32768;
        const uint32_t sKhi = stage, sKlo = stage + 8192;
        const uint32_t sVhi = stage + 16384, sVlo = stage + 24576;

        const bool active = (kt * 64) <= (qt * 128 + wid * 16 + 15);
        if (active) {
            // ---- S = QK^T, 3-pass hi/lo ----
            float S[8][4];
            #pragma unroll
            for (int nt = 0; nt < 8; nt++)
                #pragma unroll
                for (int j = 0; j < 4; j++) S[nt][j] = 0.f;

            #pragma unroll
            for (int ks = 0; ks < 4; ks++) {
                const int c16 = ks * 2;
                uint32_t bh[4][4], bl[4][4];
                #pragma unroll
                for (int jn = 0; jn < 4; jn++) {
                    const int row = jn * 16 + kbrow;
                    const int cc  = c16 + kbcadd;
                    uint32_t ad = sKhi + row * 128 + ((cc ^ (row & 7)) << 4);
                    LDSM_X4(bh[jn][0], bh[jn][1], bh[jn][2], bh[jn][3], ad);
                    ad = sKlo + row * 128 + ((cc ^ (row & 7)) << 4);
                    LDSM_X4(bl[jn][0], bl[jn][1], bl[jn][2], bl[jn][3], ad);
                }
                #pragma unroll
                for (int nt = 0; nt < 8; nt++) {
                    const int jn = nt >> 1, s = (nt & 1) * 2;
                    MMA16816(S[nt], aqh[ks], bh[jn][s], bh[jn][s + 1]);
                    MMA16816(S[nt], aqh[ks], bl[jn][s], bl[jn][s + 1]);
                    MMA16816(S[nt], aql[ks], bh[jn][s], bh[jn][s + 1]);
                }
            }

            // ---- causal mask (diagonal tiles only) ----
            if (kt >= 2 * qt) {
                #pragma unroll
                for (int nt = 0; nt < 8; nt++) {
                    const int jg = kt * 64 + nt * 8 + tig * 2;
                    if (jg     > rg0)     S[nt][0] = -1e30f;
                    if (jg + 1 > rg0)     S[nt][1] = -1e30f;
                    if (jg     > rg0 + 8) S[nt][2] = -1e30f;
                    if (jg + 1 > rg0 + 8) S[nt][3] = -1e30f;
                }
            }

            // ---- online softmax ----
            float t0 = -1e30f, t1 = -1e30f;
            #pragma unroll
            for (int nt = 0; nt < 8; nt++) {
                t0 = fmaxf(t0, fmaxf(S[nt][0], S[nt][1]));
                t1 = fmaxf(t1, fmaxf(S[nt][2], S[nt][3]));
            }
            t0 = fmaxf(t0, __shfl_xor_sync(0xffffffffu, t0, 1));
            t0 = fmaxf(t0, __shfl_xor_sync(0xffffffffu, t0, 2));
            t1 = fmaxf(t1, __shfl_xor_sync(0xffffffffu, t1, 1));
            t1 = fmaxf(t1, __shfl_xor_sync(0xffffffffu, t1, 2));
            const float mn0 = fmaxf(m0, t0), mn1 = fmaxf(m1, t1);
            const float a0 = __expf(m0 - mn0), a1 = __expf(m1 - mn1);
            m0 = mn0; m1 = mn1;
            l0 *= a0;  l1 *= a1;
            #pragma unroll
            for (int d = 0; d < 8; d++) {
                O[d][0] *= a0; O[d][1] *= a0;
                O[d][2] *= a1; O[d][3] *= a1;
            }

            // ---- P = exp(S-m), split hi/lo bf16 A-fragments ----
            uint32_t phi[4][4], plo[4][4];
            #pragma unroll
            for (int nt = 0; nt < 8; nt++) {
                const float p0 = __expf(S[nt][0] - m0);
                const float p1 = __expf(S[nt][1] - m0);
                const float p2 = __expf(S[nt][2] - m1);
                const float p3 = __expf(S[nt][3] - m1);
                l0 += p0 + p1;
                l1 += p2 + p3;
                __nv_bfloat162 h01 = __floats2bfloat162_rn(p0, p1);
                __nv_bfloat162 h23 = __floats2bfloat162_rn(p2, p3);
                __nv_bfloat162 e01 = __floats2bfloat162_rn(
                    p0 - __bfloat162float(h01.x), p1 - __bfloat162float(h01.y));
                __nv_bfloat162 e23 = __floats2bfloat162_rn(
                    p2 - __bfloat162float(h23.x), p3 - __bfloat162float(h23.y));
                const int jb = nt >> 1, o = (nt & 1) * 2;
                phi[jb][o]     = *reinterpret_cast<uint32_t*>(&h01);
                phi[jb][o + 1] = *reinterpret_cast<uint32_t*>(&h23);
                plo[jb][o]     = *reinterpret_cast<uint32_t*>(&e01);
                plo[jb][o + 1] = *reinterpret_cast<uint32_t*>(&e23);
            }

            // ---- O += P @ V, 3-pass hi/lo ----
            #pragma unroll
            for (int jb = 0; jb < 4; jb++) {
                #pragma unroll
                for (int dp = 0; dp < 4; dp++) {
                    const int row = jb * 16 + vbrow;
                    const int cc  = dp * 2 + vbcadd;
                    uint32_t vh[4], vl[4];
                    uint32_t ad = sVhi + row * 128 + ((cc ^ (row & 7)) << 4);
                    LDSM_X4T(vh[0], vh[1], vh[2], vh[3], ad);
                    ad = sVlo + row * 128 + ((cc ^ (row & 7)) << 4);
                    LDSM_X4T(vl[0], vl[1], vl[2], vl[3], ad);
                    const int d0 = dp * 2;
                    MMA16816(O[d0],     phi[jb], vh[0], vh[1]);
                    MMA16816(O[d0],     phi[jb], vl[0], vl[1]);
                    MMA16816(O[d0],     plo[jb], vh[0], vh[1]);
                    MMA16816(O[d0 + 1], phi[jb], vh[2], vh[3]);
                    MMA16816(O[d0 + 1], phi[jb], vl[2], vl[3]);
                    MMA16816(O[d0 + 1], plo[jb], vh[2], vh[3]);
                }
            }
        }

        if (kt + 2 < ktmax)
            kv_load(sb, khi, klo, vhi, vlo, hb, kt + 2, tid);
        CP_COMMIT();
        __syncthreads();   // buffer-reuse guard: next iter overwrites stage (kt+2)%3
    }

    // ---- epilogue: normalize + write fp16 [hi|lo] expanded rows ----
    l0 += __shfl_xor_sync(0xffffffffu, l0, 1);
    l0 += __shfl_xor_sync(0xffffffffu, l0, 2);
    l1 += __shfl_xor_sync(0xffffffffu, l1, 1);
    l1 += __shfl_xor_sync(0xffffffffu, l1, 2);
    const float inv0 = 1.f / l0, inv1 = 1.f / l1;

    const size_t row0 = (size_t)(b * T_ + rg0) * KP_;
    const size_t row1 = row0 + (size_t)8 * KP_;
    #pragma unroll
    for (int d = 0; d < 8; d++) {
        const int c = h * 64 + d * 8 + tig * 2;
        float v0 = O[d][0] * inv0, v1 = O[d][1] * inv0;
        float v2 = O[d][2] * inv1, v3 = O[d][3] * inv1;
        __half h0 = __float2half(v0), h1 = __float2half(v1);
        __half h2 = __float2half(v2), h3 = __float2half(v3);
        __half e0 = __float2half(v0 - __half2float(h0));
        __half e1 = __float2half(v1 - __half2float(h1));
        __half e2 = __float2half(v2 - __half2float(h2));
        __half e3 = __float2half(v3 - __half2float(h3));
        *reinterpret_cast<__half2*>(yexp + row0 + c)       = __halves2half2(h0, h1);
        *reinterpret_cast<__half2*>(yexp + row0 + C_ + c)  = __halves2half2(e0, e1);
        *reinterpret_cast<__half2*>(yexp + row1 + c)       = __halves2half2(h2, h3);
        *reinterpret_cast<__half2*>(yexp + row1 + C_ + c)  = __halves2half2(e2, e3);
    }
}

// ---------------------------------------------------------------------------
extern "C" void kernel_launch(void* const* d_in, const int* in_sizes, int n_in,
                              void* d_out, int out_size)
{
    const float* x     = (const float*)d_in[0];
    const float* wkqv  = (const float*)d_in[1];
    const float* wproj = (const float*)d_in[2];
    const float* bproj = (const float*)d_in[3];
    float* out = (float*)d_out;

    __nv_bfloat16 *xe, *w1e;
    __half *ye, *w2h;
    __nv_bfloat16 *qh, *ql, *kh, *kl, *vh, *vl;
    cudaGetSymbolAddress((void**)&xe,  g_xexp);
    cudaGetSymbolAddress((void**)&w1e, g_w1e);
    cudaGetSymbolAddress((void**)&ye,  g_yexp);
    cudaGetSymbolAddress((void**)&w2h, g_w2h);
    cudaGetSymbolAddress((void**)&qh,  g_qhi);
    cudaGetSymbolAddress((void**)&ql,  g_qlo);
    cudaGetSymbolAddress((void**)&kh,  g_khi);
    cudaGetSymbolAddress((void**)&kl,  g_klo);
    cudaGetSymbolAddress((void**)&vh,  g_vhi);
    cudaGetSymbolAddress((void**)&vl,  g_vlo);

    cudaFuncSetAttribute((const void*)gemm_mma<1, false>,
                         cudaFuncAttributeMaxDynamicSharedMemorySize, SMEM_TOTAL);
    cudaFuncSetAttribute((const void*)gemm_mma<2, true>,
                         cudaFuncAttributeMaxDynamicSharedMemorySize, SMEM_TOTAL);
    cudaFuncSetAttribute((const void*)attn_mma,
                         cudaFuncAttributeMaxDynamicSharedMemorySize, ATT_SMEM);

    // Prep
    split3<<<(BT_ * C_ / 4 + 255) / 256, 256>>>(x, xe, BT_ * C_ / 4);
    tsplit3<<<dim3(C3_ / 32, C_ / 32), dim3(32, 8)>>>(wkqv, w1e, C_, C3_);
    tsplit2h<<<dim3(C_ / 32, C_ / 32), dim3(32, 8)>>>(wproj, w2h, C_, C_);

    // 1) QKV GEMM (bf16 3-pass) with fused per-head hi/lo split epilogue
    {
        dim3 grid(C3_ / GBN, BT_ / GBM);   // (24, 32)
        gemm_mma<1, false><<<grid, 256, SMEM_TOTAL>>>(
            (const uint16_t*)xe, (const uint16_t*)w1e, nullptr, nullptr,
            qh, ql, kh, kl, vh, vl, BT_, C3_, KK_);
    }

    // 2) MMA flash attention -> g_yexp (fp16 hi/lo expanded)
    {
        dim3 grid(T_ / 128, H_, B_);       // (16, 16, 2)
        attn_mma<<<grid, 256, ATT_SMEM>>>(qh, ql, kh, kl, vh, vl, ye);
    }

    // 3) proj GEMM (fp16 2-pass) + bias -> out
    {
        dim3 grid(C_ / GBN, BT_ / GBM);    // (8, 32)
        gemm_mma<2, true><<<grid, 256, SMEM_TOTAL>>>(
            (const uint16_t*)ye, (const uint16_t*)w2h, bproj, out,
            nullptr, nullptr, nullptr, nullptr, nullptr, nullptr,
            BT_, C_, KP_);
    }
}

// round 7
// speedup vs baseline: 4.5769x; 1.0520x over previous
#include <cuda_runtime.h>
#include <cuda_bf16.h>
#include <cuda_fp16.h>
#include <cstdint>

// Problem constants (fixed by the reference)
#define B_   2
#define T_   2048
#define C_   1024
#define H_   16
#define HS_  64
#define C3_  3072
#define BT_  (B_*T_)          // 4096 rows
#define KK_  (3*C_)           // QKV expanded K (hi/hi/lo folding) = 3072
#define KP_  (2*C_)           // proj expanded K (hi/lo, fp16) = 2048

// ---------------------------------------------------------------------------
// Scratch (device globals — no runtime allocation allowed)
// ---------------------------------------------------------------------------
__device__ __nv_bfloat16 g_xexp[(size_t)BT_ * KK_];   // [Ahi|Ahi|Alo] of x
__device__ __nv_bfloat16 g_w1e [(size_t)C3_ * KK_];   // W_kqv^T [Bhi|Blo|Bhi] bf16
__device__ __half        g_yexp[(size_t)BT_ * KP_];   // attn out [hi|lo] fp16
__device__ __half        g_w2h [(size_t)C_  * KP_];   // W_proj^T [W|W] fp16

// per-head attention operands [B, H, T, 64] bf16
#define NHE ((size_t)B_ * H_ * T_ * 64)
__device__ __nv_bfloat16 g_qhi[NHE], g_qlo[NHE];
__device__ __nv_bfloat16 g_khi[NHE], g_klo[NHE];
__device__ __nv_bfloat16 g_vhi[NHE], g_vlo[NHE];

// ---------------------------------------------------------------------------
// PTX helpers (no 'a'-gated instructions)
// ---------------------------------------------------------------------------
__device__ __forceinline__ uint32_t smem_u32(const void* p) {
    uint32_t a;
    asm("{ .reg .u64 t; cvta.to.shared.u64 t, %1; cvt.u32.u64 %0, t; }"
        : "=r"(a) : "l"(p));
    return a;
}

#define CP_ASYNC16(dst, src) \
    asm volatile("cp.async.cg.shared.global [%0], [%1], 16;" \
                 :: "r"(dst), "l"(src) : "memory")
#define CP_COMMIT() asm volatile("cp.async.commit_group;" ::: "memory")
#define CP_WAIT0()  asm volatile("cp.async.wait_group 0;" ::: "memory")
#define CP_WAIT1()  asm volatile("cp.async.wait_group 1;" ::: "memory")
#define CP_WAIT2()  asm volatile("cp.async.wait_group 2;" ::: "memory")

#define LDSM_X4(r0, r1, r2, r3, addr) \
    asm volatile("ldmatrix.sync.aligned.m8n8.x4.shared.b16 {%0,%1,%2,%3}, [%4];" \
                 : "=r"(r0), "=r"(r1), "=r"(r2), "=r"(r3) : "r"(addr))
#define LDSM_X4T(r0, r1, r2, r3, addr) \
    asm volatile("ldmatrix.sync.aligned.m8n8.x4.trans.shared.b16 {%0,%1,%2,%3}, [%4];" \
                 : "=r"(r0), "=r"(r1), "=r"(r2), "=r"(r3) : "r"(addr))

template<bool HALF>
__device__ __forceinline__ void mma_any(float* c, const uint32_t* a,
                                        uint32_t b0, uint32_t b1) {
    if (HALF)
        asm volatile("mma.sync.aligned.m16n8k16.row.col.f32.f16.f16.f32 "
                     "{%0,%1,%2,%3}, {%4,%5,%6,%7}, {%8,%9}, {%0,%1,%2,%3};"
                     : "+f"(c[0]), "+f"(c[1]), "+f"(c[2]), "+f"(c[3])
                     : "r"(a[0]), "r"(a[1]), "r"(a[2]), "r"(a[3]), "r"(b0), "r"(b1));
    else
        asm volatile("mma.sync.aligned.m16n8k16.row.col.f32.bf16.bf16.f32 "
                     "{%0,%1,%2,%3}, {%4,%5,%6,%7}, {%8,%9}, {%0,%1,%2,%3};"
                     : "+f"(c[0]), "+f"(c[1]), "+f"(c[2]), "+f"(c[3])
                     : "r"(a[0]), "r"(a[1]), "r"(a[2]), "r"(a[3]), "r"(b0), "r"(b1));
}
#define MMA16816(c, a, b0, b1) \
    asm volatile("mma.sync.aligned.m16n8k16.row.col.f32.bf16.bf16.f32 " \
                 "{%0,%1,%2,%3}, {%4,%5,%6,%7}, {%8,%9}, {%0,%1,%2,%3};" \
                 : "+f"((c)[0]), "+f"((c)[1]), "+f"((c)[2]), "+f"((c)[3]) \
                 : "r"((a)[0]), "r"((a)[1]), "r"((a)[2]), "r"((a)[3]), \
                   "r"(b0), "r"(b1))

// ---------------------------------------------------------------------------
// Prep 1: x fp32 [R, C] -> xexp bf16 [R, 3C] = [hi | hi | lo]
// ---------------------------------------------------------------------------
__global__ __launch_bounds__(256)
void split3(const float* __restrict__ in, __nv_bfloat16* __restrict__ out,
            int total4)
{
    int i = blockIdx.x * blockDim.x + threadIdx.x;
    if (i >= total4) return;
    const int c4_per_row = C_ / 4;
    int r = i / c4_per_row, c = (i % c4_per_row) * 4;
    float4 v = reinterpret_cast<const float4*>(in)[i];

    __nv_bfloat16 h[4], l[4];
    float vv[4] = {v.x, v.y, v.z, v.w};
    #pragma unroll
    for (int j = 0; j < 4; j++) {
        h[j] = __float2bfloat16(vv[j]);
        l[j] = __float2bfloat16(vv[j] - __bfloat162float(h[j]));
    }
    uint2 hu, lu;
    hu.x = (uint32_t)__bfloat16_as_ushort(h[0]) | ((uint32_t)__bfloat16_as_ushort(h[1]) << 16);
    hu.y = (uint32_t)__bfloat16_as_ushort(h[2]) | ((uint32_t)__bfloat16_as_ushort(h[3]) << 16);
    lu.x = (uint32_t)__bfloat16_as_ushort(l[0]) | ((uint32_t)__bfloat16_as_ushort(l[1]) << 16);
    lu.y = (uint32_t)__bfloat16_as_ushort(l[2]) | ((uint32_t)__bfloat16_as_ushort(l[3]) << 16);

    __nv_bfloat16* row = out + (size_t)r * KK_;
    *reinterpret_cast<uint2*>(row + c)          = hu;
    *reinterpret_cast<uint2*>(row + C_ + c)     = hu;
    *reinterpret_cast<uint2*>(row + 2 * C_ + c) = lu;
}

// ---------------------------------------------------------------------------
// Prep 2a: W_kqv fp32 [K,N] -> [N,3K] bf16 = [hi | lo | hi] (transposed)
// ---------------------------------------------------------------------------
__global__ __launch_bounds__(256)
void tsplit3(const float* __restrict__ W, __nv_bfloat16* __restrict__ out,
             int K, int N)
{
    __shared__ float t[32][33];
    const int n0 = blockIdx.x * 32, k0 = blockIdx.y * 32;
    const int tx = threadIdx.x, ty = threadIdx.y;
    #pragma unroll
    for (int r = 0; r < 4; r++)
        t[ty + 8 * r][tx] = W[(size_t)(k0 + ty + 8 * r) * N + n0 + tx];
    __syncthreads();
    #pragma unroll
    for (int r = 0; r < 4; r++) {
        float v = t[tx][ty + 8 * r];
        __nv_bfloat16 h = __float2bfloat16(v);
        __nv_bfloat16 l = __float2bfloat16(v - __bfloat162float(h));
        const int n = n0 + ty + 8 * r, k = k0 + tx;
        __nv_bfloat16* row = out + (size_t)n * (3 * K);
        row[k]         = h;
        row[K + k]     = l;
        row[2 * K + k] = h;
    }
}

// ---------------------------------------------------------------------------
// Prep 2b: W_proj fp32 [K,N] -> [N,2K] fp16 = [W | W] (transposed, duplicated)
// ---------------------------------------------------------------------------
__global__ __launch_bounds__(256)
void tsplit2h(const float* __restrict__ W, __half* __restrict__ out,
              int K, int N)
{
    __shared__ float t[32][33];
    const int n0 = blockIdx.x * 32, k0 = blockIdx.y * 32;
    const int tx = threadIdx.x, ty = threadIdx.y;
    #pragma unroll
    for (int r = 0; r < 4; r++)
        t[ty + 8 * r][tx] = W[(size_t)(k0 + ty + 8 * r) * N + n0 + tx];
    __syncthreads();
    #pragma unroll
    for (int r = 0; r < 4; r++) {
        __half h = __float2half(t[tx][ty + 8 * r]);
        const int n = n0 + ty + 8 * r, k = k0 + tx;
        __half* row = out + (size_t)n * (2 * K);
        row[k]     = h;
        row[K + k] = h;
    }
}

// ---------------------------------------------------------------------------
// mma.sync GEMM, 3-stage cp.async pipeline, templated dtype + epilogue.
// __launch_bounds__(256, 2): cap at 128 regs so 2 CTAs/SM fit (the Round-6
// fused epilogue pushed regs to 144 -> occ 12.4% -> tensor 51%). Any spill
// lands in the cold epilogue tail.
// EPI 1: QKV — split accumulators into per-head bf16 hi/lo arrays (q x 1/8)
// EPI 2: proj — add bias, fp32 store
// ---------------------------------------------------------------------------
#define GBM 128
#define GBN 128
#define GBK 64
#define STAGE_BYTES 32768
#define SMEM_TOTAL  (3 * STAGE_BYTES)

__device__ __forceinline__ void load_tile_async(
    uint32_t s_base, const uint16_t* __restrict__ g,
    int ld, int row0, int k0, int tid)
{
    #pragma unroll
    for (int it = 0; it < 4; it++) {
        int i = tid + it * 256;
        int row = i >> 3, c = i & 7;
        uint32_t dst = s_base + row * 128 + (((c ^ (row & 7))) << 4);
        const uint16_t* src = g + (size_t)(row0 + row) * ld + k0 + c * 8;
        CP_ASYNC16(dst, src);
    }
}

template<int EPI, bool HALF>
__global__ __launch_bounds__(256, 2)
void gemm_mma(const uint16_t* __restrict__ A,
              const uint16_t* __restrict__ Bt,
              const float* __restrict__ bias, float* __restrict__ C,
              __nv_bfloat16* __restrict__ qhi, __nv_bfloat16* __restrict__ qlo,
              __nv_bfloat16* __restrict__ khi, __nv_bfloat16* __restrict__ klo,
              __nv_bfloat16* __restrict__ vhi, __nv_bfloat16* __restrict__ vlo,
              int M, int N, int KK)
{
    extern __shared__ char sm[];
    const uint32_t sbase = smem_u32(sm);
    const int tid = threadIdx.x;
    const int wid = tid >> 5, lane = tid & 31;
    const int wm = wid >> 1, wn = wid & 1;
    const int m0 = blockIdx.y * GBM, n0 = blockIdx.x * GBN;

    float acc[2][8][4];
    #pragma unroll
    for (int mt = 0; mt < 2; mt++)
        #pragma unroll
        for (int nt = 0; nt < 8; nt++)
            #pragma unroll
            for (int j = 0; j < 4; j++) acc[mt][nt][j] = 0.f;

    const int nchunks = KK / GBK;

    // Prologue: stages 0,1
    load_tile_async(sbase,         A,  KK, m0, 0, tid);
    load_tile_async(sbase + 16384, Bt, KK, n0, 0, tid);
    CP_COMMIT();
    {
        const uint32_t nb = sbase + STAGE_BYTES;
        load_tile_async(nb,         A,  KK, m0, GBK, tid);
        load_tile_async(nb + 16384, Bt, KK, n0, GBK, tid);
    }
    CP_COMMIT();

    const int a_row  = wm * 32 + (lane & 15);
    const int a_cadd = (lane >> 4);
    const int b_row  = wn * 64 + (lane & 7) + ((lane >> 4) << 3);
    const int b_cadd = (lane >> 3) & 1;

    for (int ch = 0; ch < nchunks; ch++) {
        CP_WAIT1();
        __syncthreads();

        const uint32_t sA = sbase + (ch % 3) * STAGE_BYTES;
        const uint32_t sB = sA + 16384;

        #pragma unroll
        for (int ks = 0; ks < 4; ks++) {
            uint32_t a[2][4];
            #pragma unroll
            for (int mt = 0; mt < 2; mt++) {
                const int row = a_row + mt * 16;
                const int c16 = ks * 2 + a_cadd;
                const uint32_t addr = sA + row * 128 + ((c16 ^ (row & 7)) << 4);
                LDSM_X4(a[mt][0], a[mt][1], a[mt][2], a[mt][3], addr);
            }
            uint32_t b[4][4];
            #pragma unroll
            for (int ntp = 0; ntp < 4; ntp++) {
                const int row = b_row + ntp * 16;
                const int c16 = ks * 2 + b_cadd;
                const uint32_t addr = sB + row * 128 + ((c16 ^ (row & 7)) << 4);
                LDSM_X4(b[ntp][0], b[ntp][1], b[ntp][2], b[ntp][3], addr);
            }
            #pragma unroll
            for (int mt = 0; mt < 2; mt++)
                #pragma unroll
                for (int nt = 0; nt < 8; nt++)
                    mma_any<HALF>(acc[mt][nt], a[mt],
                                  b[nt >> 1][(nt & 1) * 2],
                                  b[nt >> 1][(nt & 1) * 2 + 1]);
        }

        if (ch + 2 < nchunks) {
            const uint32_t nb = sbase + ((ch + 2) % 3) * STAGE_BYTES;
            load_tile_async(nb,         A,  KK, m0, (ch + 2) * GBK, tid);
            load_tile_async(nb + 16384, Bt, KK, n0, (ch + 2) * GBK, tid);
        }
        CP_COMMIT();
    }

    const int gid = lane >> 2, tig = lane & 3;

    if (EPI == 2) {
        #pragma unroll
        for (int mt = 0; mt < 2; mt++) {
            #pragma unroll
            for (int nt = 0; nt < 8; nt++) {
                const int col = n0 + wn * 64 + nt * 8 + tig * 2;
                const float bx = bias[col], by = bias[col + 1];
                const int r0 = m0 + wm * 32 + mt * 16 + gid;
                float2 v0 = { acc[mt][nt][0] + bx, acc[mt][nt][1] + by };
                float2 v1 = { acc[mt][nt][2] + bx, acc[mt][nt][3] + by };
                *reinterpret_cast<float2*>(&C[(size_t)r0 * N + col])       = v0;
                *reinterpret_cast<float2*>(&C[(size_t)(r0 + 8) * N + col]) = v1;
            }
        }
    } else {  // EPI == 1: QKV split epilogue
        #pragma unroll
        for (int mt = 0; mt < 2; mt++) {
            #pragma unroll
            for (int nt = 0; nt < 8; nt++) {
                const int col   = n0 + wn * 64 + nt * 8 + tig * 2;
                const int which = col >> 10;            // 0=q 1=k 2=v
                const int hh    = (col >> 6) & 15;
                const int d     = col & 63;
                const float sc  = (which == 0) ? 0.125f : 1.0f;
                __nv_bfloat16* hp = (which == 0) ? qhi : (which == 1) ? khi : vhi;
                __nv_bfloat16* lp = (which == 0) ? qlo : (which == 1) ? klo : vlo;
                #pragma unroll
                for (int rr = 0; rr < 2; rr++) {
                    const int r  = m0 + wm * 32 + mt * 16 + gid + rr * 8;
                    const int bb = r >> 11, t = r & 2047;
                    const size_t off = (((size_t)(bb * 16 + hh)) * 2048 + t) * 64 + d;
                    const float v0 = acc[mt][nt][rr * 2 + 0] * sc;
                    const float v1 = acc[mt][nt][rr * 2 + 1] * sc;
                    const __nv_bfloat16 h0 = __float2bfloat16(v0);
                    const __nv_bfloat16 h1 = __float2bfloat16(v1);
                    const float e0 = v0 - __bfloat162float(h0);
                    const float e1 = v1 - __bfloat162float(h1);
                    uint32_t hw = (uint32_t)__bfloat16_as_ushort(h0)
                                | ((uint32_t)__bfloat16_as_ushort(h1) << 16);
                    uint32_t lw = (uint32_t)__bfloat16_as_ushort(__float2bfloat16(e0))
                                | ((uint32_t)__bfloat16_as_ushort(__float2bfloat16(e1)) << 16);
                    *reinterpret_cast<uint32_t*>(hp + off) = hw;
                    *reinterpret_cast<uint32_t*>(lp + off) = lw;
                }
            }
        }
    }
}

// ---------------------------------------------------------------------------
// MMA flash attention, 3-stage cp.async K/V pipeline, Q fragments hoisted.
// Output written directly as fp16 [hi | lo] expanded operand for proj GEMM.
// smem: Qhi 16K | Qlo 16K | 3 x (Khi 8K, Klo 8K, Vhi 8K, Vlo 8K) = 128KB
// ---------------------------------------------------------------------------
#define ATT_SMEM (32768 + 3 * 32768)

__device__ __forceinline__ void kv_load(uint32_t sb,
    const __nv_bfloat16* __restrict__ khi, const __nv_bfloat16* __restrict__ klo,
    const __nv_bfloat16* __restrict__ vhi, const __nv_bfloat16* __restrict__ vlo,
    size_t hb, int kt, int tid)
{
    const uint32_t stage = sb + 32768 + (kt % 3) * 32768;
    #pragma unroll
    for (int it = 0; it < 8; it++) {
        int i = tid + (it & 1) * 256;            // 0..511
        int row = i >> 3, c = i & 7;
        const __nv_bfloat16* g = (it < 2) ? khi : (it < 4) ? klo
                               : (it < 6) ? vhi : vlo;
        uint32_t dst = stage + (it >> 1) * 8192 + row * 128 + ((c ^ (row & 7)) << 4);
        CP_ASYNC16(dst, g + hb + (size_t)(kt * 64 + row) * 64 + c * 8);
    }
}

__global__ __launch_bounds__(256, 1)
void attn_mma(const __nv_bfloat16* __restrict__ qhi, const __nv_bfloat16* __restrict__ qlo,
              const __nv_bfloat16* __restrict__ khi, const __nv_bfloat16* __restrict__ klo,
              const __nv_bfloat16* __restrict__ vhi, const __nv_bfloat16* __restrict__ vlo,
              __half* __restrict__ yexp)
{
    extern __shared__ char sm[];
    const uint32_t sb = smem_u32(sm);
    const uint32_t sQhi = sb, sQlo = sb + 16384;

    const int tid = threadIdx.x, wid = tid >> 5, lane = tid & 31;
    const int qt = gridDim.x - 1 - blockIdx.x;    // heavy q-tiles first
    const int h = blockIdx.y, b = blockIdx.z;
    const size_t hb = ((size_t)(b * H_ + h)) * T_ * 64;
    const int ktmax = 2 * (qt + 1);               // >= 2

    // Stage Q tiles (hi+lo)
    #pragma unroll
    for (int it = 0; it < 8; it++) {
        int i = tid + (it & 3) * 256;
        int row = i >> 3, c = i & 7;
        uint32_t dst = (it < 4 ? sQhi : sQlo) + row * 128 + ((c ^ (row & 7)) << 4);
        const __nv_bfloat16* src = (it < 4 ? qhi : qlo)
                                 + hb + (size_t)(qt * 128 + row) * 64 + c * 8;
        CP_ASYNC16(dst, src);
    }
    CP_COMMIT();                                   // g0: Q
    kv_load(sb, khi, klo, vhi, vlo, hb, 0, tid);
    CP_COMMIT();                                   // g1: KV0
    kv_load(sb, khi, klo, vhi, vlo, hb, 1, tid);
    CP_COMMIT();                                   // g2: KV1

    const int gid = lane >> 2, tig = lane & 3;
    const int arow   = wid * 16 + (lane & 15);
    const int acadd  = lane >> 4;
    const int kbrow  = (lane & 7) + ((lane >> 4) << 3);
    const int kbcadd = (lane >> 3) & 1;
    const int vbrow  = (lane & 7) + (((lane >> 3) & 1) << 3);
    const int vbcadd = lane >> 4;

    // Q fragments (loop-invariant) — wait for g0, then hoist into registers
    CP_WAIT2();
    __syncthreads();
    uint32_t aqh[4][4], aql[4][4];
    #pragma unroll
    for (int ks = 0; ks < 4; ks++) {
        const int c16 = ks * 2 + acadd;
        uint32_t ad = sQhi + arow * 128 + ((c16 ^ (arow & 7)) << 4);
        LDSM_X4(aqh[ks][0], aqh[ks][1], aqh[ks][2], aqh[ks][3], ad);
        ad = sQlo + arow * 128 + ((c16 ^ (arow & 7)) << 4);
        LDSM_X4(aql[ks][0], aql[ks][1], aql[ks][2], aql[ks][3], ad);
    }

    float m0 = -1e30f, m1 = -1e30f, l0 = 0.f, l1 = 0.f;
    float O[8][4];
    #pragma unroll
    for (int d = 0; d < 8; d++)
        #pragma unroll
        for (int j = 0; j < 4; j++) O[d][j] = 0.f;

    const int rg0 = qt * 128 + wid * 16 + gid;

    for (int kt = 0; kt < ktmax; kt++) {
        // Top barrier: after every warp's WAIT1, all of stage kt%3 is visible,
        // and all warps have finished computing on stage (kt-1)%3 — which makes
        // this iteration's kv_load into (kt+2)%3 safe without a bottom barrier.
        CP_WAIT1();
        __syncthreads();

        const uint32_t stage = sb + 32768 + (kt % 3) * 32768;
        const uint32_t sKhi = stage, sKlo = stage + 8192;
        const uint32_t sVhi = stage + 16384, sVlo = stage + 24576;

        const bool active = (kt * 64) <= (qt * 128 + wid * 16 + 15);
        if (active) {
            // ---- S = QK^T, 3-pass hi/lo ----
            float S[8][4];
            #pragma unroll
            for (int nt = 0; nt < 8; nt++)
                #pragma unroll
                for (int j = 0; j < 4; j++) S[nt][j] = 0.f;

            #pragma unroll
            for (int ks = 0; ks < 4; ks++) {
                const int c16 = ks * 2;
                uint32_t bh[4][4], bl[4][4];
                #pragma unroll
                for (int jn = 0; jn < 4; jn++) {
                    const int row = jn * 16 + kbrow;
                    const int cc  = c16 + kbcadd;
                    uint32_t ad = sKhi + row * 128 + ((cc ^ (row & 7)) << 4);
                    LDSM_X4(bh[jn][0], bh[jn][1], bh[jn][2], bh[jn][3], ad);
                    ad = sKlo + row * 128 + ((cc ^ (row & 7)) << 4);
                    LDSM_X4(bl[jn][0], bl[jn][1], bl[jn][2], bl[jn][3], ad);
                }
                #pragma unroll
                for (int nt = 0; nt < 8; nt++) {
                    const int jn = nt >> 1, s = (nt & 1) * 2;
                    MMA16816(S[nt], aqh[ks], bh[jn][s], bh[jn][s + 1]);
                    MMA16816(S[nt], aqh[ks], bl[jn][s], bl[jn][s + 1]);
                    MMA16816(S[nt], aql[ks], bh[jn][s], bh[jn][s + 1]);
                }
            }

            // ---- causal mask (diagonal tiles only) ----
            if (kt >= 2 * qt) {
                #pragma unroll
                for (int nt = 0; nt < 8; nt++) {
                    const int jg = kt * 64 + nt * 8 + tig * 2;
                    if (jg     > rg0)     S[nt][0] = -1e30f;
                    if (jg + 1 > rg0)     S[nt][1] = -1e30f;
                    if (jg     > rg0 + 8) S[nt][2] = -1e30f;
                    if (jg + 1 > rg0 + 8) S[nt][3] = -1e30f;
                }
            }

            // ---- online softmax ----
            float t0 = -1e30f, t1 = -1e30f;
            #pragma unroll
            for (int nt = 0; nt < 8; nt++) {
                t0 = fmaxf(t0, fmaxf(S[nt][0], S[nt][1]));
                t1 = fmaxf(t1, fmaxf(S[nt][2], S[nt][3]));
            }
            t0 = fmaxf(t0, __shfl_xor_sync(0xffffffffu, t0, 1));
            t0 = fmaxf(t0, __shfl_xor_sync(0xffffffffu, t0, 2));
            t1 = fmaxf(t1, __shfl_xor_sync(0xffffffffu, t1, 1));
            t1 = fmaxf(t1, __shfl_xor_sync(0xffffffffu, t1, 2));
            const float mn0 = fmaxf(m0, t0), mn1 = fmaxf(m1, t1);
            const float a0 = __expf(m0 - mn0), a1 = __expf(m1 - mn1);
            m0 = mn0; m1 = mn1;
            l0 *= a0;  l1 *= a1;
            #pragma unroll
            for (int d = 0; d < 8; d++) {
                O[d][0] *= a0; O[d][1] *= a0;
                O[d][2] *= a1; O[d][3] *= a1;
            }

            // ---- P = exp(S-m), split hi/lo bf16 A-fragments ----
            uint32_t phi[4][4], plo[4][4];
            #pragma unroll
            for (int nt = 0; nt < 8; nt++) {
                const float p0 = __expf(S[nt][0] - m0);
                const float p1 = __expf(S[nt][1] - m0);
                const float p2 = __expf(S[nt][2] - m1);
                const float p3 = __expf(S[nt][3] - m1);
                l0 += p0 + p1;
                l1 += p2 + p3;
                __nv_bfloat162 h01 = __floats2bfloat162_rn(p0, p1);
                __nv_bfloat162 h23 = __floats2bfloat162_rn(p2, p3);
                __nv_bfloat162 e01 = __floats2bfloat162_rn(
                    p0 - __bfloat162float(h01.x), p1 - __bfloat162float(h01.y));
                __nv_bfloat162 e23 = __floats2bfloat162_rn(
                    p2 - __bfloat162float(h23.x), p3 - __bfloat162float(h23.y));
                const int jb = nt >> 1, o = (nt & 1) * 2;
                phi[jb][o]     = *reinterpret_cast<uint32_t*>(&h01);
                phi[jb][o + 1] = *reinterpret_cast<uint32_t*>(&h23);
                plo[jb][o]     = *reinterpret_cast<uint32_t*>(&e01);
                plo[jb][o + 1] = *reinterpret_cast<uint32_t*>(&e23);
            }

            // ---- O += P @ V, 3-pass hi/lo ----
            #pragma unroll
            for (int jb = 0; jb < 4; jb++) {
                #pragma unroll
                for (int dp = 0; dp < 4; dp++) {
                    const int row = jb * 16 + vbrow;
                    const int cc  = dp * 2 + vbcadd;
                    uint32_t vh[4], vl[4];
                    uint32_t ad = sVhi + row * 128 + ((cc ^ (row & 7)) << 4);
                    LDSM_X4T(vh[0], vh[1], vh[2], vh[3], ad);
                    ad = sVlo + row * 128 + ((cc ^ (row & 7)) << 4);
                    LDSM_X4T(vl[0], vl[1], vl[2], vl[3], ad);
                    const int d0 = dp * 2;
                    MMA16816(O[d0],     phi[jb], vh[0], vh[1]);
                    MMA16816(O[d0],     phi[jb], vl[0], vl[1]);
                    MMA16816(O[d0],     plo[jb], vh[0], vh[1]);
                    MMA16816(O[d0 + 1], phi[jb], vh[2], vh[3]);
                    MMA16816(O[d0 + 1], phi[jb], vl[2], vl[3]);
                    MMA16816(O[d0 + 1], plo[jb], vh[2], vh[3]);
                }
            }
        }

        if (kt + 2 < ktmax)
            kv_load(sb, khi, klo, vhi, vlo, hb, kt + 2, tid);
        CP_COMMIT();
    }

    // ---- epilogue: normalize + write fp16 [hi|lo] expanded rows ----
    l0 += __shfl_xor_sync(0xffffffffu, l0, 1);
    l0 += __shfl_xor_sync(0xffffffffu, l0, 2);
    l1 += __shfl_xor_sync(0xffffffffu, l1, 1);
    l1 += __shfl_xor_sync(0xffffffffu, l1, 2);
    const float inv0 = 1.f / l0, inv1 = 1.f / l1;

    const size_t row0 = (size_t)(b * T_ + rg0) * KP_;
    const size_t row1 = row0 + (size_t)8 * KP_;
    #pragma unroll
    for (int d = 0; d < 8; d++) {
        const int c = h * 64 + d * 8 + tig * 2;
        float v0 = O[d][0] * inv0, v1 = O[d][1] * inv0;
        float v2 = O[d][2] * inv1, v3 = O[d][3] * inv1;
        __half h0 = __float2half(v0), h1 = __float2half(v1);
        __half h2 = __float2half(v2), h3 = __float2half(v3);
        __half e0 = __float2half(v0 - __half2float(h0));
        __half e1 = __float2half(v1 - __half2float(h1));
        __half e2 = __float2half(v2 - __half2float(h2));
        __half e3 = __float2half(v3 - __half2float(h3));
        *reinterpret_cast<__half2*>(yexp + row0 + c)       = __halves2half2(h0, h1);
        *reinterpret_cast<__half2*>(yexp + row0 + C_ + c)  = __halves2half2(e0, e1);
        *reinterpret_cast<__half2*>(yexp + row1 + c)       = __halves2half2(h2, h3);
        *reinterpret_cast<__half2*>(yexp + row1 + C_ + c)  = __halves2half2(e2, e3);
    }
}

// ---------------------------------------------------------------------------
extern "C" void kernel_launch(void* const* d_in, const int* in_sizes, int n_in,
                              void* d_out, int out_size)
{
    const float* x     = (const float*)d_in[0];
    const float* wkqv  = (const float*)d_in[1];
    const float* wproj = (const float*)d_in[2];
    const float* bproj = (const float*)d_in[3];
    float* out = (float*)d_out;

    __nv_bfloat16 *xe, *w1e;
    __half *ye, *w2h;
    __nv_bfloat16 *qh, *ql, *kh, *kl, *vh, *vl;
    cudaGetSymbolAddress((void**)&xe,  g_xexp);
    cudaGetSymbolAddress((void**)&w1e, g_w1e);
    cudaGetSymbolAddress((void**)&ye,  g_yexp);
    cudaGetSymbolAddress((void**)&w2h, g_w2h);
    cudaGetSymbolAddress((void**)&qh,  g_qhi);
    cudaGetSymbolAddress((void**)&ql,  g_qlo);
    cudaGetSymbolAddress((void**)&kh,  g_khi);
    cudaGetSymbolAddress((void**)&kl,  g_klo);
    cudaGetSymbolAddress((void**)&vh,  g_vhi);
    cudaGetSymbolAddress((void**)&vl,  g_vlo);

    cudaFuncSetAttribute((const void*)gemm_mma<1, false>,
                         cudaFuncAttributeMaxDynamicSharedMemorySize, SMEM_TOTAL);
    cudaFuncSetAttribute((const void*)gemm_mma<2, true>,
                         cudaFuncAttributeMaxDynamicSharedMemorySize, SMEM_TOTAL);
    cudaFuncSetAttribute((const void*)attn_mma,
                         cudaFuncAttributeMaxDynamicSharedMemorySize, ATT_SMEM);

    // Prep
    split3<<<(BT_ * C_ / 4 + 255) / 256, 256>>>(x, xe, BT_ * C_ / 4);
    tsplit3<<<dim3(C3_ / 32, C_ / 32), dim3(32, 8)>>>(wkqv, w1e, C_, C3_);
    tsplit2h<<<dim3(C_ / 32, C_ / 32), dim3(32, 8)>>>(wproj, w2h, C_, C_);

    // 1) QKV GEMM (bf16 3-pass) with fused per-head hi/lo split epilogue
    {
        dim3 grid(C3_ / GBN, BT_ / GBM);   // (24, 32)
        gemm_mma<1, false><<<grid, 256, SMEM_TOTAL>>>(
            (const uint16_t*)xe, (const uint16_t*)w1e, nullptr, nullptr,
            qh, ql, kh, kl, vh, vl, BT_, C3_, KK_);
    }

    // 2) MMA flash attention -> g_yexp (fp16 hi/lo expanded)
    {
        dim3 grid(T_ / 128, H_, B_);       // (16, 16, 2)
        attn_mma<<<grid, 256, ATT_SMEM>>>(qh, ql, kh, kl, vh, vl, ye);
    }

    // 3) proj GEMM (fp16 2-pass) + bias -> out
    {
        dim3 grid(C_ / GBN, BT_ / GBM);    // (8, 32)
        gemm_mma<2, true><<<grid, 256, SMEM_TOTAL>>>(
            (const uint16_t*)ye, (const uint16_t*)w2h, bproj, out,
            nullptr, nullptr, nullptr, nullptr, nullptr, nullptr,
            BT_, C_, KP_);
    }
}

// round 8
// speedup vs baseline: 6.0297x; 1.3174x over previous
#include <cuda_runtime.h>
#include <cuda_bf16.h>
#include <cuda_fp16.h>
#include <cstdint>

// Problem constants (fixed by the reference)
#define B_   2
#define T_   2048
#define C_   1024
#define H_   16
#define HS_  64
#define C3_  3072
#define BT_  (B_*T_)          // 4096 rows
#define KP_  (2*C_)           // expanded K (fp16 2-pass) = 2048

// ---------------------------------------------------------------------------
// Scratch (device globals — no runtime allocation allowed)
// ---------------------------------------------------------------------------
__device__ __half g_xe  [(size_t)BT_ * KP_];   // [x_hi | x_lo] fp16
__device__ __half g_w1h [(size_t)C3_ * KP_];   // W_kqv^T [W|W] fp16
__device__ __half g_yexp[(size_t)BT_ * KP_];   // attn out [hi|lo] fp16
__device__ __half g_w2h [(size_t)C_  * KP_];   // W_proj^T [W|W] fp16

// per-head attention operands [B, H, T, 64] fp16
#define NHE ((size_t)B_ * H_ * T_ * 64)
__device__ __half g_qhi[NHE], g_qlo[NHE];      // q exact (hi/lo), pre-scaled 1/8
__device__ __half g_kh [NHE], g_vh [NHE];      // k, v single fp16

// ---------------------------------------------------------------------------
// PTX helpers (no 'a'-gated instructions)
// ---------------------------------------------------------------------------
__device__ __forceinline__ uint32_t smem_u32(const void* p) {
    uint32_t a;
    asm("{ .reg .u64 t; cvta.to.shared.u64 t, %1; cvt.u32.u64 %0, t; }"
        : "=r"(a) : "l"(p));
    return a;
}

#define CP_ASYNC16(dst, src) \
    asm volatile("cp.async.cg.shared.global [%0], [%1], 16;" \
                 :: "r"(dst), "l"(src) : "memory")
#define CP_COMMIT() asm volatile("cp.async.commit_group;" ::: "memory")
#define CP_WAIT1()  asm volatile("cp.async.wait_group 1;" ::: "memory")
#define CP_WAIT2()  asm volatile("cp.async.wait_group 2;" ::: "memory")

#define LDSM_X4(r0, r1, r2, r3, addr) \
    asm volatile("ldmatrix.sync.aligned.m8n8.x4.shared.b16 {%0,%1,%2,%3}, [%4];" \
                 : "=r"(r0), "=r"(r1), "=r"(r2), "=r"(r3) : "r"(addr))
#define LDSM_X4T(r0, r1, r2, r3, addr) \
    asm volatile("ldmatrix.sync.aligned.m8n8.x4.trans.shared.b16 {%0,%1,%2,%3}, [%4];" \
                 : "=r"(r0), "=r"(r1), "=r"(r2), "=r"(r3) : "r"(addr))

#define MMAH(c, a, b0, b1) \
    asm volatile("mma.sync.aligned.m16n8k16.row.col.f32.f16.f16.f32 " \
                 "{%0,%1,%2,%3}, {%4,%5,%6,%7}, {%8,%9}, {%0,%1,%2,%3};" \
                 : "+f"((c)[0]), "+f"((c)[1]), "+f"((c)[2]), "+f"((c)[3]) \
                 : "r"((a)[0]), "r"((a)[1]), "r"((a)[2]), "r"((a)[3]), \
                   "r"(b0), "r"(b1))

__device__ __forceinline__ uint32_t pack_h2(__half a, __half b) {
    __half2 t = __halves2half2(a, b);
    return *reinterpret_cast<uint32_t*>(&t);
}

// ---------------------------------------------------------------------------
// Prep 1: x fp32 [R, C] -> [R, 2C] fp16 = [hi | lo] (exact to ~2^-22)
// ---------------------------------------------------------------------------
__global__ __launch_bounds__(256)
void split2h(const float* __restrict__ in, __half* __restrict__ out, int total4)
{
    int i = blockIdx.x * blockDim.x + threadIdx.x;
    if (i >= total4) return;
    const int c4 = C_ / 4;
    int r = i / c4, c = (i % c4) * 4;
    float4 v = reinterpret_cast<const float4*>(in)[i];
    float vv[4] = {v.x, v.y, v.z, v.w};
    __half h[4], l[4];
    #pragma unroll
    for (int j = 0; j < 4; j++) {
        h[j] = __float2half(vv[j]);
        l[j] = __float2half(vv[j] - __half2float(h[j]));
    }
    __half* row = out + (size_t)r * KP_;
    *reinterpret_cast<uint2*>(row + c)      = make_uint2(pack_h2(h[0], h[1]), pack_h2(h[2], h[3]));
    *reinterpret_cast<uint2*>(row + C_ + c) = make_uint2(pack_h2(l[0], l[1]), pack_h2(l[2], l[3]));
}

// ---------------------------------------------------------------------------
// Prep 2: W fp32 [K,N] -> [N,2K] fp16 = [W | W] (transposed, duplicated)
// ---------------------------------------------------------------------------
__global__ __launch_bounds__(256)
void tsplit2h(const float* __restrict__ W, __half* __restrict__ out,
              int K, int N)
{
    __shared__ float t[32][33];
    const int n0 = blockIdx.x * 32, k0 = blockIdx.y * 32;
    const int tx = threadIdx.x, ty = threadIdx.y;
    #pragma unroll
    for (int r = 0; r < 4; r++)
        t[ty + 8 * r][tx] = W[(size_t)(k0 + ty + 8 * r) * N + n0 + tx];
    __syncthreads();
    #pragma unroll
    for (int r = 0; r < 4; r++) {
        __half h = __float2half(t[tx][ty + 8 * r]);
        const int n = n0 + ty + 8 * r, k = k0 + tx;
        __half* row = out + (size_t)n * (2 * K);
        row[k]     = h;
        row[K + k] = h;
    }
}

// ---------------------------------------------------------------------------
// fp16 mma.sync GEMM, 3-stage cp.async pipeline.
// EPI 1: QKV — write q (x1/8) as fp16 hi/lo, k and v as single fp16, per-head.
// EPI 2: proj — add bias, fp32 store.
// ---------------------------------------------------------------------------
#define GBM 128
#define GBN 128
#define GBK 64
#define STAGE_BYTES 32768
#define SMEM_TOTAL  (3 * STAGE_BYTES)

__device__ __forceinline__ void load_tile_async(
    uint32_t s_base, const uint16_t* __restrict__ g,
    int ld, int row0, int k0, int tid)
{
    #pragma unroll
    for (int it = 0; it < 4; it++) {
        int i = tid + it * 256;
        int row = i >> 3, c = i & 7;
        uint32_t dst = s_base + row * 128 + (((c ^ (row & 7))) << 4);
        const uint16_t* src = g + (size_t)(row0 + row) * ld + k0 + c * 8;
        CP_ASYNC16(dst, src);
    }
}

template<int EPI>
__global__ __launch_bounds__(256, 2)
void gemm_mma(const uint16_t* __restrict__ A,
              const uint16_t* __restrict__ Bt,
              const float* __restrict__ bias, float* __restrict__ C,
              __half* __restrict__ qhi, __half* __restrict__ qlo,
              __half* __restrict__ kh,  __half* __restrict__ vh,
              int M, int N, int KK)
{
    extern __shared__ char sm[];
    const uint32_t sbase = smem_u32(sm);
    const int tid = threadIdx.x;
    const int wid = tid >> 5, lane = tid & 31;
    const int wm = wid >> 1, wn = wid & 1;
    const int m0 = blockIdx.y * GBM, n0 = blockIdx.x * GBN;

    float acc[2][8][4];
    #pragma unroll
    for (int mt = 0; mt < 2; mt++)
        #pragma unroll
        for (int nt = 0; nt < 8; nt++)
            #pragma unroll
            for (int j = 0; j < 4; j++) acc[mt][nt][j] = 0.f;

    const int nchunks = KK / GBK;

    load_tile_async(sbase,         A,  KK, m0, 0, tid);
    load_tile_async(sbase + 16384, Bt, KK, n0, 0, tid);
    CP_COMMIT();
    {
        const uint32_t nb = sbase + STAGE_BYTES;
        load_tile_async(nb,         A,  KK, m0, GBK, tid);
        load_tile_async(nb + 16384, Bt, KK, n0, GBK, tid);
    }
    CP_COMMIT();

    const int a_row  = wm * 32 + (lane & 15);
    const int a_cadd = (lane >> 4);
    const int b_row  = wn * 64 + (lane & 7) + ((lane >> 4) << 3);
    const int b_cadd = (lane >> 3) & 1;

    for (int ch = 0; ch < nchunks; ch++) {
        CP_WAIT1();
        __syncthreads();

        const uint32_t sA = sbase + (ch % 3) * STAGE_BYTES;
        const uint32_t sB = sA + 16384;

        #pragma unroll
        for (int ks = 0; ks < 4; ks++) {
            uint32_t a[2][4];
            #pragma unroll
            for (int mt = 0; mt < 2; mt++) {
                const int row = a_row + mt * 16;
                const int c16 = ks * 2 + a_cadd;
                const uint32_t addr = sA + row * 128 + ((c16 ^ (row & 7)) << 4);
                LDSM_X4(a[mt][0], a[mt][1], a[mt][2], a[mt][3], addr);
            }
            uint32_t b[4][4];
            #pragma unroll
            for (int ntp = 0; ntp < 4; ntp++) {
                const int row = b_row + ntp * 16;
                const int c16 = ks * 2 + b_cadd;
                const uint32_t addr = sB + row * 128 + ((c16 ^ (row & 7)) << 4);
                LDSM_X4(b[ntp][0], b[ntp][1], b[ntp][2], b[ntp][3], addr);
            }
            #pragma unroll
            for (int mt = 0; mt < 2; mt++)
                #pragma unroll
                for (int nt = 0; nt < 8; nt++)
                    MMAH(acc[mt][nt], a[mt],
                         b[nt >> 1][(nt & 1) * 2],
                         b[nt >> 1][(nt & 1) * 2 + 1]);
        }

        if (ch + 2 < nchunks) {
            const uint32_t nb = sbase + ((ch + 2) % 3) * STAGE_BYTES;
            load_tile_async(nb,         A,  KK, m0, (ch + 2) * GBK, tid);
            load_tile_async(nb + 16384, Bt, KK, n0, (ch + 2) * GBK, tid);
        }
        CP_COMMIT();
    }

    const int gid = lane >> 2, tig = lane & 3;

    if (EPI == 2) {
        #pragma unroll
        for (int mt = 0; mt < 2; mt++) {
            #pragma unroll
            for (int nt = 0; nt < 8; nt++) {
                const int col = n0 + wn * 64 + nt * 8 + tig * 2;
                const float bx = bias[col], by = bias[col + 1];
                const int r0 = m0 + wm * 32 + mt * 16 + gid;
                float2 v0 = { acc[mt][nt][0] + bx, acc[mt][nt][1] + by };
                float2 v1 = { acc[mt][nt][2] + bx, acc[mt][nt][3] + by };
                *reinterpret_cast<float2*>(&C[(size_t)r0 * N + col])       = v0;
                *reinterpret_cast<float2*>(&C[(size_t)(r0 + 8) * N + col]) = v1;
            }
        }
    } else {  // EPI == 1: QKV split epilogue (fp16)
        #pragma unroll
        for (int mt = 0; mt < 2; mt++) {
            #pragma unroll
            for (int nt = 0; nt < 8; nt++) {
                const int col   = n0 + wn * 64 + nt * 8 + tig * 2;
                const int which = col >> 10;            // 0=q 1=k 2=v
                const int hh    = (col >> 6) & 15;
                const int d     = col & 63;
                #pragma unroll
                for (int rr = 0; rr < 2; rr++) {
                    const int r  = m0 + wm * 32 + mt * 16 + gid + rr * 8;
                    const int bb = r >> 11, t = r & 2047;
                    const size_t off = (((size_t)(bb * 16 + hh)) * 2048 + t) * 64 + d;
                    float v0 = acc[mt][nt][rr * 2 + 0];
                    float v1 = acc[mt][nt][rr * 2 + 1];
                    if (which == 0) {
                        v0 *= 0.125f; v1 *= 0.125f;
                        const __half h0 = __float2half(v0);
                        const __half h1 = __float2half(v1);
                        const __half e0 = __float2half(v0 - __half2float(h0));
                        const __half e1 = __float2half(v1 - __half2float(h1));
                        *reinterpret_cast<uint32_t*>(qhi + off) = pack_h2(h0, h1);
                        *reinterpret_cast<uint32_t*>(qlo + off) = pack_h2(e0, e1);
                    } else {
                        __half* p = (which == 1) ? kh : vh;
                        *reinterpret_cast<uint32_t*>(p + off) =
                            pack_h2(__float2half(v0), __float2half(v1));
                    }
                }
            }
        }
    }
}

// ---------------------------------------------------------------------------
// MMA flash attention (fp16 2-pass), 3-stage cp.async K/V pipeline.
// q exact (hi/lo fp16, hoisted fragments); k,v single fp16.
// smem: Qhi 16K | Qlo 16K | 3 x (Kh 8K, Vh 8K) = 80KB
// ---------------------------------------------------------------------------
#define ATT_SMEM (32768 + 3 * 16384)

__device__ __forceinline__ void kv_load(uint32_t sb,
    const __half* __restrict__ kh, const __half* __restrict__ vh,
    size_t hb, int kt, int tid)
{
    const uint32_t stage = sb + 32768 + (kt % 3) * 16384;
    #pragma unroll
    for (int it = 0; it < 4; it++) {
        int i = tid + (it & 1) * 256;            // 0..511
        int row = i >> 3, c = i & 7;
        const __half* g = (it < 2) ? kh : vh;
        uint32_t dst = stage + ((it < 2) ? 0 : 8192)
                     + row * 128 + ((c ^ (row & 7)) << 4);
        CP_ASYNC16(dst, g + hb + (size_t)(kt * 64 + row) * 64 + c * 8);
    }
}

__global__ __launch_bounds__(256, 1)
void attn_mma(const __half* __restrict__ qhi, const __half* __restrict__ qlo,
              const __half* __restrict__ kh,  const __half* __restrict__ vh,
              __half* __restrict__ yexp)
{
    extern __shared__ char sm[];
    const uint32_t sb = smem_u32(sm);
    const uint32_t sQhi = sb, sQlo = sb + 16384;

    const int tid = threadIdx.x, wid = tid >> 5, lane = tid & 31;
    const int qt = gridDim.x - 1 - blockIdx.x;    // heavy q-tiles first
    const int h = blockIdx.y, b = blockIdx.z;
    const size_t hb = ((size_t)(b * H_ + h)) * T_ * 64;
    const int ktmax = 2 * (qt + 1);               // >= 2

    // Stage Q tiles (hi+lo)
    #pragma unroll
    for (int it = 0; it < 8; it++) {
        int i = tid + (it & 3) * 256;
        int row = i >> 3, c = i & 7;
        uint32_t dst = (it < 4 ? sQhi : sQlo) + row * 128 + ((c ^ (row & 7)) << 4);
        const __half* src = (it < 4 ? qhi : qlo)
                          + hb + (size_t)(qt * 128 + row) * 64 + c * 8;
        CP_ASYNC16(dst, src);
    }
    CP_COMMIT();                                   // g0: Q
    kv_load(sb, kh, vh, hb, 0, tid);
    CP_COMMIT();                                   // g1: KV0
    kv_load(sb, kh, vh, hb, 1, tid);
    CP_COMMIT();                                   // g2: KV1

    const int gid = lane >> 2, tig = lane & 3;
    const int arow   = wid * 16 + (lane & 15);
    const int acadd  = lane >> 4;
    const int kbrow  = (lane & 7) + ((lane >> 4) << 3);
    const int kbcadd = (lane >> 3) & 1;
    const int vbrow  = (lane & 7) + (((lane >> 3) & 1) << 3);
    const int vbcadd = lane >> 4;

    // Q fragments (loop-invariant), hoisted after g0 lands
    CP_WAIT2();
    __syncthreads();
    uint32_t aqh[4][4], aql[4][4];
    #pragma unroll
    for (int ks = 0; ks < 4; ks++) {
        const int c16 = ks * 2 + acadd;
        uint32_t ad = sQhi + arow * 128 + ((c16 ^ (arow & 7)) << 4);
        LDSM_X4(aqh[ks][0], aqh[ks][1], aqh[ks][2], aqh[ks][3], ad);
        ad = sQlo + arow * 128 + ((c16 ^ (arow & 7)) << 4);
        LDSM_X4(aql[ks][0], aql[ks][1], aql[ks][2], aql[ks][3], ad);
    }

    float m0 = -1e30f, m1 = -1e30f, l0 = 0.f, l1 = 0.f;
    float O[8][4];
    #pragma unroll
    for (int d = 0; d < 8; d++)
        #pragma unroll
        for (int j = 0; j < 4; j++) O[d][j] = 0.f;

    const int rg0 = qt * 128 + wid * 16 + gid;

    for (int kt = 0; kt < ktmax; kt++) {
        CP_WAIT1();
        __syncthreads();

        const uint32_t stage = sb + 32768 + (kt % 3) * 16384;
        const uint32_t sKh = stage, sVh = stage + 8192;

        const bool active = (kt * 64) <= (qt * 128 + wid * 16 + 15);
        if (active) {
            // ---- S = QK^T, 2-pass (q exact, k fp16) ----
            float S[8][4];
            #pragma unroll
            for (int nt = 0; nt < 8; nt++)
                #pragma unroll
                for (int j = 0; j < 4; j++) S[nt][j] = 0.f;

            #pragma unroll
            for (int ks = 0; ks < 4; ks++) {
                const int c16 = ks * 2;
                uint32_t bh[4][4];
                #pragma unroll
                for (int jn = 0; jn < 4; jn++) {
                    const int row = jn * 16 + kbrow;
                    const int cc  = c16 + kbcadd;
                    uint32_t ad = sKh + row * 128 + ((cc ^ (row & 7)) << 4);
                    LDSM_X4(bh[jn][0], bh[jn][1], bh[jn][2], bh[jn][3], ad);
                }
                #pragma unroll
                for (int nt = 0; nt < 8; nt++) {
                    const int jn = nt >> 1, s = (nt & 1) * 2;
                    MMAH(S[nt], aqh[ks], bh[jn][s], bh[jn][s + 1]);
                    MMAH(S[nt], aql[ks], bh[jn][s], bh[jn][s + 1]);
                }
            }

            // ---- causal mask (diagonal tiles only) ----
            if (kt >= 2 * qt) {
                #pragma unroll
                for (int nt = 0; nt < 8; nt++) {
                    const int jg = kt * 64 + nt * 8 + tig * 2;
                    if (jg     > rg0)     S[nt][0] = -1e30f;
                    if (jg + 1 > rg0)     S[nt][1] = -1e30f;
                    if (jg     > rg0 + 8) S[nt][2] = -1e30f;
                    if (jg + 1 > rg0 + 8) S[nt][3] = -1e30f;
                }
            }

            // ---- online softmax ----
            float t0 = -1e30f, t1 = -1e30f;
            #pragma unroll
            for (int nt = 0; nt < 8; nt++) {
                t0 = fmaxf(t0, fmaxf(S[nt][0], S[nt][1]));
                t1 = fmaxf(t1, fmaxf(S[nt][2], S[nt][3]));
            }
            t0 = fmaxf(t0, __shfl_xor_sync(0xffffffffu, t0, 1));
            t0 = fmaxf(t0, __shfl_xor_sync(0xffffffffu, t0, 2));
            t1 = fmaxf(t1, __shfl_xor_sync(0xffffffffu, t1, 1));
            t1 = fmaxf(t1, __shfl_xor_sync(0xffffffffu, t1, 2));
            const float mn0 = fmaxf(m0, t0), mn1 = fmaxf(m1, t1);
            const float a0 = __expf(m0 - mn0), a1 = __expf(m1 - mn1);
            m0 = mn0; m1 = mn1;
            l0 *= a0;  l1 *= a1;
            #pragma unroll
            for (int d = 0; d < 8; d++) {
                O[d][0] *= a0; O[d][1] *= a0;
                O[d][2] *= a1; O[d][3] *= a1;
            }

            // ---- P = exp(S-m), fp16 hi/lo A-fragments ----
            uint32_t phi[4][4], plo[4][4];
            #pragma unroll
            for (int nt = 0; nt < 8; nt++) {
                const float p0 = __expf(S[nt][0] - m0);
                const float p1 = __expf(S[nt][1] - m0);
                const float p2 = __expf(S[nt][2] - m1);
                const float p3 = __expf(S[nt][3] - m1);
                l0 += p0 + p1;
                l1 += p2 + p3;
                const __half h0 = __float2half(p0), h1 = __float2half(p1);
                const __half h2 = __float2half(p2), h3 = __float2half(p3);
                const __half e0 = __float2half(p0 - __half2float(h0));
                const __half e1 = __float2half(p1 - __half2float(h1));
                const __half e2 = __float2half(p2 - __half2float(h2));
                const __half e3 = __float2half(p3 - __half2float(h3));
                const int jb = nt >> 1, o = (nt & 1) * 2;
                phi[jb][o]     = pack_h2(h0, h1);
                phi[jb][o + 1] = pack_h2(h2, h3);
                plo[jb][o]     = pack_h2(e0, e1);
                plo[jb][o + 1] = pack_h2(e2, e3);
            }

            // ---- O += P @ V, 2-pass (p exact, v fp16) ----
            #pragma unroll
            for (int jb = 0; jb < 4; jb++) {
                #pragma unroll
                for (int dp = 0; dp < 4; dp++) {
                    const int row = jb * 16 + vbrow;
                    const int cc  = dp * 2 + vbcadd;
                    uint32_t vv[4];
                    uint32_t ad = sVh + row * 128 + ((cc ^ (row & 7)) << 4);
                    LDSM_X4T(vv[0], vv[1], vv[2], vv[3], ad);
                    const int d0 = dp * 2;
                    MMAH(O[d0],     phi[jb], vv[0], vv[1]);
                    MMAH(O[d0],     plo[jb], vv[0], vv[1]);
                    MMAH(O[d0 + 1], phi[jb], vv[2], vv[3]);
                    MMAH(O[d0 + 1], plo[jb], vv[2], vv[3]);
                }
            }
        }

        if (kt + 2 < ktmax)
            kv_load(sb, kh, vh, hb, kt + 2, tid);
        CP_COMMIT();
    }

    // ---- epilogue: normalize + write fp16 [hi|lo] expanded rows ----
    l0 += __shfl_xor_sync(0xffffffffu, l0, 1);
    l0 += __shfl_xor_sync(0xffffffffu, l0, 2);
    l1 += __shfl_xor_sync(0xffffffffu, l1, 1);
    l1 += __shfl_xor_sync(0xffffffffu, l1, 2);
    const float inv0 = 1.f / l0, inv1 = 1.f / l1;

    const size_t row0 = (size_t)(b * T_ + rg0) * KP_;
    const size_t row1 = row0 + (size_t)8 * KP_;
    #pragma unroll
    for (int d = 0; d < 8; d++) {
        const int c = h * 64 + d * 8 + tig * 2;
        float v0 = O[d][0] * inv0, v1 = O[d][1] * inv0;
        float v2 = O[d][2] * inv1, v3 = O[d][3] * inv1;
        __half h0 = __float2half(v0), h1 = __float2half(v1);
        __half h2 = __float2half(v2), h3 = __float2half(v3);
        __half e0 = __float2half(v0 - __half2float(h0));
        __half e1 = __float2half(v1 - __half2float(h1));
        __half e2 = __float2half(v2 - __half2float(h2));
        __half e3 = __float2half(v3 - __half2float(h3));
        *reinterpret_cast<uint32_t*>(yexp + row0 + c)      = pack_h2(h0, h1);
        *reinterpret_cast<uint32_t*>(yexp + row0 + C_ + c) = pack_h2(e0, e1);
        *reinterpret_cast<uint32_t*>(yexp + row1 + c)      = pack_h2(h2, h3);
        *reinterpret_cast<uint32_t*>(yexp + row1 + C_ + c) = pack_h2(e2, e3);
    }
}

// ---------------------------------------------------------------------------
extern "C" void kernel_launch(void* const* d_in, const int* in_sizes, int n_in,
                              void* d_out, int out_size)
{
    const float* x     = (const float*)d_in[0];
    const float* wkqv  = (const float*)d_in[1];
    const float* wproj = (const float*)d_in[2];
    const float* bproj = (const float*)d_in[3];
    float* out = (float*)d_out;

    __half *xe, *w1h, *ye, *w2h, *qh, *ql, *kh, *vh;
    cudaGetSymbolAddress((void**)&xe,  g_xe);
    cudaGetSymbolAddress((void**)&w1h, g_w1h);
    cudaGetSymbolAddress((void**)&ye,  g_yexp);
    cudaGetSymbolAddress((void**)&w2h, g_w2h);
    cudaGetSymbolAddress((void**)&qh,  g_qhi);
    cudaGetSymbolAddress((void**)&ql,  g_qlo);
    cudaGetSymbolAddress((void**)&kh,  g_kh);
    cudaGetSymbolAddress((void**)&vh,  g_vh);

    cudaFuncSetAttribute((const void*)gemm_mma<1>,
                         cudaFuncAttributeMaxDynamicSharedMemorySize, SMEM_TOTAL);
    cudaFuncSetAttribute((const void*)gemm_mma<2>,
                         cudaFuncAttributeMaxDynamicSharedMemorySize, SMEM_TOTAL);
    cudaFuncSetAttribute((const void*)attn_mma,
                         cudaFuncAttributeMaxDynamicSharedMemorySize, ATT_SMEM);

    // Prep
    split2h<<<(BT_ * C_ / 4 + 255) / 256, 256>>>(x, xe, BT_ * C_ / 4);
    tsplit2h<<<dim3(C3_ / 32, C_ / 32), dim3(32, 8)>>>(wkqv, w1h, C_, C3_);
    tsplit2h<<<dim3(C_ / 32, C_ / 32), dim3(32, 8)>>>(wproj, w2h, C_, C_);

    // 1) QKV GEMM (fp16 2-pass, K=2048) with fused per-head split epilogue
    {
        dim3 grid(C3_ / GBN, BT_ / GBM);   // (24, 32)
        gemm_mma<1><<<grid, 256, SMEM_TOTAL>>>(
            (const uint16_t*)xe, (const uint16_t*)w1h, nullptr, nullptr,
            qh, ql, kh, vh, BT_, C3_, KP_);
    }

    // 2) MMA flash attention (fp16 2-pass) -> g_yexp
    {
        dim3 grid(T_ / 128, H_, B_);       // (16, 16, 2)
        attn_mma<<<grid, 256, ATT_SMEM>>>(qh, ql, kh, vh, ye);
    }

    // 3) proj GEMM (fp16 2-pass) + bias -> out
    {
        dim3 grid(C_ / GBN, BT_ / GBM);    // (8, 32)
        gemm_mma<2><<<grid, 256, SMEM_TOTAL>>>(
            (const uint16_t*)ye, (const uint16_t*)w2h, bproj, out,
            nullptr, nullptr, nullptr, nullptr, BT_, C_, KP_);
    }
}

// round 9
// speedup vs baseline: 6.7432x; 1.1183x over previous
#include <cuda_runtime.h>
#include <cuda_bf16.h>
#include <cuda_fp16.h>
#include <cstdint>

// Problem constants (fixed by the reference)
#define B_   2
#define T_   2048
#define C_   1024
#define H_   16
#define HS_  64
#define C3_  3072
#define BT_  (B_*T_)          // 4096 rows
#define KP_  (2*C_)           // expanded K (fp16 2-pass) = 2048

// ---------------------------------------------------------------------------
// Scratch (device globals — no runtime allocation allowed)
// ---------------------------------------------------------------------------
__device__ __half g_xe  [(size_t)BT_ * KP_];   // [x_hi | x_lo] fp16
__device__ __half g_w1h [(size_t)C3_ * KP_];   // W_kqv^T [W|W] fp16
__device__ __half g_yexp[(size_t)BT_ * KP_];   // attn out [hi|lo] fp16
__device__ __half g_w2h [(size_t)C_  * KP_];   // W_proj^T [W|W] fp16

// per-head attention operands [B, H, T, 64] fp16 (all single precision fp16)
#define NHE ((size_t)B_ * H_ * T_ * 64)
__device__ __half g_qh[NHE];                   // q fp16, pre-scaled 1/8
__device__ __half g_kh[NHE], g_vh[NHE];        // k, v fp16

// ---------------------------------------------------------------------------
// PTX helpers (no 'a'-gated instructions)
// ---------------------------------------------------------------------------
__device__ __forceinline__ uint32_t smem_u32(const void* p) {
    uint32_t a;
    asm("{ .reg .u64 t; cvta.to.shared.u64 t, %1; cvt.u32.u64 %0, t; }"
        : "=r"(a) : "l"(p));
    return a;
}

#define CP_ASYNC16(dst, src) \
    asm volatile("cp.async.cg.shared.global [%0], [%1], 16;" \
                 :: "r"(dst), "l"(src) : "memory")
#define CP_COMMIT() asm volatile("cp.async.commit_group;" ::: "memory")
#define CP_WAIT1()  asm volatile("cp.async.wait_group 1;" ::: "memory")
#define CP_WAIT2()  asm volatile("cp.async.wait_group 2;" ::: "memory")

#define LDSM_X4(r0, r1, r2, r3, addr) \
    asm volatile("ldmatrix.sync.aligned.m8n8.x4.shared.b16 {%0,%1,%2,%3}, [%4];" \
                 : "=r"(r0), "=r"(r1), "=r"(r2), "=r"(r3) : "r"(addr))
#define LDSM_X4T(r0, r1, r2, r3, addr) \
    asm volatile("ldmatrix.sync.aligned.m8n8.x4.trans.shared.b16 {%0,%1,%2,%3}, [%4];" \
                 : "=r"(r0), "=r"(r1), "=r"(r2), "=r"(r3) : "r"(addr))

#define MMAH(c, a, b0, b1) \
    asm volatile("mma.sync.aligned.m16n8k16.row.col.f32.f16.f16.f32 " \
                 "{%0,%1,%2,%3}, {%4,%5,%6,%7}, {%8,%9}, {%0,%1,%2,%3};" \
                 : "+f"((c)[0]), "+f"((c)[1]), "+f"((c)[2]), "+f"((c)[3]) \
                 : "r"((a)[0]), "r"((a)[1]), "r"((a)[2]), "r"((a)[3]), \
                   "r"(b0), "r"(b1))

__device__ __forceinline__ uint32_t pack_h2(__half a, __half b) {
    __half2 t = __halves2half2(a, b);
    return *reinterpret_cast<uint32_t*>(&t);
}

// ---------------------------------------------------------------------------
// Prep 1: x fp32 [R, C] -> [R, 2C] fp16 = [hi | lo] (exact to ~2^-22)
// ---------------------------------------------------------------------------
__global__ __launch_bounds__(256)
void split2h(const float* __restrict__ in, __half* __restrict__ out, int total4)
{
    int i = blockIdx.x * blockDim.x + threadIdx.x;
    if (i >= total4) return;
    const int c4 = C_ / 4;
    int r = i / c4, c = (i % c4) * 4;
    float4 v = reinterpret_cast<const float4*>(in)[i];
    float vv[4] = {v.x, v.y, v.z, v.w};
    __half h[4], l[4];
    #pragma unroll
    for (int j = 0; j < 4; j++) {
        h[j] = __float2half(vv[j]);
        l[j] = __float2half(vv[j] - __half2float(h[j]));
    }
    __half* row = out + (size_t)r * KP_;
    *reinterpret_cast<uint2*>(row + c)      = make_uint2(pack_h2(h[0], h[1]), pack_h2(h[2], h[3]));
    *reinterpret_cast<uint2*>(row + C_ + c) = make_uint2(pack_h2(l[0], l[1]), pack_h2(l[2], l[3]));
}

// ---------------------------------------------------------------------------
// Prep 2: W fp32 [K,N] -> [N,2K] fp16 = [W | W] (transposed, duplicated)
// ---------------------------------------------------------------------------
__global__ __launch_bounds__(256)
void tsplit2h(const float* __restrict__ W, __half* __restrict__ out,
              int K, int N)
{
    __shared__ float t[32][33];
    const int n0 = blockIdx.x * 32, k0 = blockIdx.y * 32;
    const int tx = threadIdx.x, ty = threadIdx.y;
    #pragma unroll
    for (int r = 0; r < 4; r++)
        t[ty + 8 * r][tx] = W[(size_t)(k0 + ty + 8 * r) * N + n0 + tx];
    __syncthreads();
    #pragma unroll
    for (int r = 0; r < 4; r++) {
        __half h = __float2half(t[tx][ty + 8 * r]);
        const int n = n0 + ty + 8 * r, k = k0 + tx;
        __half* row = out + (size_t)n * (2 * K);
        row[k]     = h;
        row[K + k] = h;
    }
}

// ---------------------------------------------------------------------------
// fp16 mma.sync GEMM, 3-stage cp.async pipeline.
// EPI 1: QKV — write q (x1/8), k, v as single fp16 per-head arrays.
// EPI 2: proj — add bias, fp32 store.
// ---------------------------------------------------------------------------
#define GBM 128
#define GBN 128
#define GBK 64
#define STAGE_BYTES 32768
#define SMEM_TOTAL  (3 * STAGE_BYTES)

__device__ __forceinline__ void load_tile_async(
    uint32_t s_base, const uint16_t* __restrict__ g,
    int ld, int row0, int k0, int tid)
{
    #pragma unroll
    for (int it = 0; it < 4; it++) {
        int i = tid + it * 256;
        int row = i >> 3, c = i & 7;
        uint32_t dst = s_base + row * 128 + (((c ^ (row & 7))) << 4);
        const uint16_t* src = g + (size_t)(row0 + row) * ld + k0 + c * 8;
        CP_ASYNC16(dst, src);
    }
}

template<int EPI>
__global__ __launch_bounds__(256, 2)
void gemm_mma(const uint16_t* __restrict__ A,
              const uint16_t* __restrict__ Bt,
              const float* __restrict__ bias, float* __restrict__ C,
              __half* __restrict__ qh, __half* __restrict__ kh,
              __half* __restrict__ vh,
              int M, int N, int KK)
{
    extern __shared__ char sm[];
    const uint32_t sbase = smem_u32(sm);
    const int tid = threadIdx.x;
    const int wid = tid >> 5, lane = tid & 31;
    const int wm = wid >> 1, wn = wid & 1;
    const int m0 = blockIdx.y * GBM, n0 = blockIdx.x * GBN;

    float acc[2][8][4];
    #pragma unroll
    for (int mt = 0; mt < 2; mt++)
        #pragma unroll
        for (int nt = 0; nt < 8; nt++)
            #pragma unroll
            for (int j = 0; j < 4; j++) acc[mt][nt][j] = 0.f;

    const int nchunks = KK / GBK;

    load_tile_async(sbase,         A,  KK, m0, 0, tid);
    load_tile_async(sbase + 16384, Bt, KK, n0, 0, tid);
    CP_COMMIT();
    {
        const uint32_t nb = sbase + STAGE_BYTES;
        load_tile_async(nb,         A,  KK, m0, GBK, tid);
        load_tile_async(nb + 16384, Bt, KK, n0, GBK, tid);
    }
    CP_COMMIT();

    const int a_row  = wm * 32 + (lane & 15);
    const int a_cadd = (lane >> 4);
    const int b_row  = wn * 64 + (lane & 7) + ((lane >> 4) << 3);
    const int b_cadd = (lane >> 3) & 1;

    for (int ch = 0; ch < nchunks; ch++) {
        CP_WAIT1();
        __syncthreads();

        const uint32_t sA = sbase + (ch % 3) * STAGE_BYTES;
        const uint32_t sB = sA + 16384;

        #pragma unroll
        for (int ks = 0; ks < 4; ks++) {
            uint32_t a[2][4];
            #pragma unroll
            for (int mt = 0; mt < 2; mt++) {
                const int row = a_row + mt * 16;
                const int c16 = ks * 2 + a_cadd;
                const uint32_t addr = sA + row * 128 + ((c16 ^ (row & 7)) << 4);
                LDSM_X4(a[mt][0], a[mt][1], a[mt][2], a[mt][3], addr);
            }
            uint32_t b[4][4];
            #pragma unroll
            for (int ntp = 0; ntp < 4; ntp++) {
                const int row = b_row + ntp * 16;
                const int c16 = ks * 2 + b_cadd;
                const uint32_t addr = sB + row * 128 + ((c16 ^ (row & 7)) << 4);
                LDSM_X4(b[ntp][0], b[ntp][1], b[ntp][2], b[ntp][3], addr);
            }
            #pragma unroll
            for (int mt = 0; mt < 2; mt++)
                #pragma unroll
                for (int nt = 0; nt < 8; nt++)
                    MMAH(acc[mt][nt], a[mt],
                         b[nt >> 1][(nt & 1) * 2],
                         b[nt >> 1][(nt & 1) * 2 + 1]);
        }

        if (ch + 2 < nchunks) {
            const uint32_t nb = sbase + ((ch + 2) % 3) * STAGE_BYTES;
            load_tile_async(nb,         A,  KK, m0, (ch + 2) * GBK, tid);
            load_tile_async(nb + 16384, Bt, KK, n0, (ch + 2) * GBK, tid);
        }
        CP_COMMIT();
    }

    const int gid = lane >> 2, tig = lane & 3;

    if (EPI == 2) {
        #pragma unroll
        for (int mt = 0; mt < 2; mt++) {
            #pragma unroll
            for (int nt = 0; nt < 8; nt++) {
                const int col = n0 + wn * 64 + nt * 8 + tig * 2;
                const float bx = bias[col], by = bias[col + 1];
                const int r0 = m0 + wm * 32 + mt * 16 + gid;
                float2 v0 = { acc[mt][nt][0] + bx, acc[mt][nt][1] + by };
                float2 v1 = { acc[mt][nt][2] + bx, acc[mt][nt][3] + by };
                *reinterpret_cast<float2*>(&C[(size_t)r0 * N + col])       = v0;
                *reinterpret_cast<float2*>(&C[(size_t)(r0 + 8) * N + col]) = v1;
            }
        }
    } else {  // EPI == 1: QKV per-head split epilogue (single fp16)
        #pragma unroll
        for (int mt = 0; mt < 2; mt++) {
            #pragma unroll
            for (int nt = 0; nt < 8; nt++) {
                const int col   = n0 + wn * 64 + nt * 8 + tig * 2;
                const int which = col >> 10;            // 0=q 1=k 2=v
                const int hh    = (col >> 6) & 15;
                const int d     = col & 63;
                const float sc  = (which == 0) ? 0.125f : 1.0f;
                __half* p = (which == 0) ? qh : (which == 1) ? kh : vh;
                #pragma unroll
                for (int rr = 0; rr < 2; rr++) {
                    const int r  = m0 + wm * 32 + mt * 16 + gid + rr * 8;
                    const int bb = r >> 11, t = r & 2047;
                    const size_t off = (((size_t)(bb * 16 + hh)) * 2048 + t) * 64 + d;
                    *reinterpret_cast<uint32_t*>(p + off) =
                        pack_h2(__float2half(acc[mt][nt][rr * 2 + 0] * sc),
                                __float2half(acc[mt][nt][rr * 2 + 1] * sc));
                }
            }
        }
    }
}

// ---------------------------------------------------------------------------
// MMA flash attention, single-pass fp16, 3-stage cp.async K/V pipeline.
// smem: Q 16K | 3 x (Kh 8K, Vh 8K) = 64KB
// ---------------------------------------------------------------------------
#define ATT_SMEM (16384 + 3 * 16384)

__device__ __forceinline__ void kv_load(uint32_t sb,
    const __half* __restrict__ kh, const __half* __restrict__ vh,
    size_t hb, int kt, int tid)
{
    const uint32_t stage = sb + 16384 + (kt % 3) * 16384;
    #pragma unroll
    for (int it = 0; it < 4; it++) {
        int i = tid + (it & 1) * 256;            // 0..511
        int row = i >> 3, c = i & 7;
        const __half* g = (it < 2) ? kh : vh;
        uint32_t dst = stage + ((it < 2) ? 0 : 8192)
                     + row * 128 + ((c ^ (row & 7)) << 4);
        CP_ASYNC16(dst, g + hb + (size_t)(kt * 64 + row) * 64 + c * 8);
    }
}

__global__ __launch_bounds__(256, 1)
void attn_mma(const __half* __restrict__ qh,
              const __half* __restrict__ kh, const __half* __restrict__ vh,
              __half* __restrict__ yexp)
{
    extern __shared__ char sm[];
    const uint32_t sb = smem_u32(sm);
    const uint32_t sQ = sb;

    const int tid = threadIdx.x, wid = tid >> 5, lane = tid & 31;
    const int qt = gridDim.x - 1 - blockIdx.x;    // heavy q-tiles first
    const int h = blockIdx.y, b = blockIdx.z;
    const size_t hb = ((size_t)(b * H_ + h)) * T_ * 64;
    const int ktmax = 2 * (qt + 1);               // >= 2

    // Stage Q tile (128 rows x 8 x 16B)
    #pragma unroll
    for (int it = 0; it < 4; it++) {
        int i = tid + it * 256;
        int row = i >> 3, c = i & 7;
        uint32_t dst = sQ + row * 128 + ((c ^ (row & 7)) << 4);
        CP_ASYNC16(dst, qh + hb + (size_t)(qt * 128 + row) * 64 + c * 8);
    }
    CP_COMMIT();                                   // g0: Q
    kv_load(sb, kh, vh, hb, 0, tid);
    CP_COMMIT();                                   // g1: KV0
    kv_load(sb, kh, vh, hb, 1, tid);
    CP_COMMIT();                                   // g2: KV1

    const int gid = lane >> 2, tig = lane & 3;
    const int arow   = wid * 16 + (lane & 15);
    const int acadd  = lane >> 4;
    const int kbrow  = (lane & 7) + ((lane >> 4) << 3);
    const int kbcadd = (lane >> 3) & 1;
    const int vbrow  = (lane & 7) + (((lane >> 3) & 1) << 3);
    const int vbcadd = lane >> 4;

    // Q fragments (loop-invariant), hoisted after g0 lands
    CP_WAIT2();
    __syncthreads();
    uint32_t aq[4][4];
    #pragma unroll
    for (int ks = 0; ks < 4; ks++) {
        const int c16 = ks * 2 + acadd;
        uint32_t ad = sQ + arow * 128 + ((c16 ^ (arow & 7)) << 4);
        LDSM_X4(aq[ks][0], aq[ks][1], aq[ks][2], aq[ks][3], ad);
    }

    float m0 = -1e30f, m1 = -1e30f, l0 = 0.f, l1 = 0.f;
    float O[8][4];
    #pragma unroll
    for (int d = 0; d < 8; d++)
        #pragma unroll
        for (int j = 0; j < 4; j++) O[d][j] = 0.f;

    const int rg0 = qt * 128 + wid * 16 + gid;

    for (int kt = 0; kt < ktmax; kt++) {
        CP_WAIT1();
        __syncthreads();

        const uint32_t stage = sb + 16384 + (kt % 3) * 16384;
        const uint32_t sKh = stage, sVh = stage + 8192;

        const bool active = (kt * 64) <= (qt * 128 + wid * 16 + 15);
        if (active) {
            // ---- S = QK^T (single pass) ----
            float S[8][4];
            #pragma unroll
            for (int nt = 0; nt < 8; nt++)
                #pragma unroll
                for (int j = 0; j < 4; j++) S[nt][j] = 0.f;

            #pragma unroll
            for (int ks = 0; ks < 4; ks++) {
                const int c16 = ks * 2;
                uint32_t bh[4][4];
                #pragma unroll
                for (int jn = 0; jn < 4; jn++) {
                    const int row = jn * 16 + kbrow;
                    const int cc  = c16 + kbcadd;
                    uint32_t ad = sKh + row * 128 + ((cc ^ (row & 7)) << 4);
                    LDSM_X4(bh[jn][0], bh[jn][1], bh[jn][2], bh[jn][3], ad);
                }
                #pragma unroll
                for (int nt = 0; nt < 8; nt++)
                    MMAH(S[nt], aq[ks],
                         bh[nt >> 1][(nt & 1) * 2],
                         bh[nt >> 1][(nt & 1) * 2 + 1]);
            }

            // ---- causal mask (diagonal tiles only) ----
            if (kt >= 2 * qt) {
                #pragma unroll
                for (int nt = 0; nt < 8; nt++) {
                    const int jg = kt * 64 + nt * 8 + tig * 2;
                    if (jg     > rg0)     S[nt][0] = -1e30f;
                    if (jg + 1 > rg0)     S[nt][1] = -1e30f;
                    if (jg     > rg0 + 8) S[nt][2] = -1e30f;
                    if (jg + 1 > rg0 + 8) S[nt][3] = -1e30f;
                }
            }

            // ---- online softmax ----
            float t0 = -1e30f, t1 = -1e30f;
            #pragma unroll
            for (int nt = 0; nt < 8; nt++) {
                t0 = fmaxf(t0, fmaxf(S[nt][0], S[nt][1]));
                t1 = fmaxf(t1, fmaxf(S[nt][2], S[nt][3]));
            }
            t0 = fmaxf(t0, __shfl_xor_sync(0xffffffffu, t0, 1));
            t0 = fmaxf(t0, __shfl_xor_sync(0xffffffffu, t0, 2));
            t1 = fmaxf(t1, __shfl_xor_sync(0xffffffffu, t1, 1));
            t1 = fmaxf(t1, __shfl_xor_sync(0xffffffffu, t1, 2));
            const float mn0 = fmaxf(m0, t0), mn1 = fmaxf(m1, t1);
            const float a0 = __expf(m0 - mn0), a1 = __expf(m1 - mn1);
            m0 = mn0; m1 = mn1;
            l0 *= a0;  l1 *= a1;
            #pragma unroll
            for (int d = 0; d < 8; d++) {
                O[d][0] *= a0; O[d][1] *= a0;
                O[d][2] *= a1; O[d][3] *= a1;
            }

            // ---- P = exp(S-m), single fp16 A-fragments ----
            uint32_t pf[4][4];
            #pragma unroll
            for (int nt = 0; nt < 8; nt++) {
                const float p0 = __expf(S[nt][0] - m0);
                const float p1 = __expf(S[nt][1] - m0);
                const float p2 = __expf(S[nt][2] - m1);
                const float p3 = __expf(S[nt][3] - m1);
                l0 += p0 + p1;
                l1 += p2 + p3;
                const int jb = nt >> 1, o = (nt & 1) * 2;
                pf[jb][o]     = pack_h2(__float2half(p0), __float2half(p1));
                pf[jb][o + 1] = pack_h2(__float2half(p2), __float2half(p3));
            }

            // ---- O += P @ V (single pass) ----
            #pragma unroll
            for (int jb = 0; jb < 4; jb++) {
                #pragma unroll
                for (int dp = 0; dp < 4; dp++) {
                    const int row = jb * 16 + vbrow;
                    const int cc  = dp * 2 + vbcadd;
                    uint32_t vv[4];
                    uint32_t ad = sVh + row * 128 + ((cc ^ (row & 7)) << 4);
                    LDSM_X4T(vv[0], vv[1], vv[2], vv[3], ad);
                    const int d0 = dp * 2;
                    MMAH(O[d0],     pf[jb], vv[0], vv[1]);
                    MMAH(O[d0 + 1], pf[jb], vv[2], vv[3]);
                }
            }
        }

        if (kt + 2 < ktmax)
            kv_load(sb, kh, vh, hb, kt + 2, tid);
        CP_COMMIT();
    }

    // ---- epilogue: normalize + write fp16 [hi|lo] expanded rows ----
    l0 += __shfl_xor_sync(0xffffffffu, l0, 1);
    l0 += __shfl_xor_sync(0xffffffffu, l0, 2);
    l1 += __shfl_xor_sync(0xffffffffu, l1, 1);
    l1 += __shfl_xor_sync(0xffffffffu, l1, 2);
    const float inv0 = 1.f / l0, inv1 = 1.f / l1;

    const size_t row0 = (size_t)(b * T_ + rg0) * KP_;
    const size_t row1 = row0 + (size_t)8 * KP_;
    #pragma unroll
    for (int d = 0; d < 8; d++) {
        const int c = h * 64 + d * 8 + tig * 2;
        float v0 = O[d][0] * inv0, v1 = O[d][1] * inv0;
        float v2 = O[d][2] * inv1, v3 = O[d][3] * inv1;
        __half h0 = __float2half(v0), h1 = __float2half(v1);
        __half h2 = __float2half(v2), h3 = __float2half(v3);
        __half e0 = __float2half(v0 - __half2float(h0));
        __half e1 = __float2half(v1 - __half2float(h1));
        __half e2 = __float2half(v2 - __half2float(h2));
        __half e3 = __float2half(v3 - __half2float(h3));
        *reinterpret_cast<uint32_t*>(yexp + row0 + c)      = pack_h2(h0, h1);
        *reinterpret_cast<uint32_t*>(yexp + row0 + C_ + c) = pack_h2(e0, e1);
        *reinterpret_cast<uint32_t*>(yexp + row1 + c)      = pack_h2(h2, h3);
        *reinterpret_cast<uint32_t*>(yexp + row1 + C_ + c) = pack_h2(e2, e3);
    }
}

// ---------------------------------------------------------------------------
extern "C" void kernel_launch(void* const* d_in, const int* in_sizes, int n_in,
                              void* d_out, int out_size)
{
    const float* x     = (const float*)d_in[0];
    const float* wkqv  = (const float*)d_in[1];
    const float* wproj = (const float*)d_in[2];
    const float* bproj = (const float*)d_in[3];
    float* out = (float*)d_out;

    __half *xe, *w1h, *ye, *w2h, *qh, *kh, *vh;
    cudaGetSymbolAddress((void**)&xe,  g_xe);
    cudaGetSymbolAddress((void**)&w1h, g_w1h);
    cudaGetSymbolAddress((void**)&ye,  g_yexp);
    cudaGetSymbolAddress((void**)&w2h, g_w2h);
    cudaGetSymbolAddress((void**)&qh,  g_qh);
    cudaGetSymbolAddress((void**)&kh,  g_kh);
    cudaGetSymbolAddress((void**)&vh,  g_vh);

    cudaFuncSetAttribute((const void*)gemm_mma<1>,
                         cudaFuncAttributeMaxDynamicSharedMemorySize, SMEM_TOTAL);
    cudaFuncSetAttribute((const void*)gemm_mma<2>,
                         cudaFuncAttributeMaxDynamicSharedMemorySize, SMEM_TOTAL);
    cudaFuncSetAttribute((const void*)attn_mma,
                         cudaFuncAttributeMaxDynamicSharedMemorySize, ATT_SMEM);

    // Prep
    split2h<<<(BT_ * C_ / 4 + 255) / 256, 256>>>(x, xe, BT_ * C_ / 4);
    tsplit2h<<<dim3(C3_ / 32, C_ / 32), dim3(32, 8)>>>(wkqv, w1h, C_, C3_);
    tsplit2h<<<dim3(C_ / 32, C_ / 32), dim3(32, 8)>>>(wproj, w2h, C_, C_);

    // 1) QKV GEMM (fp16 2-pass, K=2048) with fused per-head split epilogue
    {
        dim3 grid(C3_ / GBN, BT_ / GBM);   // (24, 32)
        gemm_mma<1><<<grid, 256, SMEM_TOTAL>>>(
            (const uint16_t*)xe, (const uint16_t*)w1h, nullptr, nullptr,
            qh, kh, vh, BT_, C3_, KP_);
    }

    // 2) MMA flash attention (single-pass fp16) -> g_yexp
    {
        dim3 grid(T_ / 128, H_, B_);       // (16, 16, 2)
        attn_mma<<<grid, 256, ATT_SMEM>>>(qh, kh, vh, ye);
    }

    // 3) proj GEMM (fp16 2-pass) + bias -> out
    {
        dim3 grid(C_ / GBN, BT_ / GBM);    // (8, 32)
        gemm_mma<2><<<grid, 256, SMEM_TOTAL>>>(
            (const uint16_t*)ye, (const uint16_t*)w2h, bproj, out,
            nullptr, nullptr, nullptr, BT_, C_, KP_);
    }
}

// round 10
// speedup vs baseline: 7.4271x; 1.1014x over previous
#include <cuda_runtime.h>
#include <cuda_bf16.h>
#include <cuda_fp16.h>
#include <cstdint>

// Problem constants (fixed by the reference)
#define B_   2
#define T_   2048
#define C_   1024
#define H_   16
#define HS_  64
#define C3_  3072
#define BT_  (B_*T_)          // 4096 rows

// ---------------------------------------------------------------------------
// Scratch (device globals — no runtime allocation allowed)
// ---------------------------------------------------------------------------
__device__ __half g_xh [(size_t)BT_ * C_];     // x hi fp16
__device__ __half g_xl [(size_t)BT_ * C_];     // x lo fp16 (residual)
__device__ __half g_w1h[(size_t)C3_ * C_];     // W_kqv^T [N,K] fp16
__device__ __half g_yh [(size_t)BT_ * C_];     // attn out hi fp16
__device__ __half g_yl [(size_t)BT_ * C_];     // attn out lo fp16
__device__ __half g_w2h[(size_t)C_  * C_];     // W_proj^T [N,K] fp16

// per-head attention operands [B, H, T, 64] fp16
#define NHE ((size_t)B_ * H_ * T_ * 64)
__device__ __half g_qh[NHE];                   // q fp16, pre-scaled 1/8
__device__ __half g_kh[NHE], g_vh[NHE];        // k, v fp16

// ---------------------------------------------------------------------------
// PTX helpers (no 'a'-gated instructions)
// ---------------------------------------------------------------------------
__device__ __forceinline__ uint32_t smem_u32(const void* p) {
    uint32_t a;
    asm("{ .reg .u64 t; cvta.to.shared.u64 t, %1; cvt.u32.u64 %0, t; }"
        : "=r"(a) : "l"(p));
    return a;
}

#define CP_ASYNC16(dst, src) \
    asm volatile("cp.async.cg.shared.global [%0], [%1], 16;" \
                 :: "r"(dst), "l"(src) : "memory")
#define CP_COMMIT() asm volatile("cp.async.commit_group;" ::: "memory")
#define CP_WAIT1()  asm volatile("cp.async.wait_group 1;" ::: "memory")
#define CP_WAIT2()  asm volatile("cp.async.wait_group 2;" ::: "memory")

#define LDSM_X4(r0, r1, r2, r3, addr) \
    asm volatile("ldmatrix.sync.aligned.m8n8.x4.shared.b16 {%0,%1,%2,%3}, [%4];" \
                 : "=r"(r0), "=r"(r1), "=r"(r2), "=r"(r3) : "r"(addr))
#define LDSM_X4T(r0, r1, r2, r3, addr) \
    asm volatile("ldmatrix.sync.aligned.m8n8.x4.trans.shared.b16 {%0,%1,%2,%3}, [%4];" \
                 : "=r"(r0), "=r"(r1), "=r"(r2), "=r"(r3) : "r"(addr))

#define MMAH(c, a, b0, b1) \
    asm volatile("mma.sync.aligned.m16n8k16.row.col.f32.f16.f16.f32 " \
                 "{%0,%1,%2,%3}, {%4,%5,%6,%7}, {%8,%9}, {%0,%1,%2,%3};" \
                 : "+f"((c)[0]), "+f"((c)[1]), "+f"((c)[2]), "+f"((c)[3]) \
                 : "r"((a)[0]), "r"((a)[1]), "r"((a)[2]), "r"((a)[3]), \
                   "r"(b0), "r"(b1))

__device__ __forceinline__ uint32_t pack_h2(__half a, __half b) {
    __half2 t = __halves2half2(a, b);
    return *reinterpret_cast<uint32_t*>(&t);
}

// ---------------------------------------------------------------------------
// Prep 1: x fp32 [R, C] -> hi/lo fp16 arrays (exact to ~2^-22)
// ---------------------------------------------------------------------------
__global__ __launch_bounds__(256)
void split2h(const float* __restrict__ in, __half* __restrict__ oh,
             __half* __restrict__ ol, int total4)
{
    int i = blockIdx.x * blockDim.x + threadIdx.x;
    if (i >= total4) return;
    float4 v = reinterpret_cast<const float4*>(in)[i];
    float vv[4] = {v.x, v.y, v.z, v.w};
    __half h[4], l[4];
    #pragma unroll
    for (int j = 0; j < 4; j++) {
        h[j] = __float2half(vv[j]);
        l[j] = __float2half(vv[j] - __half2float(h[j]));
    }
    reinterpret_cast<uint2*>(oh)[i] = make_uint2(pack_h2(h[0], h[1]), pack_h2(h[2], h[3]));
    reinterpret_cast<uint2*>(ol)[i] = make_uint2(pack_h2(l[0], l[1]), pack_h2(l[2], l[3]));
}

// ---------------------------------------------------------------------------
// Prep 2: W fp32 [K,N] -> W^T [N,K] fp16
// ---------------------------------------------------------------------------
__global__ __launch_bounds__(256)
void tconvh(const float* __restrict__ W, __half* __restrict__ out,
            int K, int N)
{
    __shared__ float t[32][33];
    const int n0 = blockIdx.x * 32, k0 = blockIdx.y * 32;
    const int tx = threadIdx.x, ty = threadIdx.y;
    #pragma unroll
    for (int r = 0; r < 4; r++)
        t[ty + 8 * r][tx] = W[(size_t)(k0 + ty + 8 * r) * N + n0 + tx];
    __syncthreads();
    #pragma unroll
    for (int r = 0; r < 4; r++) {
        const int n = n0 + ty + 8 * r, k = k0 + tx;
        out[(size_t)n * K + k] = __float2half(t[tx][ty + 8 * r]);
    }
}

// ---------------------------------------------------------------------------
// Shared-B hi/lo fp16 GEMM: C = (Ahi + Alo) @ B^T. K = 1024 real.
// Per chunk stage: Ahi 16K | Alo 16K | B 16K = 48KB; 2 stages (96KB, 2 CTA/SM).
// B fragments loaded once, used by both hi and lo MMA passes.
// EPI 1: QKV — write q (x1/8), k, v as single fp16 per-head arrays.
// EPI 2: proj — add bias, fp32 store.
// ---------------------------------------------------------------------------
#define GBM 128
#define GBN 128
#define GBK 64
#define STAGE_BYTES 49152          // 3 x 16KB
#define SMEM_TOTAL  (2 * STAGE_BYTES)

__device__ __forceinline__ void load_tile_async(
    uint32_t s_base, const uint16_t* __restrict__ g,
    int ld, int row0, int k0, int tid)
{
    #pragma unroll
    for (int it = 0; it < 4; it++) {
        int i = tid + it * 256;
        int row = i >> 3, c = i & 7;
        uint32_t dst = s_base + row * 128 + (((c ^ (row & 7))) << 4);
        const uint16_t* src = g + (size_t)(row0 + row) * ld + k0 + c * 8;
        CP_ASYNC16(dst, src);
    }
}

template<int EPI>
__global__ __launch_bounds__(256, 2)
void gemm_mma(const uint16_t* __restrict__ Ahi,
              const uint16_t* __restrict__ Alo,
              const uint16_t* __restrict__ Bt,
              const float* __restrict__ bias, float* __restrict__ C,
              __half* __restrict__ qh, __half* __restrict__ kh,
              __half* __restrict__ vh,
              int M, int N, int K)
{
    extern __shared__ char sm[];
    const uint32_t sbase = smem_u32(sm);
    const int tid = threadIdx.x;
    const int wid = tid >> 5, lane = tid & 31;
    const int wm = wid >> 1, wn = wid & 1;
    const int m0 = blockIdx.y * GBM, n0 = blockIdx.x * GBN;

    float acc[2][8][4];
    #pragma unroll
    for (int mt = 0; mt < 2; mt++)
        #pragma unroll
        for (int nt = 0; nt < 8; nt++)
            #pragma unroll
            for (int j = 0; j < 4; j++) acc[mt][nt][j] = 0.f;

    const int nchunks = K / GBK;    // 16

    // Prologue: stages 0,1
    #pragma unroll
    for (int s = 0; s < 2; s++) {
        const uint32_t st = sbase + s * STAGE_BYTES;
        load_tile_async(st,         Ahi, K, m0, s * GBK, tid);
        load_tile_async(st + 16384, Alo, K, m0, s * GBK, tid);
        load_tile_async(st + 32768, Bt,  K, n0, s * GBK, tid);
        CP_COMMIT();
    }

    const int a_row  = wm * 32 + (lane & 15);
    const int a_cadd = (lane >> 4);
    const int b_row  = wn * 64 + (lane & 7) + ((lane >> 4) << 3);
    const int b_cadd = (lane >> 3) & 1;

    for (int ch = 0; ch < nchunks; ch++) {
        CP_WAIT1();
        __syncthreads();

        const uint32_t st = sbase + (ch & 1) * STAGE_BYTES;
        const uint32_t sAh = st, sAl = st + 16384, sB = st + 32768;

        #pragma unroll
        for (int ks = 0; ks < 4; ks++) {
            const int c16 = ks * 2;
            uint32_t ah[2][4], al[2][4];
            #pragma unroll
            for (int mt = 0; mt < 2; mt++) {
                const int row = a_row + mt * 16;
                const int cc  = c16 + a_cadd;
                uint32_t ad = sAh + row * 128 + ((cc ^ (row & 7)) << 4);
                LDSM_X4(ah[mt][0], ah[mt][1], ah[mt][2], ah[mt][3], ad);
                ad = sAl + row * 128 + ((cc ^ (row & 7)) << 4);
                LDSM_X4(al[mt][0], al[mt][1], al[mt][2], al[mt][3], ad);
            }
            uint32_t b[4][4];
            #pragma unroll
            for (int ntp = 0; ntp < 4; ntp++) {
                const int row = b_row + ntp * 16;
                const int cc  = c16 + b_cadd;
                const uint32_t ad = sB + row * 128 + ((cc ^ (row & 7)) << 4);
                LDSM_X4(b[ntp][0], b[ntp][1], b[ntp][2], b[ntp][3], ad);
            }
            #pragma unroll
            for (int mt = 0; mt < 2; mt++)
                #pragma unroll
                for (int nt = 0; nt < 8; nt++) {
                    const uint32_t b0 = b[nt >> 1][(nt & 1) * 2];
                    const uint32_t b1 = b[nt >> 1][(nt & 1) * 2 + 1];
                    MMAH(acc[mt][nt], ah[mt], b0, b1);
                    MMAH(acc[mt][nt], al[mt], b0, b1);
                }
        }

        __syncthreads();   // all warps done with stage ch&1 before reload
        if (ch + 2 < nchunks) {
            const uint32_t nb = sbase + (ch & 1) * STAGE_BYTES;
            load_tile_async(nb,         Ahi, K, m0, (ch + 2) * GBK, tid);
            load_tile_async(nb + 16384, Alo, K, m0, (ch + 2) * GBK, tid);
            load_tile_async(nb + 32768, Bt,  K, n0, (ch + 2) * GBK, tid);
        }
        CP_COMMIT();
    }

    const int gid = lane >> 2, tig = lane & 3;

    if (EPI == 2) {
        #pragma unroll
        for (int mt = 0; mt < 2; mt++) {
            #pragma unroll
            for (int nt = 0; nt < 8; nt++) {
                const int col = n0 + wn * 64 + nt * 8 + tig * 2;
                const float bx = bias[col], by = bias[col + 1];
                const int r0 = m0 + wm * 32 + mt * 16 + gid;
                float2 v0 = { acc[mt][nt][0] + bx, acc[mt][nt][1] + by };
                float2 v1 = { acc[mt][nt][2] + bx, acc[mt][nt][3] + by };
                *reinterpret_cast<float2*>(&C[(size_t)r0 * N + col])       = v0;
                *reinterpret_cast<float2*>(&C[(size_t)(r0 + 8) * N + col]) = v1;
            }
        }
    } else {  // EPI == 1: QKV per-head split epilogue (single fp16)
        #pragma unroll
        for (int mt = 0; mt < 2; mt++) {
            #pragma unroll
            for (int nt = 0; nt < 8; nt++) {
                const int col   = n0 + wn * 64 + nt * 8 + tig * 2;
                const int which = col >> 10;            // 0=q 1=k 2=v
                const int hh    = (col >> 6) & 15;
                const int d     = col & 63;
                const float sc  = (which == 0) ? 0.125f : 1.0f;
                __half* p = (which == 0) ? qh : (which == 1) ? kh : vh;
                #pragma unroll
                for (int rr = 0; rr < 2; rr++) {
                    const int r  = m0 + wm * 32 + mt * 16 + gid + rr * 8;
                    const int bb = r >> 11, t = r & 2047;
                    const size_t off = (((size_t)(bb * 16 + hh)) * 2048 + t) * 64 + d;
                    *reinterpret_cast<uint32_t*>(p + off) =
                        pack_h2(__float2half(acc[mt][nt][rr * 2 + 0] * sc),
                                __float2half(acc[mt][nt][rr * 2 + 1] * sc));
                }
            }
        }
    }
}

// ---------------------------------------------------------------------------
// MMA flash attention, single-pass fp16, 3-stage cp.async K/V pipeline.
// Output written as separate hi/lo fp16 arrays for the proj GEMM.
// smem: Q 16K | 3 x (Kh 8K, Vh 8K) = 64KB
// ---------------------------------------------------------------------------
#define ATT_SMEM (16384 + 3 * 16384)

__device__ __forceinline__ void kv_load(uint32_t sb,
    const __half* __restrict__ kh, const __half* __restrict__ vh,
    size_t hb, int kt, int tid)
{
    const uint32_t stage = sb + 16384 + (kt % 3) * 16384;
    #pragma unroll
    for (int it = 0; it < 4; it++) {
        int i = tid + (it & 1) * 256;            // 0..511
        int row = i >> 3, c = i & 7;
        const __half* g = (it < 2) ? kh : vh;
        uint32_t dst = stage + ((it < 2) ? 0 : 8192)
                     + row * 128 + ((c ^ (row & 7)) << 4);
        CP_ASYNC16(dst, g + hb + (size_t)(kt * 64 + row) * 64 + c * 8);
    }
}

__global__ __launch_bounds__(256, 1)
void attn_mma(const __half* __restrict__ qh,
              const __half* __restrict__ kh, const __half* __restrict__ vh,
              __half* __restrict__ yh, __half* __restrict__ yl)
{
    extern __shared__ char sm[];
    const uint32_t sb = smem_u32(sm);
    const uint32_t sQ = sb;

    const int tid = threadIdx.x, wid = tid >> 5, lane = tid & 31;
    const int qt = gridDim.x - 1 - blockIdx.x;    // heavy q-tiles first
    const int h = blockIdx.y, b = blockIdx.z;
    const size_t hb = ((size_t)(b * H_ + h)) * T_ * 64;
    const int ktmax = 2 * (qt + 1);               // >= 2

    // Stage Q tile (128 rows x 8 x 16B)
    #pragma unroll
    for (int it = 0; it < 4; it++) {
        int i = tid + it * 256;
        int row = i >> 3, c = i & 7;
        uint32_t dst = sQ + row * 128 + ((c ^ (row & 7)) << 4);
        CP_ASYNC16(dst, qh + hb + (size_t)(qt * 128 + row) * 64 + c * 8);
    }
    CP_COMMIT();                                   // g0: Q
    kv_load(sb, kh, vh, hb, 0, tid);
    CP_COMMIT();                                   // g1: KV0
    kv_load(sb, kh, vh, hb, 1, tid);
    CP_COMMIT();                                   // g2: KV1

    const int gid = lane >> 2, tig = lane & 3;
    const int arow   = wid * 16 + (lane & 15);
    const int acadd  = lane >> 4;
    const int kbrow  = (lane & 7) + ((lane >> 4) << 3);
    const int kbcadd = (lane >> 3) & 1;
    const int vbrow  = (lane & 7) + (((lane >> 3) & 1) << 3);
    const int vbcadd = lane >> 4;

    // Q fragments (loop-invariant), hoisted after g0 lands
    CP_WAIT2();
    __syncthreads();
    uint32_t aq[4][4];
    #pragma unroll
    for (int ks = 0; ks < 4; ks++) {
        const int c16 = ks * 2 + acadd;
        uint32_t ad = sQ + arow * 128 + ((c16 ^ (arow & 7)) << 4);
        LDSM_X4(aq[ks][0], aq[ks][1], aq[ks][2], aq[ks][3], ad);
    }

    float m0 = -1e30f, m1 = -1e30f, l0 = 0.f, l1 = 0.f;
    float O[8][4];
    #pragma unroll
    for (int d = 0; d < 8; d++)
        #pragma unroll
        for (int j = 0; j < 4; j++) O[d][j] = 0.f;

    const int rg0 = qt * 128 + wid * 16 + gid;

    for (int kt = 0; kt < ktmax; kt++) {
        CP_WAIT1();
        __syncthreads();

        const uint32_t stage = sb + 16384 + (kt % 3) * 16384;
        const uint32_t sKh = stage, sVh = stage + 8192;

        const bool active = (kt * 64) <= (qt * 128 + wid * 16 + 15);
        if (active) {
            // ---- S = QK^T (single pass) ----
            float S[8][4];
            #pragma unroll
            for (int nt = 0; nt < 8; nt++)
                #pragma unroll
                for (int j = 0; j < 4; j++) S[nt][j] = 0.f;

            #pragma unroll
            for (int ks = 0; ks < 4; ks++) {
                const int c16 = ks * 2;
                uint32_t bh[4][4];
                #pragma unroll
                for (int jn = 0; jn < 4; jn++) {
                    const int row = jn * 16 + kbrow;
                    const int cc  = c16 + kbcadd;
                    uint32_t ad = sKh + row * 128 + ((cc ^ (row & 7)) << 4);
                    LDSM_X4(bh[jn][0], bh[jn][1], bh[jn][2], bh[jn][3], ad);
                }
                #pragma unroll
                for (int nt = 0; nt < 8; nt++)
                    MMAH(S[nt], aq[ks],
                         bh[nt >> 1][(nt & 1) * 2],
                         bh[nt >> 1][(nt & 1) * 2 + 1]);
            }

            // ---- causal mask (diagonal tiles only) ----
            if (kt >= 2 * qt) {
                #pragma unroll
                for (int nt = 0; nt < 8; nt++) {
                    const int jg = kt * 64 + nt * 8 + tig * 2;
                    if (jg     > rg0)     S[nt][0] = -1e30f;
                    if (jg + 1 > rg0)     S[nt][1] = -1e30f;
                    if (jg     > rg0 + 8) S[nt][2] = -1e30f;
                    if (jg + 1 > rg0 + 8) S[nt][3] = -1e30f;
                }
            }

            // ---- online softmax ----
            float t0 = -1e30f, t1 = -1e30f;
            #pragma unroll
            for (int nt = 0; nt < 8; nt++) {
                t0 = fmaxf(t0, fmaxf(S[nt][0], S[nt][1]));
                t1 = fmaxf(t1, fmaxf(S[nt][2], S[nt][3]));
            }
            t0 = fmaxf(t0, __shfl_xor_sync(0xffffffffu, t0, 1));
            t0 = fmaxf(t0, __shfl_xor_sync(0xffffffffu, t0, 2));
            t1 = fmaxf(t1, __shfl_xor_sync(0xffffffffu, t1, 1));
            t1 = fmaxf(t1, __shfl_xor_sync(0xffffffffu, t1, 2));
            const float mn0 = fmaxf(m0, t0), mn1 = fmaxf(m1, t1);
            const float a0 = __expf(m0 - mn0), a1 = __expf(m1 - mn1);
            m0 = mn0; m1 = mn1;
            l0 *= a0;  l1 *= a1;
            #pragma unroll
            for (int d = 0; d < 8; d++) {
                O[d][0] *= a0; O[d][1] *= a0;
                O[d][2] *= a1; O[d][3] *= a1;
            }

            // ---- P = exp(S-m), single fp16 A-fragments ----
            uint32_t pf[4][4];
            #pragma unroll
            for (int nt = 0; nt < 8; nt++) {
                const float p0 = __expf(S[nt][0] - m0);
                const float p1 = __expf(S[nt][1] - m0);
                const float p2 = __expf(S[nt][2] - m1);
                const float p3 = __expf(S[nt][3] - m1);
                l0 += p0 + p1;
                l1 += p2 + p3;
                const int jb = nt >> 1, o = (nt & 1) * 2;
                pf[jb][o]     = pack_h2(__float2half(p0), __float2half(p1));
                pf[jb][o + 1] = pack_h2(__float2half(p2), __float2half(p3));
            }

            // ---- O += P @ V (single pass) ----
            #pragma unroll
            for (int jb = 0; jb < 4; jb++) {
                #pragma unroll
                for (int dp = 0; dp < 4; dp++) {
                    const int row = jb * 16 + vbrow;
                    const int cc  = dp * 2 + vbcadd;
                    uint32_t vv[4];
                    uint32_t ad = sVh + row * 128 + ((cc ^ (row & 7)) << 4);
                    LDSM_X4T(vv[0], vv[1], vv[2], vv[3], ad);
                    const int d0 = dp * 2;
                    MMAH(O[d0],     pf[jb], vv[0], vv[1]);
                    MMAH(O[d0 + 1], pf[jb], vv[2], vv[3]);
                }
            }
        }

        if (kt + 2 < ktmax)
            kv_load(sb, kh, vh, hb, kt + 2, tid);
        CP_COMMIT();
    }

    // ---- epilogue: normalize + write fp16 hi/lo arrays ----
    l0 += __shfl_xor_sync(0xffffffffu, l0, 1);
    l0 += __shfl_xor_sync(0xffffffffu, l0, 2);
    l1 += __shfl_xor_sync(0xffffffffu, l1, 1);
    l1 += __shfl_xor_sync(0xffffffffu, l1, 2);
    const float inv0 = 1.f / l0, inv1 = 1.f / l1;

    const size_t row0 = (size_t)(b * T_ + rg0) * C_;
    const size_t row1 = row0 + (size_t)8 * C_;
    #pragma unroll
    for (int d = 0; d < 8; d++) {
        const int c = h * 64 + d * 8 + tig * 2;
        float v0 = O[d][0] * inv0, v1 = O[d][1] * inv0;
        float v2 = O[d][2] * inv1, v3 = O[d][3] * inv1;
        __half h0 = __float2half(v0), h1 = __float2half(v1);
        __half h2 = __float2half(v2), h3 = __float2half(v3);
        __half e0 = __float2half(v0 - __half2float(h0));
        __half e1 = __float2half(v1 - __half2float(h1));
        __half e2 = __float2half(v2 - __half2float(h2));
        __half e3 = __float2half(v3 - __half2float(h3));
        *reinterpret_cast<uint32_t*>(yh + row0 + c) = pack_h2(h0, h1);
        *reinterpret_cast<uint32_t*>(yl + row0 + c) = pack_h2(e0, e1);
        *reinterpret_cast<uint32_t*>(yh + row1 + c) = pack_h2(h2, h3);
        *reinterpret_cast<uint32_t*>(yl + row1 + c) = pack_h2(e2, e3);
    }
}

// ---------------------------------------------------------------------------
extern "C" void kernel_launch(void* const* d_in, const int* in_sizes, int n_in,
                              void* d_out, int out_size)
{
    const float* x     = (const float*)d_in[0];
    const float* wkqv  = (const float*)d_in[1];
    const float* wproj = (const float*)d_in[2];
    const float* bproj = (const float*)d_in[3];
    float* out = (float*)d_out;

    __half *xh, *xl, *w1h, *yh, *yl, *w2h, *qh, *kh, *vh;
    cudaGetSymbolAddress((void**)&xh,  g_xh);
    cudaGetSymbolAddress((void**)&xl,  g_xl);
    cudaGetSymbolAddress((void**)&w1h, g_w1h);
    cudaGetSymbolAddress((void**)&yh,  g_yh);
    cudaGetSymbolAddress((void**)&yl,  g_yl);
    cudaGetSymbolAddress((void**)&w2h, g_w2h);
    cudaGetSymbolAddress((void**)&qh,  g_qh);
    cudaGetSymbolAddress((void**)&kh,  g_kh);
    cudaGetSymbolAddress((void**)&vh,  g_vh);

    cudaFuncSetAttribute((const void*)gemm_mma<1>,
                         cudaFuncAttributeMaxDynamicSharedMemorySize, SMEM_TOTAL);
    cudaFuncSetAttribute((const void*)gemm_mma<2>,
                         cudaFuncAttributeMaxDynamicSharedMemorySize, SMEM_TOTAL);
    cudaFuncSetAttribute((const void*)attn_mma,
                         cudaFuncAttributeMaxDynamicSharedMemorySize, ATT_SMEM);

    // Prep
    split2h<<<(BT_ * C_ / 4 + 255) / 256, 256>>>(x, xh, xl, BT_ * C_ / 4);
    tconvh<<<dim3(C3_ / 32, C_ / 32), dim3(32, 8)>>>(wkqv, w1h, C_, C3_);
    tconvh<<<dim3(C_ / 32, C_ / 32), dim3(32, 8)>>>(wproj, w2h, C_, C_);

    // 1) QKV GEMM (shared-B hi/lo fp16, K=1024) with fused split epilogue
    {
        dim3 grid(C3_ / GBN, BT_ / GBM);   // (24, 32)
        gemm_mma<1><<<grid, 256, SMEM_TOTAL>>>(
            (const uint16_t*)xh, (const uint16_t*)xl, (const uint16_t*)w1h,
            nullptr, nullptr, qh, kh, vh, BT_, C3_, C_);
    }

    // 2) MMA flash attention (single-pass fp16) -> yh/yl
    {
        dim3 grid(T_ / 128, H_, B_);       // (16, 16, 2)
        attn_mma<<<grid, 256, ATT_SMEM>>>(qh, kh, vh, yh, yl);
    }

    // 3) proj GEMM (shared-B hi/lo fp16) + bias -> out
    {
        dim3 grid(C_ / GBN, BT_ / GBM);    // (8, 32)
        gemm_mma<2><<<grid, 256, SMEM_TOTAL>>>(
            (const uint16_t*)yh, (const uint16_t*)yl, (const uint16_t*)w2h,
            bproj, out, nullptr, nullptr, nullptr, BT_, C_, C_);
    }
}

// round 11
// speedup vs baseline: 8.9273x; 1.2020x over previous
#include <cuda_runtime.h>
#include <cuda_bf16.h>
#include <cuda_fp16.h>
#include <cstdint>

// Problem constants (fixed by the reference)
#define B_   2
#define T_   2048
#define C_   1024
#define H_   16
#define HS_  64
#define C3_  3072
#define BT_  (B_*T_)          // 4096 rows

// ---------------------------------------------------------------------------
// Scratch (device globals — no runtime allocation allowed)
// ---------------------------------------------------------------------------
__device__ __half g_xh [(size_t)BT_ * C_];     // x fp16
__device__ __half g_w1h[(size_t)C3_ * C_];     // W_kqv^T [N,K] fp16
__device__ __half g_yh [(size_t)BT_ * C_];     // attn out hi fp16
__device__ __half g_yl [(size_t)BT_ * C_];     // attn out lo fp16
__device__ __half g_w2h[(size_t)C_  * C_];     // W_proj^T [N,K] fp16

// per-head attention operands [B, H, T, 64] fp16
#define NHE ((size_t)B_ * H_ * T_ * 64)
__device__ __half g_qh[NHE];                   // q fp16, pre-scaled 1/8
__device__ __half g_kh[NHE], g_vh[NHE];        // k, v fp16

// ---------------------------------------------------------------------------
// PTX helpers (no 'a'-gated instructions)
// ---------------------------------------------------------------------------
__device__ __forceinline__ uint32_t smem_u32(const void* p) {
    uint32_t a;
    asm("{ .reg .u64 t; cvta.to.shared.u64 t, %1; cvt.u32.u64 %0, t; }"
        : "=r"(a) : "l"(p));
    return a;
}

#define CP_ASYNC16(dst, src) \
    asm volatile("cp.async.cg.shared.global [%0], [%1], 16;" \
                 :: "r"(dst), "l"(src) : "memory")
#define CP_COMMIT() asm volatile("cp.async.commit_group;" ::: "memory")
#define CP_WAIT1()  asm volatile("cp.async.wait_group 1;" ::: "memory")
#define CP_WAIT2()  asm volatile("cp.async.wait_group 2;" ::: "memory")

#define LDSM_X4(r0, r1, r2, r3, addr) \
    asm volatile("ldmatrix.sync.aligned.m8n8.x4.shared.b16 {%0,%1,%2,%3}, [%4];" \
                 : "=r"(r0), "=r"(r1), "=r"(r2), "=r"(r3) : "r"(addr))
#define LDSM_X4T(r0, r1, r2, r3, addr) \
    asm volatile("ldmatrix.sync.aligned.m8n8.x4.trans.shared.b16 {%0,%1,%2,%3}, [%4];" \
                 : "=r"(r0), "=r"(r1), "=r"(r2), "=r"(r3) : "r"(addr))

#define MMAH(c, a, b0, b1) \
    asm volatile("mma.sync.aligned.m16n8k16.row.col.f32.f16.f16.f32 " \
                 "{%0,%1,%2,%3}, {%4,%5,%6,%7}, {%8,%9}, {%0,%1,%2,%3};" \
                 : "+f"((c)[0]), "+f"((c)[1]), "+f"((c)[2]), "+f"((c)[3]) \
                 : "r"((a)[0]), "r"((a)[1]), "r"((a)[2]), "r"((a)[3]), \
                   "r"(b0), "r"(b1))

__device__ __forceinline__ uint32_t pack_h2(__half a, __half b) {
    __half2 t = __halves2half2(a, b);
    return *reinterpret_cast<uint32_t*>(&t);
}

// ---------------------------------------------------------------------------
// Prep 1: x fp32 -> fp16 (single precision path)
// ---------------------------------------------------------------------------
__global__ __launch_bounds__(256)
void cvth(const float* __restrict__ in, __half* __restrict__ out, int total4)
{
    int i = blockIdx.x * blockDim.x + threadIdx.x;
    if (i >= total4) return;
    float4 v = reinterpret_cast<const float4*>(in)[i];
    reinterpret_cast<uint2*>(out)[i] =
        make_uint2(pack_h2(__float2half(v.x), __float2half(v.y)),
                   pack_h2(__float2half(v.z), __float2half(v.w)));
}

// ---------------------------------------------------------------------------
// Prep 2: W fp32 [K,N] -> W^T [N,K] fp16
// ---------------------------------------------------------------------------
__global__ __launch_bounds__(256)
void tconvh(const float* __restrict__ W, __half* __restrict__ out,
            int K, int N)
{
    __shared__ float t[32][33];
    const int n0 = blockIdx.x * 32, k0 = blockIdx.y * 32;
    const int tx = threadIdx.x, ty = threadIdx.y;
    #pragma unroll
    for (int r = 0; r < 4; r++)
        t[ty + 8 * r][tx] = W[(size_t)(k0 + ty + 8 * r) * N + n0 + tx];
    __syncthreads();
    #pragma unroll
    for (int r = 0; r < 4; r++) {
        const int n = n0 + ty + 8 * r, k = k0 + tx;
        out[(size_t)n * K + k] = __float2half(t[tx][ty + 8 * r]);
    }
}

// ---------------------------------------------------------------------------
// fp16 GEMM, templated:
//  HILO=false: C = A @ B^T           — 3-stage (32KB/stage), 1 sync/chunk
//  HILO=true : C = (Ahi+Alo) @ B^T   — 2-stage (48KB/stage), shared-B frags
// EPI 1: QKV per-head split epilogue. EPI 2: bias + fp32 store.
// ---------------------------------------------------------------------------
#define GBM 128
#define GBN 128
#define GBK 64
#define STG_S 32768                   // single: A 16K + B 16K
#define STG_H 49152                   // hilo:   Ah 16K + Al 16K + B 16K
#define SMEM_TOTAL 98304              // = 3*STG_S = 2*STG_H

__device__ __forceinline__ void load_tile_async(
    uint32_t s_base, const uint16_t* __restrict__ g,
    int ld, int row0, int k0, int tid)
{
    #pragma unroll
    for (int it = 0; it < 4; it++) {
        int i = tid + it * 256;
        int row = i >> 3, c = i & 7;
        uint32_t dst = s_base + row * 128 + (((c ^ (row & 7))) << 4);
        const uint16_t* src = g + (size_t)(row0 + row) * ld + k0 + c * 8;
        CP_ASYNC16(dst, src);
    }
}

template<int EPI, bool HILO>
__global__ __launch_bounds__(256, 2)
void gemm_mma(const uint16_t* __restrict__ Ahi,
              const uint16_t* __restrict__ Alo,
              const uint16_t* __restrict__ Bt,
              const float* __restrict__ bias, float* __restrict__ C,
              __half* __restrict__ qh, __half* __restrict__ kh,
              __half* __restrict__ vh,
              int M, int N, int K)
{
    extern __shared__ char sm[];
    const uint32_t sbase = smem_u32(sm);
    const int tid = threadIdx.x;
    const int wid = tid >> 5, lane = tid & 31;
    const int wm = wid >> 1, wn = wid & 1;
    const int m0 = blockIdx.y * GBM, n0 = blockIdx.x * GBN;

    float acc[2][8][4];
    #pragma unroll
    for (int mt = 0; mt < 2; mt++)
        #pragma unroll
        for (int nt = 0; nt < 8; nt++)
            #pragma unroll
            for (int j = 0; j < 4; j++) acc[mt][nt][j] = 0.f;

    const int nchunks = K / GBK;    // 16

    // Prologue: stages 0,1
    #pragma unroll
    for (int s = 0; s < 2; s++) {
        if (HILO) {
            const uint32_t st = sbase + s * STG_H;
            load_tile_async(st,         Ahi, K, m0, s * GBK, tid);
            load_tile_async(st + 16384, Alo, K, m0, s * GBK, tid);
            load_tile_async(st + 32768, Bt,  K, n0, s * GBK, tid);
        } else {
            const uint32_t st = sbase + s * STG_S;
            load_tile_async(st,         Ahi, K, m0, s * GBK, tid);
            load_tile_async(st + 16384, Bt,  K, n0, s * GBK, tid);
        }
        CP_COMMIT();
    }

    const int a_row  = wm * 32 + (lane & 15);
    const int a_cadd = (lane >> 4);
    const int b_row  = wn * 64 + (lane & 7) + ((lane >> 4) << 3);
    const int b_cadd = (lane >> 3) & 1;

    for (int ch = 0; ch < nchunks; ch++) {
        CP_WAIT1();
        __syncthreads();

        const uint32_t st = HILO ? (sbase + (ch & 1) * STG_H)
                                 : (sbase + (ch % 3) * STG_S);
        const uint32_t sAh = st;
        const uint32_t sAl = st + 16384;                 // HILO only
        const uint32_t sB  = st + (HILO ? 32768 : 16384);

        #pragma unroll
        for (int ks = 0; ks < 4; ks++) {
            const int c16 = ks * 2;
            uint32_t ah[2][4], al[2][4];
            #pragma unroll
            for (int mt = 0; mt < 2; mt++) {
                const int row = a_row + mt * 16;
                const int cc  = c16 + a_cadd;
                uint32_t ad = sAh + row * 128 + ((cc ^ (row & 7)) << 4);
                LDSM_X4(ah[mt][0], ah[mt][1], ah[mt][2], ah[mt][3], ad);
                if (HILO) {
                    ad = sAl + row * 128 + ((cc ^ (row & 7)) << 4);
                    LDSM_X4(al[mt][0], al[mt][1], al[mt][2], al[mt][3], ad);
                }
            }
            uint32_t b[4][4];
            #pragma unroll
            for (int ntp = 0; ntp < 4; ntp++) {
                const int row = b_row + ntp * 16;
                const int cc  = c16 + b_cadd;
                const uint32_t ad = sB + row * 128 + ((cc ^ (row & 7)) << 4);
                LDSM_X4(b[ntp][0], b[ntp][1], b[ntp][2], b[ntp][3], ad);
            }
            #pragma unroll
            for (int mt = 0; mt < 2; mt++)
                #pragma unroll
                for (int nt = 0; nt < 8; nt++) {
                    const uint32_t b0 = b[nt >> 1][(nt & 1) * 2];
                    const uint32_t b1 = b[nt >> 1][(nt & 1) * 2 + 1];
                    MMAH(acc[mt][nt], ah[mt], b0, b1);
                    if (HILO) MMAH(acc[mt][nt], al[mt], b0, b1);
                }
        }

        if (HILO) {
            // 2-stage: must guard buffer reuse before reloading same stage
            __syncthreads();
            if (ch + 2 < nchunks) {
                const uint32_t nb = sbase + (ch & 1) * STG_H;
                load_tile_async(nb,         Ahi, K, m0, (ch + 2) * GBK, tid);
                load_tile_async(nb + 16384, Alo, K, m0, (ch + 2) * GBK, tid);
                load_tile_async(nb + 32768, Bt,  K, n0, (ch + 2) * GBK, tid);
            }
        } else {
            // 3-stage: top wait+sync already guards stage (ch+2)%3
            if (ch + 2 < nchunks) {
                const uint32_t nb = sbase + ((ch + 2) % 3) * STG_S;
                load_tile_async(nb,         Ahi, K, m0, (ch + 2) * GBK, tid);
                load_tile_async(nb + 16384, Bt,  K, n0, (ch + 2) * GBK, tid);
            }
        }
        CP_COMMIT();
    }

    const int gid = lane >> 2, tig = lane & 3;

    if (EPI == 2) {
        #pragma unroll
        for (int mt = 0; mt < 2; mt++) {
            #pragma unroll
            for (int nt = 0; nt < 8; nt++) {
                const int col = n0 + wn * 64 + nt * 8 + tig * 2;
                const float bx = bias[col], by = bias[col + 1];
                const int r0 = m0 + wm * 32 + mt * 16 + gid;
                float2 v0 = { acc[mt][nt][0] + bx, acc[mt][nt][1] + by };
                float2 v1 = { acc[mt][nt][2] + bx, acc[mt][nt][3] + by };
                *reinterpret_cast<float2*>(&C[(size_t)r0 * N + col])       = v0;
                *reinterpret_cast<float2*>(&C[(size_t)(r0 + 8) * N + col]) = v1;
            }
        }
    } else {  // EPI == 1: QKV per-head split epilogue (single fp16)
        #pragma unroll
        for (int mt = 0; mt < 2; mt++) {
            #pragma unroll
            for (int nt = 0; nt < 8; nt++) {
                const int col   = n0 + wn * 64 + nt * 8 + tig * 2;
                const int which = col >> 10;            // 0=q 1=k 2=v
                const int hh    = (col >> 6) & 15;
                const int d     = col & 63;
                const float sc  = (which == 0) ? 0.125f : 1.0f;
                __half* p = (which == 0) ? qh : (which == 1) ? kh : vh;
                #pragma unroll
                for (int rr = 0; rr < 2; rr++) {
                    const int r  = m0 + wm * 32 + mt * 16 + gid + rr * 8;
                    const int bb = r >> 11, t = r & 2047;
                    const size_t off = (((size_t)(bb * 16 + hh)) * 2048 + t) * 64 + d;
                    *reinterpret_cast<uint32_t*>(p + off) =
                        pack_h2(__float2half(acc[mt][nt][rr * 2 + 0] * sc),
                                __float2half(acc[mt][nt][rr * 2 + 1] * sc));
                }
            }
        }
    }
}

// ---------------------------------------------------------------------------
// MMA flash attention, single-pass fp16, 3-stage cp.async K/V pipeline.
// Output written as separate hi/lo fp16 arrays for the proj GEMM.
// smem: Q 16K | 3 x (Kh 8K, Vh 8K) = 64KB
// ---------------------------------------------------------------------------
#define ATT_SMEM (16384 + 3 * 16384)

__device__ __forceinline__ void kv_load(uint32_t sb,
    const __half* __restrict__ kh, const __half* __restrict__ vh,
    size_t hb, int kt, int tid)
{
    const uint32_t stage = sb + 16384 + (kt % 3) * 16384;
    #pragma unroll
    for (int it = 0; it < 4; it++) {
        int i = tid + (it & 1) * 256;            // 0..511
        int row = i >> 3, c = i & 7;
        const __half* g = (it < 2) ? kh : vh;
        uint32_t dst = stage + ((it < 2) ? 0 : 8192)
                     + row * 128 + ((c ^ (row & 7)) << 4);
        CP_ASYNC16(dst, g + hb + (size_t)(kt * 64 + row) * 64 + c * 8);
    }
}

__global__ __launch_bounds__(256, 1)
void attn_mma(const __half* __restrict__ qh,
              const __half* __restrict__ kh, const __half* __restrict__ vh,
              __half* __restrict__ yh, __half* __restrict__ yl)
{
    extern __shared__ char sm[];
    const uint32_t sb = smem_u32(sm);
    const uint32_t sQ = sb;

    const int tid = threadIdx.x, wid = tid >> 5, lane = tid & 31;
    const int qt = gridDim.x - 1 - blockIdx.x;    // heavy q-tiles first
    const int h = blockIdx.y, b = blockIdx.z;
    const size_t hb = ((size_t)(b * H_ + h)) * T_ * 64;
    const int ktmax = 2 * (qt + 1);               // >= 2

    // Stage Q tile (128 rows x 8 x 16B)
    #pragma unroll
    for (int it = 0; it < 4; it++) {
        int i = tid + it * 256;
        int row = i >> 3, c = i & 7;
        uint32_t dst = sQ + row * 128 + ((c ^ (row & 7)) << 4);
        CP_ASYNC16(dst, qh + hb + (size_t)(qt * 128 + row) * 64 + c * 8);
    }
    CP_COMMIT();                                   // g0: Q
    kv_load(sb, kh, vh, hb, 0, tid);
    CP_COMMIT();                                   // g1: KV0
    kv_load(sb, kh, vh, hb, 1, tid);
    CP_COMMIT();                                   // g2: KV1

    const int gid = lane >> 2, tig = lane & 3;
    const int arow   = wid * 16 + (lane & 15);
    const int acadd  = lane >> 4;
    const int kbrow  = (lane & 7) + ((lane >> 4) << 3);
    const int kbcadd = (lane >> 3) & 1;
    const int vbrow  = (lane & 7) + (((lane >> 3) & 1) << 3);
    const int vbcadd = lane >> 4;

    // Q fragments (loop-invariant), hoisted after g0 lands
    CP_WAIT2();
    __syncthreads();
    uint32_t aq[4][4];
    #pragma unroll
    for (int ks = 0; ks < 4; ks++) {
        const int c16 = ks * 2 + acadd;
        uint32_t ad = sQ + arow * 128 + ((c16 ^ (arow & 7)) << 4);
        LDSM_X4(aq[ks][0], aq[ks][1], aq[ks][2], aq[ks][3], ad);
    }

    float m0 = -1e30f, m1 = -1e30f, l0 = 0.f, l1 = 0.f;
    float O[8][4];
    #pragma unroll
    for (int d = 0; d < 8; d++)
        #pragma unroll
        for (int j = 0; j < 4; j++) O[d][j] = 0.f;

    const int rg0 = qt * 128 + wid * 16 + gid;

    for (int kt = 0; kt < ktmax; kt++) {
        CP_WAIT1();
        __syncthreads();

        const uint32_t stage = sb + 16384 + (kt % 3) * 16384;
        const uint32_t sKh = stage, sVh = stage + 8192;

        const bool active = (kt * 64) <= (qt * 128 + wid * 16 + 15);
        if (active) {
            // ---- S = QK^T (single pass) ----
            float S[8][4];
            #pragma unroll
            for (int nt = 0; nt < 8; nt++)
                #pragma unroll
                for (int j = 0; j < 4; j++) S[nt][j] = 0.f;

            #pragma unroll
            for (int ks = 0; ks < 4; ks++) {
                const int c16 = ks * 2;
                uint32_t bh[4][4];
                #pragma unroll
                for (int jn = 0; jn < 4; jn++) {
                    const int row = jn * 16 + kbrow;
                    const int cc  = c16 + kbcadd;
                    uint32_t ad = sKh + row * 128 + ((cc ^ (row & 7)) << 4);
                    LDSM_X4(bh[jn][0], bh[jn][1], bh[jn][2], bh[jn][3], ad);
                }
                #pragma unroll
                for (int nt = 0; nt < 8; nt++)
                    MMAH(S[nt], aq[ks],
                         bh[nt >> 1][(nt & 1) * 2],
                         bh[nt >> 1][(nt & 1) * 2 + 1]);
            }

            // ---- causal mask (diagonal tiles only) ----
            if (kt >= 2 * qt) {
                #pragma unroll
                for (int nt = 0; nt < 8; nt++) {
                    const int jg = kt * 64 + nt * 8 + tig * 2;
                    if (jg     > rg0)     S[nt][0] = -1e30f;
                    if (jg + 1 > rg0)     S[nt][1] = -1e30f;
                    if (jg     > rg0 + 8) S[nt][2] = -1e30f;
                    if (jg + 1 > rg0 + 8) S[nt][3] = -1e30f;
                }
            }

            // ---- online softmax ----
            float t0 = -1e30f, t1 = -1e30f;
            #pragma unroll
            for (int nt = 0; nt < 8; nt++) {
                t0 = fmaxf(t0, fmaxf(S[nt][0], S[nt][1]));
                t1 = fmaxf(t1, fmaxf(S[nt][2], S[nt][3]));
            }
            t0 = fmaxf(t0, __shfl_xor_sync(0xffffffffu, t0, 1));
            t0 = fmaxf(t0, __shfl_xor_sync(0xffffffffu, t0, 2));
            t1 = fmaxf(t1, __shfl_xor_sync(0xffffffffu, t1, 1));
            t1 = fmaxf(t1, __shfl_xor_sync(0xffffffffu, t1, 2));
            const float mn0 = fmaxf(m0, t0), mn1 = fmaxf(m1, t1);
            const float a0 = __expf(m0 - mn0), a1 = __expf(m1 - mn1);
            m0 = mn0; m1 = mn1;
            l0 *= a0;  l1 *= a1;
            #pragma unroll
            for (int d = 0; d < 8; d++) {
                O[d][0] *= a0; O[d][1] *= a0;
                O[d][2] *= a1; O[d][3] *= a1;
            }

            // ---- P = exp(S-m), single fp16 A-fragments ----
            uint32_t pf[4][4];
            #pragma unroll
            for (int nt = 0; nt < 8; nt++) {
                const float p0 = __expf(S[nt][0] - m0);
                const float p1 = __expf(S[nt][1] - m0);
                const float p2 = __expf(S[nt][2] - m1);
                const float p3 = __expf(S[nt][3] - m1);
                l0 += p0 + p1;
                l1 += p2 + p3;
                const int jb = nt >> 1, o = (nt & 1) * 2;
                pf[jb][o]     = pack_h2(__float2half(p0), __float2half(p1));
                pf[jb][o + 1] = pack_h2(__float2half(p2), __float2half(p3));
            }

            // ---- O += P @ V (single pass) ----
            #pragma unroll
            for (int jb = 0; jb < 4; jb++) {
                #pragma unroll
                for (int dp = 0; dp < 4; dp++) {
                    const int row = jb * 16 + vbrow;
                    const int cc  = dp * 2 + vbcadd;
                    uint32_t vv[4];
                    uint32_t ad = sVh + row * 128 + ((cc ^ (row & 7)) << 4);
                    LDSM_X4T(vv[0], vv[1], vv[2], vv[3], ad);
                    const int d0 = dp * 2;
                    MMAH(O[d0],     pf[jb], vv[0], vv[1]);
                    MMAH(O[d0 + 1], pf[jb], vv[2], vv[3]);
                }
            }
        }

        if (kt + 2 < ktmax)
            kv_load(sb, kh, vh, hb, kt + 2, tid);
        CP_COMMIT();
    }

    // ---- epilogue: normalize + write fp16 hi/lo arrays ----
    l0 += __shfl_xor_sync(0xffffffffu, l0, 1);
    l0 += __shfl_xor_sync(0xffffffffu, l0, 2);
    l1 += __shfl_xor_sync(0xffffffffu, l1, 1);
    l1 += __shfl_xor_sync(0xffffffffu, l1, 2);
    const float inv0 = 1.f / l0, inv1 = 1.f / l1;

    const size_t row0 = (size_t)(b * T_ + rg0) * C_;
    const size_t row1 = row0 + (size_t)8 * C_;
    #pragma unroll
    for (int d = 0; d < 8; d++) {
        const int c = h * 64 + d * 8 + tig * 2;
        float v0 = O[d][0] * inv0, v1 = O[d][1] * inv0;
        float v2 = O[d][2] * inv1, v3 = O[d][3] * inv1;
        __half h0 = __float2half(v0), h1 = __float2half(v1);
        __half h2 = __float2half(v2), h3 = __float2half(v3);
        __half e0 = __float2half(v0 - __half2float(h0));
        __half e1 = __float2half(v1 - __half2float(h1));
        __half e2 = __float2half(v2 - __half2float(h2));
        __half e3 = __float2half(v3 - __half2float(h3));
        *reinterpret_cast<uint32_t*>(yh + row0 + c) = pack_h2(h0, h1);
        *reinterpret_cast<uint32_t*>(yl + row0 + c) = pack_h2(e0, e1);
        *reinterpret_cast<uint32_t*>(yh + row1 + c) = pack_h2(h2, h3);
        *reinterpret_cast<uint32_t*>(yl + row1 + c) = pack_h2(e2, e3);
    }
}

// ---------------------------------------------------------------------------
extern "C" void kernel_launch(void* const* d_in, const int* in_sizes, int n_in,
                              void* d_out, int out_size)
{
    const float* x     = (const float*)d_in[0];
    const float* wkqv  = (const float*)d_in[1];
    const float* wproj = (const float*)d_in[2];
    const float* bproj = (const float*)d_in[3];
    float* out = (float*)d_out;

    __half *xh, *w1h, *yh, *yl, *w2h, *qh, *kh, *vh;
    cudaGetSymbolAddress((void**)&xh,  g_xh);
    cudaGetSymbolAddress((void**)&w1h, g_w1h);
    cudaGetSymbolAddress((void**)&yh,  g_yh);
    cudaGetSymbolAddress((void**)&yl,  g_yl);
    cudaGetSymbolAddress((void**)&w2h, g_w2h);
    cudaGetSymbolAddress((void**)&qh,  g_qh);
    cudaGetSymbolAddress((void**)&kh,  g_kh);
    cudaGetSymbolAddress((void**)&vh,  g_vh);

    cudaFuncSetAttribute((const void*)gemm_mma<1, false>,
                         cudaFuncAttributeMaxDynamicSharedMemorySize, SMEM_TOTAL);
    cudaFuncSetAttribute((const void*)gemm_mma<2, true>,
                         cudaFuncAttributeMaxDynamicSharedMemorySize, SMEM_TOTAL);
    cudaFuncSetAttribute((const void*)attn_mma,
                         cudaFuncAttributeMaxDynamicSharedMemorySize, ATT_SMEM);

    // Prep
    cvth<<<(BT_ * C_ / 4 + 255) / 256, 256>>>(x, xh, BT_ * C_ / 4);
    tconvh<<<dim3(C3_ / 32, C_ / 32), dim3(32, 8)>>>(wkqv, w1h, C_, C3_);
    tconvh<<<dim3(C_ / 32, C_ / 32), dim3(32, 8)>>>(wproj, w2h, C_, C_);

    // 1) QKV GEMM (single-pass fp16, 3-stage) with fused split epilogue
    {
        dim3 grid(C3_ / GBN, BT_ / GBM);   // (24, 32)
        gemm_mma<1, false><<<grid, 256, SMEM_TOTAL>>>(
            (const uint16_t*)xh, nullptr, (const uint16_t*)w1h,
            nullptr, nullptr, qh, kh, vh, BT_, C3_, C_);
    }

    // 2) MMA flash attention (single-pass fp16) -> yh/yl
    {
        dim3 grid(T_ / 128, H_, B_);       // (16, 16, 2)
        attn_mma<<<grid, 256, ATT_SMEM>>>(qh, kh, vh, yh, yl);
    }

    // 3) proj GEMM (shared-B hi/lo fp16, 2-stage) + bias -> out
    {
        dim3 grid(C_ / GBN, BT_ / GBM);    // (8, 32)
        gemm_mma<2, true><<<grid, 256, SMEM_TOTAL>>>(
            (const uint16_t*)yh, (const uint16_t*)yl, (const uint16_t*)w2h,
            bproj, out, nullptr, nullptr, nullptr, BT_, C_, C_);
    }
}

// round 12
// speedup vs baseline: 9.7842x; 1.0960x over previous
#include <cuda_runtime.h>
#include <cuda_bf16.h>
#include <cuda_fp16.h>
#include <cstdint>

// Problem constants (fixed by the reference)
#define B_   2
#define T_   2048
#define C_   1024
#define H_   16
#define HS_  64
#define C3_  3072
#define BT_  (B_*T_)          // 4096 rows

// ---------------------------------------------------------------------------
// Scratch (device globals — no runtime allocation allowed)
// ---------------------------------------------------------------------------
__device__ __half g_xh [(size_t)BT_ * C_];     // x fp16
__device__ __half g_w1h[(size_t)C3_ * C_];     // W_kqv^T [N,K] fp16
__device__ __half g_yh [(size_t)BT_ * C_];     // attn out fp16
__device__ __half g_w2h[(size_t)C_  * C_];     // W_proj^T [N,K] fp16

// per-head attention operands [B, H, T, 64] fp16
#define NHE ((size_t)B_ * H_ * T_ * 64)
__device__ __half g_qh[NHE];                   // q fp16, pre-scaled 1/8
__device__ __half g_kh[NHE], g_vh[NHE];        // k, v fp16

// ---------------------------------------------------------------------------
// PTX helpers (no 'a'-gated instructions)
// ---------------------------------------------------------------------------
__device__ __forceinline__ uint32_t smem_u32(const void* p) {
    uint32_t a;
    asm("{ .reg .u64 t; cvta.to.shared.u64 t, %1; cvt.u32.u64 %0, t; }"
        : "=r"(a) : "l"(p));
    return a;
}

#define CP_ASYNC16(dst, src) \
    asm volatile("cp.async.cg.shared.global [%0], [%1], 16;" \
                 :: "r"(dst), "l"(src) : "memory")
#define CP_COMMIT() asm volatile("cp.async.commit_group;" ::: "memory")
#define CP_WAIT1()  asm volatile("cp.async.wait_group 1;" ::: "memory")
#define CP_WAIT2()  asm volatile("cp.async.wait_group 2;" ::: "memory")

#define LDSM_X4(r0, r1, r2, r3, addr) \
    asm volatile("ldmatrix.sync.aligned.m8n8.x4.shared.b16 {%0,%1,%2,%3}, [%4];" \
                 : "=r"(r0), "=r"(r1), "=r"(r2), "=r"(r3) : "r"(addr))
#define LDSM_X4T(r0, r1, r2, r3, addr) \
    asm volatile("ldmatrix.sync.aligned.m8n8.x4.trans.shared.b16 {%0,%1,%2,%3}, [%4];" \
                 : "=r"(r0), "=r"(r1), "=r"(r2), "=r"(r3) : "r"(addr))

#define MMAH(c, a, b0, b1) \
    asm volatile("mma.sync.aligned.m16n8k16.row.col.f32.f16.f16.f32 " \
                 "{%0,%1,%2,%3}, {%4,%5,%6,%7}, {%8,%9}, {%0,%1,%2,%3};" \
                 : "+f"((c)[0]), "+f"((c)[1]), "+f"((c)[2]), "+f"((c)[3]) \
                 : "r"((a)[0]), "r"((a)[1]), "r"((a)[2]), "r"((a)[3]), \
                   "r"(b0), "r"(b1))

__device__ __forceinline__ uint32_t pack_h2(__half a, __half b) {
    __half2 t = __halves2half2(a, b);
    return *reinterpret_cast<uint32_t*>(&t);
}

// ---------------------------------------------------------------------------
// Prep 1: x fp32 -> fp16
// ---------------------------------------------------------------------------
__global__ __launch_bounds__(256)
void cvth(const float* __restrict__ in, __half* __restrict__ out, int total4)
{
    int i = blockIdx.x * blockDim.x + threadIdx.x;
    if (i >= total4) return;
    float4 v = reinterpret_cast<const float4*>(in)[i];
    reinterpret_cast<uint2*>(out)[i] =
        make_uint2(pack_h2(__float2half(v.x), __float2half(v.y)),
                   pack_h2(__float2half(v.z), __float2half(v.w)));
}

// ---------------------------------------------------------------------------
// Prep 2: W fp32 [K,N] -> W^T [N,K] fp16
// ---------------------------------------------------------------------------
__global__ __launch_bounds__(256)
void tconvh(const float* __restrict__ W, __half* __restrict__ out,
            int K, int N)
{
    __shared__ float t[32][33];
    const int n0 = blockIdx.x * 32, k0 = blockIdx.y * 32;
    const int tx = threadIdx.x, ty = threadIdx.y;
    #pragma unroll
    for (int r = 0; r < 4; r++)
        t[ty + 8 * r][tx] = W[(size_t)(k0 + ty + 8 * r) * N + n0 + tx];
    __syncthreads();
    #pragma unroll
    for (int r = 0; r < 4; r++) {
        const int n = n0 + ty + 8 * r, k = k0 + tx;
        out[(size_t)n * K + k] = __float2half(t[tx][ty + 8 * r]);
    }
}

// ---------------------------------------------------------------------------
// fp16 GEMM: C = A @ B^T. 3-stage cp.async pipeline, 1 sync/chunk.
// EPI 1: QKV per-head split epilogue. EPI 2: bias + fp32 store.
// ---------------------------------------------------------------------------
#define GBM 128
#define GBN 128
#define GBK 64
#define STG_S 32768                   // A 16K + B 16K
#define SMEM_TOTAL (3 * STG_S)        // 96KB, 2 CTA/SM

__device__ __forceinline__ void load_tile_async(
    uint32_t s_base, const uint16_t* __restrict__ g,
    int ld, int row0, int k0, int tid)
{
    #pragma unroll
    for (int it = 0; it < 4; it++) {
        int i = tid + it * 256;
        int row = i >> 3, c = i & 7;
        uint32_t dst = s_base + row * 128 + (((c ^ (row & 7))) << 4);
        const uint16_t* src = g + (size_t)(row0 + row) * ld + k0 + c * 8;
        CP_ASYNC16(dst, src);
    }
}

template<int EPI>
__global__ __launch_bounds__(256, 2)
void gemm_mma(const uint16_t* __restrict__ A,
              const uint16_t* __restrict__ Bt,
              const float* __restrict__ bias, float* __restrict__ C,
              __half* __restrict__ qh, __half* __restrict__ kh,
              __half* __restrict__ vh,
              int M, int N, int K)
{
    extern __shared__ char sm[];
    const uint32_t sbase = smem_u32(sm);
    const int tid = threadIdx.x;
    const int wid = tid >> 5, lane = tid & 31;
    const int wm = wid >> 1, wn = wid & 1;
    const int m0 = blockIdx.y * GBM, n0 = blockIdx.x * GBN;

    float acc[2][8][4];
    #pragma unroll
    for (int mt = 0; mt < 2; mt++)
        #pragma unroll
        for (int nt = 0; nt < 8; nt++)
            #pragma unroll
            for (int j = 0; j < 4; j++) acc[mt][nt][j] = 0.f;

    const int nchunks = K / GBK;    // 16

    // Prologue: stages 0,1
    #pragma unroll
    for (int s = 0; s < 2; s++) {
        const uint32_t st = sbase + s * STG_S;
        load_tile_async(st,         A,  K, m0, s * GBK, tid);
        load_tile_async(st + 16384, Bt, K, n0, s * GBK, tid);
        CP_COMMIT();
    }

    const int a_row  = wm * 32 + (lane & 15);
    const int a_cadd = (lane >> 4);
    const int b_row  = wn * 64 + (lane & 7) + ((lane >> 4) << 3);
    const int b_cadd = (lane >> 3) & 1;

    for (int ch = 0; ch < nchunks; ch++) {
        CP_WAIT1();
        __syncthreads();

        const uint32_t st = sbase + (ch % 3) * STG_S;
        const uint32_t sA = st, sB = st + 16384;

        #pragma unroll
        for (int ks = 0; ks < 4; ks++) {
            const int c16 = ks * 2;
            uint32_t a[2][4];
            #pragma unroll
            for (int mt = 0; mt < 2; mt++) {
                const int row = a_row + mt * 16;
                const int cc  = c16 + a_cadd;
                const uint32_t ad = sA + row * 128 + ((cc ^ (row & 7)) << 4);
                LDSM_X4(a[mt][0], a[mt][1], a[mt][2], a[mt][3], ad);
            }
            uint32_t b[4][4];
            #pragma unroll
            for (int ntp = 0; ntp < 4; ntp++) {
                const int row = b_row + ntp * 16;
                const int cc  = c16 + b_cadd;
                const uint32_t ad = sB + row * 128 + ((cc ^ (row & 7)) << 4);
                LDSM_X4(b[ntp][0], b[ntp][1], b[ntp][2], b[ntp][3], ad);
            }
            #pragma unroll
            for (int mt = 0; mt < 2; mt++)
                #pragma unroll
                for (int nt = 0; nt < 8; nt++)
                    MMAH(acc[mt][nt], a[mt],
                         b[nt >> 1][(nt & 1) * 2],
                         b[nt >> 1][(nt & 1) * 2 + 1]);
        }

        if (ch + 2 < nchunks) {
            const uint32_t nb = sbase + ((ch + 2) % 3) * STG_S;
            load_tile_async(nb,         A,  K, m0, (ch + 2) * GBK, tid);
            load_tile_async(nb + 16384, Bt, K, n0, (ch + 2) * GBK, tid);
        }
        CP_COMMIT();
    }

    const int gid = lane >> 2, tig = lane & 3;

    if (EPI == 2) {
        #pragma unroll
        for (int mt = 0; mt < 2; mt++) {
            #pragma unroll
            for (int nt = 0; nt < 8; nt++) {
                const int col = n0 + wn * 64 + nt * 8 + tig * 2;
                const float bx = bias[col], by = bias[col + 1];
                const int r0 = m0 + wm * 32 + mt * 16 + gid;
                float2 v0 = { acc[mt][nt][0] + bx, acc[mt][nt][1] + by };
                float2 v1 = { acc[mt][nt][2] + bx, acc[mt][nt][3] + by };
                *reinterpret_cast<float2*>(&C[(size_t)r0 * N + col])       = v0;
                *reinterpret_cast<float2*>(&C[(size_t)(r0 + 8) * N + col]) = v1;
            }
        }
    } else {  // EPI == 1: QKV per-head split epilogue (single fp16)
        #pragma unroll
        for (int mt = 0; mt < 2; mt++) {
            #pragma unroll
            for (int nt = 0; nt < 8; nt++) {
                const int col   = n0 + wn * 64 + nt * 8 + tig * 2;
                const int which = col >> 10;            // 0=q 1=k 2=v
                const int hh    = (col >> 6) & 15;
                const int d     = col & 63;
                const float sc  = (which == 0) ? 0.125f : 1.0f;
                __half* p = (which == 0) ? qh : (which == 1) ? kh : vh;
                #pragma unroll
                for (int rr = 0; rr < 2; rr++) {
                    const int r  = m0 + wm * 32 + mt * 16 + gid + rr * 8;
                    const int bb = r >> 11, t = r & 2047;
                    const size_t off = (((size_t)(bb * 16 + hh)) * 2048 + t) * 64 + d;
                    *reinterpret_cast<uint32_t*>(p + off) =
                        pack_h2(__float2half(acc[mt][nt][rr * 2 + 0] * sc),
                                __float2half(acc[mt][nt][rr * 2 + 1] * sc));
                }
            }
        }
    }
}

// ---------------------------------------------------------------------------
// MMA flash attention, single-pass fp16, 3-stage cp.async K/V pipeline.
// occ 2 (128KB smem total, regs capped 128) for latency hiding.
// smem: Q 16K | 3 x (Kh 8K, Vh 8K) = 64KB
// ---------------------------------------------------------------------------
#define ATT_SMEM (16384 + 3 * 16384)

__device__ __forceinline__ void kv_load(uint32_t sb,
    const __half* __restrict__ kh, const __half* __restrict__ vh,
    size_t hb, int kt, int tid)
{
    const uint32_t stage = sb + 16384 + (kt % 3) * 16384;
    #pragma unroll
    for (int it = 0; it < 4; it++) {
        int i = tid + (it & 1) * 256;            // 0..511
        int row = i >> 3, c = i & 7;
        const __half* g = (it < 2) ? kh : vh;
        uint32_t dst = stage + ((it < 2) ? 0 : 8192)
                     + row * 128 + ((c ^ (row & 7)) << 4);
        CP_ASYNC16(dst, g + hb + (size_t)(kt * 64 + row) * 64 + c * 8);
    }
}

__global__ __launch_bounds__(256, 2)
void attn_mma(const __half* __restrict__ qh,
              const __half* __restrict__ kh, const __half* __restrict__ vh,
              __half* __restrict__ yh)
{
    extern __shared__ char sm[];
    const uint32_t sb = smem_u32(sm);
    const uint32_t sQ = sb;

    const int tid = threadIdx.x, wid = tid >> 5, lane = tid & 31;
    const int qt = gridDim.x - 1 - blockIdx.x;    // heavy q-tiles first
    const int h = blockIdx.y, b = blockIdx.z;
    const size_t hb = ((size_t)(b * H_ + h)) * T_ * 64;
    const int ktmax = 2 * (qt + 1);               // >= 2

    // Stage Q tile (128 rows x 8 x 16B)
    #pragma unroll
    for (int it = 0; it < 4; it++) {
        int i = tid + it * 256;
        int row = i >> 3, c = i & 7;
        uint32_t dst = sQ + row * 128 + ((c ^ (row & 7)) << 4);
        CP_ASYNC16(dst, qh + hb + (size_t)(qt * 128 + row) * 64 + c * 8);
    }
    CP_COMMIT();                                   // g0: Q
    kv_load(sb, kh, vh, hb, 0, tid);
    CP_COMMIT();                                   // g1: KV0
    kv_load(sb, kh, vh, hb, 1, tid);
    CP_COMMIT();                                   // g2: KV1

    const int gid = lane >> 2, tig = lane & 3;
    const int arow   = wid * 16 + (lane & 15);
    const int acadd  = lane >> 4;
    const int kbrow  = (lane & 7) + ((lane >> 4) << 3);
    const int kbcadd = (lane >> 3) & 1;
    const int vbrow  = (lane & 7) + (((lane >> 3) & 1) << 3);
    const int vbcadd = lane >> 4;

    // Q fragments (loop-invariant), hoisted after g0 lands
    CP_WAIT2();
    __syncthreads();
    uint32_t aq[4][4];
    #pragma unroll
    for (int ks = 0; ks < 4; ks++) {
        const int c16 = ks * 2 + acadd;
        uint32_t ad = sQ + arow * 128 + ((c16 ^ (arow & 7)) << 4);
        LDSM_X4(aq[ks][0], aq[ks][1], aq[ks][2], aq[ks][3], ad);
    }

    float m0 = -1e30f, m1 = -1e30f, l0 = 0.f, l1 = 0.f;
    float O[8][4];
    #pragma unroll
    for (int d = 0; d < 8; d++)
        #pragma unroll
        for (int j = 0; j < 4; j++) O[d][j] = 0.f;

    const int rg0 = qt * 128 + wid * 16 + gid;

    for (int kt = 0; kt < ktmax; kt++) {
        CP_WAIT1();
        __syncthreads();

        const uint32_t stage = sb + 16384 + (kt % 3) * 16384;
        const uint32_t sKh = stage, sVh = stage + 8192;

        const bool active = (kt * 64) <= (qt * 128 + wid * 16 + 15);
        if (active) {
            // ---- S = QK^T (single pass) ----
            float S[8][4];
            #pragma unroll
            for (int nt = 0; nt < 8; nt++)
                #pragma unroll
                for (int j = 0; j < 4; j++) S[nt][j] = 0.f;

            #pragma unroll
            for (int ks = 0; ks < 4; ks++) {
                const int c16 = ks * 2;
                uint32_t bh[4][4];
                #pragma unroll
                for (int jn = 0; jn < 4; jn++) {
                    const int row = jn * 16 + kbrow;
                    const int cc  = c16 + kbcadd;
                    uint32_t ad = sKh + row * 128 + ((cc ^ (row & 7)) << 4);
                    LDSM_X4(bh[jn][0], bh[jn][1], bh[jn][2], bh[jn][3], ad);
                }
                #pragma unroll
                for (int nt = 0; nt < 8; nt++)
                    MMAH(S[nt], aq[ks],
                         bh[nt >> 1][(nt & 1) * 2],
                         bh[nt >> 1][(nt & 1) * 2 + 1]);
            }

            // ---- causal mask (diagonal tiles only) ----
            if (kt >= 2 * qt) {
                #pragma unroll
                for (int nt = 0; nt < 8; nt++) {
                    const int jg = kt * 64 + nt * 8 + tig * 2;
                    if (jg     > rg0)     S[nt][0] = -1e30f;
                    if (jg + 1 > rg0)     S[nt][1] = -1e30f;
                    if (jg     > rg0 + 8) S[nt][2] = -1e30f;
                    if (jg + 1 > rg0 + 8) S[nt][3] = -1e30f;
                }
            }

            // ---- online softmax ----
            float t0 = -1e30f, t1 = -1e30f;
            #pragma unroll
            for (int nt = 0; nt < 8; nt++) {
                t0 = fmaxf(t0, fmaxf(S[nt][0], S[nt][1]));
                t1 = fmaxf(t1, fmaxf(S[nt][2], S[nt][3]));
            }
            t0 = fmaxf(t0, __shfl_xor_sync(0xffffffffu, t0, 1));
            t0 = fmaxf(t0, __shfl_xor_sync(0xffffffffu, t0, 2));
            t1 = fmaxf(t1, __shfl_xor_sync(0xffffffffu, t1, 1));
            t1 = fmaxf(t1, __shfl_xor_sync(0xffffffffu, t1, 2));
            const float mn0 = fmaxf(m0, t0), mn1 = fmaxf(m1, t1);
            const float a0 = __expf(m0 - mn0), a1 = __expf(m1 - mn1);
            m0 = mn0; m1 = mn1;
            l0 *= a0;  l1 *= a1;
            #pragma unroll
            for (int d = 0; d < 8; d++) {
                O[d][0] *= a0; O[d][1] *= a0;
                O[d][2] *= a1; O[d][3] *= a1;
            }

            // ---- P = exp(S-m), single fp16 A-fragments ----
            uint32_t pf[4][4];
            #pragma unroll
            for (int nt = 0; nt < 8; nt++) {
                const float p0 = __expf(S[nt][0] - m0);
                const float p1 = __expf(S[nt][1] - m0);
                const float p2 = __expf(S[nt][2] - m1);
                const float p3 = __expf(S[nt][3] - m1);
                l0 += p0 + p1;
                l1 += p2 + p3;
                const int jb = nt >> 1, o = (nt & 1) * 2;
                pf[jb][o]     = pack_h2(__float2half(p0), __float2half(p1));
                pf[jb][o + 1] = pack_h2(__float2half(p2), __float2half(p3));
            }

            // ---- O += P @ V (single pass) ----
            #pragma unroll
            for (int jb = 0; jb < 4; jb++) {
                #pragma unroll
                for (int dp = 0; dp < 4; dp++) {
                    const int row = jb * 16 + vbrow;
                    const int cc  = dp * 2 + vbcadd;
                    uint32_t vv[4];
                    uint32_t ad = sVh + row * 128 + ((cc ^ (row & 7)) << 4);
                    LDSM_X4T(vv[0], vv[1], vv[2], vv[3], ad);
                    const int d0 = dp * 2;
                    MMAH(O[d0],     pf[jb], vv[0], vv[1]);
                    MMAH(O[d0 + 1], pf[jb], vv[2], vv[3]);
                }
            }
        }

        if (kt + 2 < ktmax)
            kv_load(sb, kh, vh, hb, kt + 2, tid);
        CP_COMMIT();
    }

    // ---- epilogue: normalize + write fp16 ----
    l0 += __shfl_xor_sync(0xffffffffu, l0, 1);
    l0 += __shfl_xor_sync(0xffffffffu, l0, 2);
    l1 += __shfl_xor_sync(0xffffffffu, l1, 1);
    l1 += __shfl_xor_sync(0xffffffffu, l1, 2);
    const float inv0 = 1.f / l0, inv1 = 1.f / l1;

    const size_t row0 = (size_t)(b * T_ + rg0) * C_;
    const size_t row1 = row0 + (size_t)8 * C_;
    #pragma unroll
    for (int d = 0; d < 8; d++) {
        const int c = h * 64 + d * 8 + tig * 2;
        *reinterpret_cast<uint32_t*>(yh + row0 + c) =
            pack_h2(__float2half(O[d][0] * inv0), __float2half(O[d][1] * inv0));
        *reinterpret_cast<uint32_t*>(yh + row1 + c) =
            pack_h2(__float2half(O[d][2] * inv1), __float2half(O[d][3] * inv1));
    }
}

// ---------------------------------------------------------------------------
extern "C" void kernel_launch(void* const* d_in, const int* in_sizes, int n_in,
                              void* d_out, int out_size)
{
    const float* x     = (const float*)d_in[0];
    const float* wkqv  = (const float*)d_in[1];
    const float* wproj = (const float*)d_in[2];
    const float* bproj = (const float*)d_in[3];
    float* out = (float*)d_out;

    __half *xh, *w1h, *yh, *w2h, *qh, *kh, *vh;
    cudaGetSymbolAddress((void**)&xh,  g_xh);
    cudaGetSymbolAddress((void**)&w1h, g_w1h);
    cudaGetSymbolAddress((void**)&yh,  g_yh);
    cudaGetSymbolAddress((void**)&w2h, g_w2h);
    cudaGetSymbolAddress((void**)&qh,  g_qh);
    cudaGetSymbolAddress((void**)&kh,  g_kh);
    cudaGetSymbolAddress((void**)&vh,  g_vh);

    cudaFuncSetAttribute((const void*)gemm_mma<1>,
                         cudaFuncAttributeMaxDynamicSharedMemorySize, SMEM_TOTAL);
    cudaFuncSetAttribute((const void*)gemm_mma<2>,
                         cudaFuncAttributeMaxDynamicSharedMemorySize, SMEM_TOTAL);
    cudaFuncSetAttribute((const void*)attn_mma,
                         cudaFuncAttributeMaxDynamicSharedMemorySize, ATT_SMEM);

    // Prep
    cvth<<<(BT_ * C_ / 4 + 255) / 256, 256>>>(x, xh, BT_ * C_ / 4);
    tconvh<<<dim3(C3_ / 32, C_ / 32), dim3(32, 8)>>>(wkqv, w1h, C_, C3_);
    tconvh<<<dim3(C_ / 32, C_ / 32), dim3(32, 8)>>>(wproj, w2h, C_, C_);

    // 1) QKV GEMM (single-pass fp16, 3-stage) with fused split epilogue
    {
        dim3 grid(C3_ / GBN, BT_ / GBM);   // (24, 32)
        gemm_mma<1><<<grid, 256, SMEM_TOTAL>>>(
            (const uint16_t*)xh, (const uint16_t*)w1h,
            nullptr, nullptr, qh, kh, vh, BT_, C3_, C_);
    }

    // 2) MMA flash attention (single-pass fp16, occ 2) -> yh
    {
        dim3 grid(T_ / 128, H_, B_);       // (16, 16, 2)
        attn_mma<<<grid, 256, ATT_SMEM>>>(qh, kh, vh, yh);
    }

    // 3) proj GEMM (single-pass fp16, 3-stage) + bias -> out
    {
        dim3 grid(C_ / GBN, BT_ / GBM);    // (8, 32)
        gemm_mma<2><<<grid, 256, SMEM_TOTAL>>>(
            (const uint16_t*)yh, (const uint16_t*)w2h,
            bproj, out, nullptr, nullptr, nullptr, BT_, C_, C_);
    }
}

// round 13
// speedup vs baseline: 10.1886x; 1.0413x over previous
#include <cuda_runtime.h>
#include <cuda_bf16.h>
#include <cuda_fp16.h>
#include <cstdint>

// Problem constants (fixed by the reference)
#define B_   2
#define T_   2048
#define C_   1024
#define H_   16
#define HS_  64
#define C3_  3072
#define BT_  (B_*T_)          // 4096 rows

// ---------------------------------------------------------------------------
// Scratch (device globals — no runtime allocation allowed)
// ---------------------------------------------------------------------------
__device__ __half g_xh [(size_t)BT_ * C_];     // x fp16
__device__ __half g_w1h[(size_t)C3_ * C_];     // W_kqv^T [N,K] fp16
__device__ __half g_yh [(size_t)BT_ * C_];     // attn out fp16
__device__ __half g_w2h[(size_t)C_  * C_];     // W_proj^T [N,K] fp16

// per-head attention operands [B, H, T, 64] fp16
#define NHE ((size_t)B_ * H_ * T_ * 64)
__device__ __half g_qh[NHE];                   // q fp16, pre-scaled 1/8
__device__ __half g_kh[NHE], g_vh[NHE];        // k, v fp16

// ---------------------------------------------------------------------------
// PTX helpers (no 'a'-gated instructions)
// ---------------------------------------------------------------------------
__device__ __forceinline__ uint32_t smem_u32(const void* p) {
    uint32_t a;
    asm("{ .reg .u64 t; cvta.to.shared.u64 t, %1; cvt.u32.u64 %0, t; }"
        : "=r"(a) : "l"(p));
    return a;
}

#define CP_ASYNC16(dst, src) \
    asm volatile("cp.async.cg.shared.global [%0], [%1], 16;" \
                 :: "r"(dst), "l"(src) : "memory")
#define CP_COMMIT() asm volatile("cp.async.commit_group;" ::: "memory")
#define CP_WAIT1()  asm volatile("cp.async.wait_group 1;" ::: "memory")
#define CP_WAIT2()  asm volatile("cp.async.wait_group 2;" ::: "memory")

#define LDSM_X4(r0, r1, r2, r3, addr) \
    asm volatile("ldmatrix.sync.aligned.m8n8.x4.shared.b16 {%0,%1,%2,%3}, [%4];" \
                 : "=r"(r0), "=r"(r1), "=r"(r2), "=r"(r3) : "r"(addr))
#define LDSM_X4T(r0, r1, r2, r3, addr) \
    asm volatile("ldmatrix.sync.aligned.m8n8.x4.trans.shared.b16 {%0,%1,%2,%3}, [%4];" \
                 : "=r"(r0), "=r"(r1), "=r"(r2), "=r"(r3) : "r"(addr))

#define MMAH(c, a, b0, b1) \
    asm volatile("mma.sync.aligned.m16n8k16.row.col.f32.f16.f16.f32 " \
                 "{%0,%1,%2,%3}, {%4,%5,%6,%7}, {%8,%9}, {%0,%1,%2,%3};" \
                 : "+f"((c)[0]), "+f"((c)[1]), "+f"((c)[2]), "+f"((c)[3]) \
                 : "r"((a)[0]), "r"((a)[1]), "r"((a)[2]), "r"((a)[3]), \
                   "r"(b0), "r"(b1))

__device__ __forceinline__ uint32_t pack_h2(__half a, __half b) {
    __half2 t = __halves2half2(a, b);
    return *reinterpret_cast<uint32_t*>(&t);
}

// ---------------------------------------------------------------------------
// Prep 1: x fp32 -> fp16
// ---------------------------------------------------------------------------
__global__ __launch_bounds__(256)
void cvth(const float* __restrict__ in, __half* __restrict__ out, int total4)
{
    int i = blockIdx.x * blockDim.x + threadIdx.x;
    if (i >= total4) return;
    float4 v = reinterpret_cast<const float4*>(in)[i];
    reinterpret_cast<uint2*>(out)[i] =
        make_uint2(pack_h2(__float2half(v.x), __float2half(v.y)),
                   pack_h2(__float2half(v.z), __float2half(v.w)));
}

// ---------------------------------------------------------------------------
// Prep 2 (merged): both weight transposes in one launch.
// bx < 96: W_kqv [1024,3072] -> g_w1h [3072,1024]
// bx >= 96: W_proj [1024,1024] -> g_w2h [1024,1024]
// ---------------------------------------------------------------------------
__global__ __launch_bounds__(256)
void tconvh2(const float* __restrict__ W1, __half* __restrict__ O1,
             const float* __restrict__ W2, __half* __restrict__ O2)
{
    __shared__ float t[32][33];
    const bool second = blockIdx.x >= 96;
    const float* W  = second ? W2 : W1;
    __half* out     = second ? O2 : O1;
    const int N     = second ? C_ : C3_;
    const int K     = C_;
    const int n0 = (second ? (blockIdx.x - 96) : blockIdx.x) * 32;
    const int k0 = blockIdx.y * 32;
    const int tx = threadIdx.x, ty = threadIdx.y;
    #pragma unroll
    for (int r = 0; r < 4; r++)
        t[ty + 8 * r][tx] = W[(size_t)(k0 + ty + 8 * r) * N + n0 + tx];
    __syncthreads();
    #pragma unroll
    for (int r = 0; r < 4; r++) {
        const int n = n0 + ty + 8 * r, k = k0 + tx;
        out[(size_t)n * K + k] = __float2half(t[tx][ty + 8 * r]);
    }
}

// ---------------------------------------------------------------------------
// fp16 GEMM: C = A @ B^T. CTA tile 256x128, warp tile 64x64 (ratio-4
// MMA:ldsm), 8 warps (4x2), occ 1, 3-stage cp.async pipeline.
// EPI 1: QKV per-head split epilogue. EPI 2: bias + fp32 store.
// ---------------------------------------------------------------------------
#define GBM 256
#define GBN 128
#define GBK 64
#define STG_S 49152                   // A 32K + B 16K
#define SMEM_TOTAL (3 * STG_S)        // 144KB, 1 CTA/SM

template<int ROWS>
__device__ __forceinline__ void load_tile_async(
    uint32_t s_base, const uint16_t* __restrict__ g,
    int ld, int row0, int k0, int tid)
{
    #pragma unroll
    for (int it = 0; it < ROWS / 32; it++) {
        int i = tid + it * 256;
        int row = i >> 3, c = i & 7;
        uint32_t dst = s_base + row * 128 + (((c ^ (row & 7))) << 4);
        const uint16_t* src = g + (size_t)(row0 + row) * ld + k0 + c * 8;
        CP_ASYNC16(dst, src);
    }
}

template<int EPI>
__global__ __launch_bounds__(256, 1)
void gemm_mma(const uint16_t* __restrict__ A,
              const uint16_t* __restrict__ Bt,
              const float* __restrict__ bias, float* __restrict__ C,
              __half* __restrict__ qh, __half* __restrict__ kh,
              __half* __restrict__ vh,
              int M, int N, int K)
{
    extern __shared__ char sm[];
    const uint32_t sbase = smem_u32(sm);
    const int tid = threadIdx.x;
    const int wid = tid >> 5, lane = tid & 31;
    const int wm = wid >> 1, wn = wid & 1;        // 4 x 2 warp grid
    const int m0 = blockIdx.y * GBM, n0 = blockIdx.x * GBN;

    float acc[4][8][4];                            // 64x64 warp tile
    #pragma unroll
    for (int mt = 0; mt < 4; mt++)
        #pragma unroll
        for (int nt = 0; nt < 8; nt++)
            #pragma unroll
            for (int j = 0; j < 4; j++) acc[mt][nt][j] = 0.f;

    const int nchunks = K / GBK;    // 16

    // Prologue: stages 0,1
    #pragma unroll
    for (int s = 0; s < 2; s++) {
        const uint32_t st = sbase + s * STG_S;
        load_tile_async<GBM>(st,         A,  K, m0, s * GBK, tid);
        load_tile_async<GBN>(st + 32768, Bt, K, n0, s * GBK, tid);
        CP_COMMIT();
    }

    const int a_row  = wm * 64 + (lane & 15);
    const int a_cadd = (lane >> 4);
    const int b_row  = wn * 64 + (lane & 7) + ((lane >> 4) << 3);
    const int b_cadd = (lane >> 3) & 1;

    for (int ch = 0; ch < nchunks; ch++) {
        CP_WAIT1();
        __syncthreads();

        const uint32_t st = sbase + (ch % 3) * STG_S;
        const uint32_t sA = st, sB = st + 32768;

        #pragma unroll
        for (int ks = 0; ks < 4; ks++) {
            const int c16 = ks * 2;
            uint32_t a[4][4];
            #pragma unroll
            for (int mt = 0; mt < 4; mt++) {
                const int row = a_row + mt * 16;
                const int cc  = c16 + a_cadd;
                const uint32_t ad = sA + row * 128 + ((cc ^ (row & 7)) << 4);
                LDSM_X4(a[mt][0], a[mt][1], a[mt][2], a[mt][3], ad);
            }
            uint32_t b[4][4];
            #pragma unroll
            for (int ntp = 0; ntp < 4; ntp++) {
                const int row = b_row + ntp * 16;
                const int cc  = c16 + b_cadd;
                const uint32_t ad = sB + row * 128 + ((cc ^ (row & 7)) << 4);
                LDSM_X4(b[ntp][0], b[ntp][1], b[ntp][2], b[ntp][3], ad);
            }
            #pragma unroll
            for (int mt = 0; mt < 4; mt++)
                #pragma unroll
                for (int nt = 0; nt < 8; nt++)
                    MMAH(acc[mt][nt], a[mt],
                         b[nt >> 1][(nt & 1) * 2],
                         b[nt >> 1][(nt & 1) * 2 + 1]);
        }

        if (ch + 2 < nchunks) {
            const uint32_t nb = sbase + ((ch + 2) % 3) * STG_S;
            load_tile_async<GBM>(nb,         A,  K, m0, (ch + 2) * GBK, tid);
            load_tile_async<GBN>(nb + 32768, Bt, K, n0, (ch + 2) * GBK, tid);
        }
        CP_COMMIT();
    }

    const int gid = lane >> 2, tig = lane & 3;

    if (EPI == 2) {
        #pragma unroll
        for (int mt = 0; mt < 4; mt++) {
            #pragma unroll
            for (int nt = 0; nt < 8; nt++) {
                const int col = n0 + wn * 64 + nt * 8 + tig * 2;
                const float bx = bias[col], by = bias[col + 1];
                const int r0 = m0 + wm * 64 + mt * 16 + gid;
                float2 v0 = { acc[mt][nt][0] + bx, acc[mt][nt][1] + by };
                float2 v1 = { acc[mt][nt][2] + bx, acc[mt][nt][3] + by };
                *reinterpret_cast<float2*>(&C[(size_t)r0 * N + col])       = v0;
                *reinterpret_cast<float2*>(&C[(size_t)(r0 + 8) * N + col]) = v1;
            }
        }
    } else {  // EPI == 1: QKV per-head split epilogue (single fp16)
        #pragma unroll
        for (int mt = 0; mt < 4; mt++) {
            #pragma unroll
            for (int nt = 0; nt < 8; nt++) {
                const int col   = n0 + wn * 64 + nt * 8 + tig * 2;
                const int which = col >> 10;            // 0=q 1=k 2=v
                const int hh    = (col >> 6) & 15;
                const int d     = col & 63;
                const float sc  = (which == 0) ? 0.125f : 1.0f;
                __half* p = (which == 0) ? qh : (which == 1) ? kh : vh;
                #pragma unroll
                for (int rr = 0; rr < 2; rr++) {
                    const int r  = m0 + wm * 64 + mt * 16 + gid + rr * 8;
                    const int bb = r >> 11, t = r & 2047;
                    const size_t off = (((size_t)(bb * 16 + hh)) * 2048 + t) * 64 + d;
                    *reinterpret_cast<uint32_t*>(p + off) =
                        pack_h2(__float2half(acc[mt][nt][rr * 2 + 0] * sc),
                                __float2half(acc[mt][nt][rr * 2 + 1] * sc));
                }
            }
        }
    }
}

// ---------------------------------------------------------------------------
// MMA flash attention, single-pass fp16, 3-stage cp.async K/V pipeline.
// occ 2 (128KB smem total, regs capped 128).
// smem: Q 16K | 3 x (Kh 8K, Vh 8K) = 64KB
// ---------------------------------------------------------------------------
#define ATT_SMEM (16384 + 3 * 16384)

__device__ __forceinline__ void kv_load(uint32_t sb,
    const __half* __restrict__ kh, const __half* __restrict__ vh,
    size_t hb, int kt, int tid)
{
    const uint32_t stage = sb + 16384 + (kt % 3) * 16384;
    #pragma unroll
    for (int it = 0; it < 4; it++) {
        int i = tid + (it & 1) * 256;            // 0..511
        int row = i >> 3, c = i & 7;
        const __half* g = (it < 2) ? kh : vh;
        uint32_t dst = stage + ((it < 2) ? 0 : 8192)
                     + row * 128 + ((c ^ (row & 7)) << 4);
        CP_ASYNC16(dst, g + hb + (size_t)(kt * 64 + row) * 64 + c * 8);
    }
}

__global__ __launch_bounds__(256, 2)
void attn_mma(const __half* __restrict__ qh,
              const __half* __restrict__ kh, const __half* __restrict__ vh,
              __half* __restrict__ yh)
{
    extern __shared__ char sm[];
    const uint32_t sb = smem_u32(sm);
    const uint32_t sQ = sb;

    const int tid = threadIdx.x, wid = tid >> 5, lane = tid & 31;
    const int qt = gridDim.x - 1 - blockIdx.x;    // heavy q-tiles first
    const int h = blockIdx.y, b = blockIdx.z;
    const size_t hb = ((size_t)(b * H_ + h)) * T_ * 64;
    const int ktmax = 2 * (qt + 1);               // >= 2

    // Stage Q tile (128 rows x 8 x 16B)
    #pragma unroll
    for (int it = 0; it < 4; it++) {
        int i = tid + it * 256;
        int row = i >> 3, c = i & 7;
        uint32_t dst = sQ + row * 128 + ((c ^ (row & 7)) << 4);
        CP_ASYNC16(dst, qh + hb + (size_t)(qt * 128 + row) * 64 + c * 8);
    }
    CP_COMMIT();                                   // g0: Q
    kv_load(sb, kh, vh, hb, 0, tid);
    CP_COMMIT();                                   // g1: KV0
    kv_load(sb, kh, vh, hb, 1, tid);
    CP_COMMIT();                                   // g2: KV1

    const int gid = lane >> 2, tig = lane & 3;
    const int arow   = wid * 16 + (lane & 15);
    const int acadd  = lane >> 4;
    const int kbrow  = (lane & 7) + ((lane >> 4) << 3);
    const int kbcadd = (lane >> 3) & 1;
    const int vbrow  = (lane & 7) + (((lane >> 3) & 1) << 3);
    const int vbcadd = lane >> 4;

    // Q fragments (loop-invariant), hoisted after g0 lands
    CP_WAIT2();
    __syncthreads();
    uint32_t aq[4][4];
    #pragma unroll
    for (int ks = 0; ks < 4; ks++) {
        const int c16 = ks * 2 + acadd;
        uint32_t ad = sQ + arow * 128 + ((c16 ^ (arow & 7)) << 4);
        LDSM_X4(aq[ks][0], aq[ks][1], aq[ks][2], aq[ks][3], ad);
    }

    float m0 = -1e30f, m1 = -1e30f, l0 = 0.f, l1 = 0.f;
    float O[8][4];
    #pragma unroll
    for (int d = 0; d < 8; d++)
        #pragma unroll
        for (int j = 0; j < 4; j++) O[d][j] = 0.f;

    const int rg0 = qt * 128 + wid * 16 + gid;

    for (int kt = 0; kt < ktmax; kt++) {
        CP_WAIT1();
        __syncthreads();

        const uint32_t stage = sb + 16384 + (kt % 3) * 16384;
        const uint32_t sKh = stage, sVh = stage + 8192;

        const bool active = (kt * 64) <= (qt * 128 + wid * 16 + 15);
        if (active) {
            // ---- S = QK^T (single pass) ----
            float S[8][4];
            #pragma unroll
            for (int nt = 0; nt < 8; nt++)
                #pragma unroll
                for (int j = 0; j < 4; j++) S[nt][j] = 0.f;

            #pragma unroll
            for (int ks = 0; ks < 4; ks++) {
                const int c16 = ks * 2;
                uint32_t bh[4][4];
                #pragma unroll
                for (int jn = 0; jn < 4; jn++) {
                    const int row = jn * 16 + kbrow;
                    const int cc  = c16 + kbcadd;
                    uint32_t ad = sKh + row * 128 + ((cc ^ (row & 7)) << 4);
                    LDSM_X4(bh[jn][0], bh[jn][1], bh[jn][2], bh[jn][3], ad);
                }
                #pragma unroll
                for (int nt = 0; nt < 8; nt++)
                    MMAH(S[nt], aq[ks],
                         bh[nt >> 1][(nt & 1) * 2],
                         bh[nt >> 1][(nt & 1) * 2 + 1]);
            }

            // ---- causal mask (diagonal tiles only) ----
            if (kt >= 2 * qt) {
                #pragma unroll
                for (int nt = 0; nt < 8; nt++) {
                    const int jg = kt * 64 + nt * 8 + tig * 2;
                    if (jg     > rg0)     S[nt][0] = -1e30f;
                    if (jg + 1 > rg0)     S[nt][1] = -1e30f;
                    if (jg     > rg0 + 8) S[nt][2] = -1e30f;
                    if (jg + 1 > rg0 + 8) S[nt][3] = -1e30f;
                }
            }

            // ---- online softmax ----
            float t0 = -1e30f, t1 = -1e30f;
            #pragma unroll
            for (int nt = 0; nt < 8; nt++) {
                t0 = fmaxf(t0, fmaxf(S[nt][0], S[nt][1]));
                t1 = fmaxf(t1, fmaxf(S[nt][2], S[nt][3]));
            }
            t0 = fmaxf(t0, __shfl_xor_sync(0xffffffffu, t0, 1));
            t0 = fmaxf(t0, __shfl_xor_sync(0xffffffffu, t0, 2));
            t1 = fmaxf(t1, __shfl_xor_sync(0xffffffffu, t1, 1));
            t1 = fmaxf(t1, __shfl_xor_sync(0xffffffffu, t1, 2));
            const float mn0 = fmaxf(m0, t0), mn1 = fmaxf(m1, t1);
            const float a0 = __expf(m0 - mn0), a1 = __expf(m1 - mn1);
            m0 = mn0; m1 = mn1;
            l0 *= a0;  l1 *= a1;
            #pragma unroll
            for (int d = 0; d < 8; d++) {
                O[d][0] *= a0; O[d][1] *= a0;
                O[d][2] *= a1; O[d][3] *= a1;
            }

            // ---- P = exp(S-m), single fp16 A-fragments ----
            uint32_t pf[4][4];
            #pragma unroll
            for (int nt = 0; nt < 8; nt++) {
                const float p0 = __expf(S[nt][0] - m0);
                const float p1 = __expf(S[nt][1] - m0);
                const float p2 = __expf(S[nt][2] - m1);
                const float p3 = __expf(S[nt][3] - m1);
                l0 += p0 + p1;
                l1 += p2 + p3;
                const int jb = nt >> 1, o = (nt & 1) * 2;
                pf[jb][o]     = pack_h2(__float2half(p0), __float2half(p1));
                pf[jb][o + 1] = pack_h2(__float2half(p2), __float2half(p3));
            }

            // ---- O += P @ V (single pass) ----
            #pragma unroll
            for (int jb = 0; jb < 4; jb++) {
                #pragma unroll
                for (int dp = 0; dp < 4; dp++) {
                    const int row = jb * 16 + vbrow;
                    const int cc  = dp * 2 + vbcadd;
                    uint32_t vv[4];
                    uint32_t ad = sVh + row * 128 + ((cc ^ (row & 7)) << 4);
                    LDSM_X4T(vv[0], vv[1], vv[2], vv[3], ad);
                    const int d0 = dp * 2;
                    MMAH(O[d0],     pf[jb], vv[0], vv[1]);
                    MMAH(O[d0 + 1], pf[jb], vv[2], vv[3]);
                }
            }
        }

        if (kt + 2 < ktmax)
            kv_load(sb, kh, vh, hb, kt + 2, tid);
        CP_COMMIT();
    }

    // ---- epilogue: normalize + write fp16 ----
    l0 += __shfl_xor_sync(0xffffffffu, l0, 1);
    l0 += __shfl_xor_sync(0xffffffffu, l0, 2);
    l1 += __shfl_xor_sync(0xffffffffu, l1, 1);
    l1 += __shfl_xor_sync(0xffffffffu, l1, 2);
    const float inv0 = 1.f / l0, inv1 = 1.f / l1;

    const size_t row0 = (size_t)(b * T_ + rg0) * C_;
    const size_t row1 = row0 + (size_t)8 * C_;
    #pragma unroll
    for (int d = 0; d < 8; d++) {
        const int c = h * 64 + d * 8 + tig * 2;
        *reinterpret_cast<uint32_t*>(yh + row0 + c) =
            pack_h2(__float2half(O[d][0] * inv0), __float2half(O[d][1] * inv0));
        *reinterpret_cast<uint32_t*>(yh + row1 + c) =
            pack_h2(__float2half(O[d][2] * inv1), __float2half(O[d][3] * inv1));
    }
}

// ---------------------------------------------------------------------------
extern "C" void kernel_launch(void* const* d_in, const int* in_sizes, int n_in,
                              void* d_out, int out_size)
{
    const float* x     = (const float*)d_in[0];
    const float* wkqv  = (const float*)d_in[1];
    const float* wproj = (const float*)d_in[2];
    const float* bproj = (const float*)d_in[3];
    float* out = (float*)d_out;

    __half *xh, *w1h, *yh, *w2h, *qh, *kh, *vh;
    cudaGetSymbolAddress((void**)&xh,  g_xh);
    cudaGetSymbolAddress((void**)&w1h, g_w1h);
    cudaGetSymbolAddress((void**)&yh,  g_yh);
    cudaGetSymbolAddress((void**)&w2h, g_w2h);
    cudaGetSymbolAddress((void**)&qh,  g_qh);
    cudaGetSymbolAddress((void**)&kh,  g_kh);
    cudaGetSymbolAddress((void**)&vh,  g_vh);

    cudaFuncSetAttribute((const void*)gemm_mma<1>,
                         cudaFuncAttributeMaxDynamicSharedMemorySize, SMEM_TOTAL);
    cudaFuncSetAttribute((const void*)gemm_mma<2>,
                         cudaFuncAttributeMaxDynamicSharedMemorySize, SMEM_TOTAL);
    cudaFuncSetAttribute((const void*)attn_mma,
                         cudaFuncAttributeMaxDynamicSharedMemorySize, ATT_SMEM);

    // Prep (x convert + merged weight transposes)
    cvth<<<(BT_ * C_ / 4 + 255) / 256, 256>>>(x, xh, BT_ * C_ / 4);
    tconvh2<<<dim3(128, 32), dim3(32, 8)>>>(wkqv, w1h, wproj, w2h);

    // 1) QKV GEMM (single-pass fp16, 256x128 tile) with fused split epilogue
    {
        dim3 grid(C3_ / GBN, BT_ / GBM);   // (24, 16)
        gemm_mma<1><<<grid, 256, SMEM_TOTAL>>>(
            (const uint16_t*)xh, (const uint16_t*)w1h,
            nullptr, nullptr, qh, kh, vh, BT_, C3_, C_);
    }

    // 2) MMA flash attention (single-pass fp16, occ 2) -> yh
    {
        dim3 grid(T_ / 128, H_, B_);       // (16, 16, 2)
        attn_mma<<<grid, 256, ATT_SMEM>>>(qh, kh, vh, yh);
    }

    // 3) proj GEMM (single-pass fp16, 256x128 tile) + bias -> out
    {
        dim3 grid(C_ / GBN, BT_ / GBM);    // (8, 16)
        gemm_mma<2><<<grid, 256, SMEM_TOTAL>>>(
            (const uint16_t*)yh, (const uint16_t*)w2h,
            bproj, out, nullptr, nullptr, nullptr, BT_, C_, C_);
    }
}

// round 14
// speedup vs baseline: 10.3711x; 1.0179x over previous
#include <cuda_runtime.h>
#include <cuda_bf16.h>
#include <cuda_fp16.h>
#include <cstdint>

// Problem constants (fixed by the reference)
#define B_   2
#define T_   2048
#define C_   1024
#define H_   16
#define HS_  64
#define C3_  3072
#define BT_  (B_*T_)          // 4096 rows

// q pre-scale: 1/sqrt(64) * log2(e)  -> softmax runs in exp2 domain
#define QSCALE 0.18033688011112042f

// ---------------------------------------------------------------------------
// Scratch (device globals — no runtime allocation allowed)
// ---------------------------------------------------------------------------
__device__ __half g_xh [(size_t)BT_ * C_];     // x fp16
__device__ __half g_w1h[(size_t)C3_ * C_];     // W_kqv^T [N,K] fp16
__device__ __half g_yh [(size_t)BT_ * C_];     // attn out fp16
__device__ __half g_w2h[(size_t)C_  * C_];     // W_proj^T [N,K] fp16

// per-head attention operands [B, H, T, 64] fp16
#define NHE ((size_t)B_ * H_ * T_ * 64)
__device__ __half g_qh[NHE];                   // q fp16, pre-scaled QSCALE
__device__ __half g_kh[NHE], g_vh[NHE];        // k, v fp16

// ---------------------------------------------------------------------------
// PTX helpers (no 'a'-gated instructions)
// ---------------------------------------------------------------------------
__device__ __forceinline__ uint32_t smem_u32(const void* p) {
    uint32_t a;
    asm("{ .reg .u64 t; cvta.to.shared.u64 t, %1; cvt.u32.u64 %0, t; }"
        : "=r"(a) : "l"(p));
    return a;
}

#define CP_ASYNC16(dst, src) \
    asm volatile("cp.async.cg.shared.global [%0], [%1], 16;" \
                 :: "r"(dst), "l"(src) : "memory")
#define CP_COMMIT() asm volatile("cp.async.commit_group;" ::: "memory")
#define CP_WAIT1()  asm volatile("cp.async.wait_group 1;" ::: "memory")
#define CP_WAIT2()  asm volatile("cp.async.wait_group 2;" ::: "memory")

#define LDSM_X4(r0, r1, r2, r3, addr) \
    asm volatile("ldmatrix.sync.aligned.m8n8.x4.shared.b16 {%0,%1,%2,%3}, [%4];" \
                 : "=r"(r0), "=r"(r1), "=r"(r2), "=r"(r3) : "r"(addr))
#define LDSM_X4T(r0, r1, r2, r3, addr) \
    asm volatile("ldmatrix.sync.aligned.m8n8.x4.trans.shared.b16 {%0,%1,%2,%3}, [%4];" \
                 : "=r"(r0), "=r"(r1), "=r"(r2), "=r"(r3) : "r"(addr))

#define MMAH(c, a, b0, b1) \
    asm volatile("mma.sync.aligned.m16n8k16.row.col.f32.f16.f16.f32 " \
                 "{%0,%1,%2,%3}, {%4,%5,%6,%7}, {%8,%9}, {%0,%1,%2,%3};" \
                 : "+f"((c)[0]), "+f"((c)[1]), "+f"((c)[2]), "+f"((c)[3]) \
                 : "r"((a)[0]), "r"((a)[1]), "r"((a)[2]), "r"((a)[3]), \
                   "r"(b0), "r"(b1))

__device__ __forceinline__ uint32_t pack_h2(__half a, __half b) {
    __half2 t = __halves2half2(a, b);
    return *reinterpret_cast<uint32_t*>(&t);
}
// Single-instruction f32x2 -> f16x2 pack
__device__ __forceinline__ uint32_t pack2(float a, float b) {
    __half2 t = __floats2half2_rn(a, b);
    return *reinterpret_cast<uint32_t*>(&t);
}

// ---------------------------------------------------------------------------
// Prep 1: x fp32 -> fp16
// ---------------------------------------------------------------------------
__global__ __launch_bounds__(256)
void cvth(const float* __restrict__ in, __half* __restrict__ out, int total4)
{
    int i = blockIdx.x * blockDim.x + threadIdx.x;
    if (i >= total4) return;
    float4 v = reinterpret_cast<const float4*>(in)[i];
    reinterpret_cast<uint2*>(out)[i] =
        make_uint2(pack2(v.x, v.y), pack2(v.z, v.w));
}

// ---------------------------------------------------------------------------
// Prep 2 (merged): both weight transposes in one launch.
// ---------------------------------------------------------------------------
__global__ __launch_bounds__(256)
void tconvh2(const float* __restrict__ W1, __half* __restrict__ O1,
             const float* __restrict__ W2, __half* __restrict__ O2)
{
    __shared__ float t[32][33];
    const bool second = blockIdx.x >= 96;
    const float* W  = second ? W2 : W1;
    __half* out     = second ? O2 : O1;
    const int N     = second ? C_ : C3_;
    const int K     = C_;
    const int n0 = (second ? (blockIdx.x - 96) : blockIdx.x) * 32;
    const int k0 = blockIdx.y * 32;
    const int tx = threadIdx.x, ty = threadIdx.y;
    #pragma unroll
    for (int r = 0; r < 4; r++)
        t[ty + 8 * r][tx] = W[(size_t)(k0 + ty + 8 * r) * N + n0 + tx];
    __syncthreads();
    #pragma unroll
    for (int r = 0; r < 4; r++) {
        const int n = n0 + ty + 8 * r, k = k0 + tx;
        out[(size_t)n * K + k] = __float2half(t[tx][ty + 8 * r]);
    }
}

// ---------------------------------------------------------------------------
// fp16 GEMM: C = A @ B^T. CTA tile 256x128, warp tile 64x64, occ 1, 3-stage.
// EPI 1: QKV per-head split epilogue (q scaled into exp2 domain).
// EPI 2: bias + fp32 store.
// ---------------------------------------------------------------------------
#define GBM 256
#define GBN 128
#define GBK 64
#define STG_S 49152                   // A 32K + B 16K
#define SMEM_TOTAL (3 * STG_S)        // 144KB, 1 CTA/SM

template<int ROWS>
__device__ __forceinline__ void load_tile_async(
    uint32_t s_base, const uint16_t* __restrict__ g,
    int ld, int row0, int k0, int tid)
{
    #pragma unroll
    for (int it = 0; it < ROWS / 32; it++) {
        int i = tid + it * 256;
        int row = i >> 3, c = i & 7;
        uint32_t dst = s_base + row * 128 + (((c ^ (row & 7))) << 4);
        const uint16_t* src = g + (size_t)(row0 + row) * ld + k0 + c * 8;
        CP_ASYNC16(dst, src);
    }
}

template<int EPI>
__global__ __launch_bounds__(256, 1)
void gemm_mma(const uint16_t* __restrict__ A,
              const uint16_t* __restrict__ Bt,
              const float* __restrict__ bias, float* __restrict__ C,
              __half* __restrict__ qh, __half* __restrict__ kh,
              __half* __restrict__ vh,
              int M, int N, int K)
{
    extern __shared__ char sm[];
    const uint32_t sbase = smem_u32(sm);
    const int tid = threadIdx.x;
    const int wid = tid >> 5, lane = tid & 31;
    const int wm = wid >> 1, wn = wid & 1;        // 4 x 2 warp grid
    const int m0 = blockIdx.y * GBM, n0 = blockIdx.x * GBN;

    float acc[4][8][4];                            // 64x64 warp tile
    #pragma unroll
    for (int mt = 0; mt < 4; mt++)
        #pragma unroll
        for (int nt = 0; nt < 8; nt++)
            #pragma unroll
            for (int j = 0; j < 4; j++) acc[mt][nt][j] = 0.f;

    const int nchunks = K / GBK;    // 16

    #pragma unroll
    for (int s = 0; s < 2; s++) {
        const uint32_t st = sbase + s * STG_S;
        load_tile_async<GBM>(st,         A,  K, m0, s * GBK, tid);
        load_tile_async<GBN>(st + 32768, Bt, K, n0, s * GBK, tid);
        CP_COMMIT();
    }

    const int a_row  = wm * 64 + (lane & 15);
    const int a_cadd = (lane >> 4);
    const int b_row  = wn * 64 + (lane & 7) + ((lane >> 4) << 3);
    const int b_cadd = (lane >> 3) & 1;

    for (int ch = 0; ch < nchunks; ch++) {
        CP_WAIT1();
        __syncthreads();

        const uint32_t st = sbase + (ch % 3) * STG_S;
        const uint32_t sA = st, sB = st + 32768;

        #pragma unroll
        for (int ks = 0; ks < 4; ks++) {
            const int c16 = ks * 2;
            uint32_t a[4][4];
            #pragma unroll
            for (int mt = 0; mt < 4; mt++) {
                const int row = a_row + mt * 16;
                const int cc  = c16 + a_cadd;
                const uint32_t ad = sA + row * 128 + ((cc ^ (row & 7)) << 4);
                LDSM_X4(a[mt][0], a[mt][1], a[mt][2], a[mt][3], ad);
            }
            uint32_t b[4][4];
            #pragma unroll
            for (int ntp = 0; ntp < 4; ntp++) {
                const int row = b_row + ntp * 16;
                const int cc  = c16 + b_cadd;
                const uint32_t ad = sB + row * 128 + ((cc ^ (row & 7)) << 4);
                LDSM_X4(b[ntp][0], b[ntp][1], b[ntp][2], b[ntp][3], ad);
            }
            #pragma unroll
            for (int mt = 0; mt < 4; mt++)
                #pragma unroll
                for (int nt = 0; nt < 8; nt++)
                    MMAH(acc[mt][nt], a[mt],
                         b[nt >> 1][(nt & 1) * 2],
                         b[nt >> 1][(nt & 1) * 2 + 1]);
        }

        if (ch + 2 < nchunks) {
            const uint32_t nb = sbase + ((ch + 2) % 3) * STG_S;
            load_tile_async<GBM>(nb,         A,  K, m0, (ch + 2) * GBK, tid);
            load_tile_async<GBN>(nb + 32768, Bt, K, n0, (ch + 2) * GBK, tid);
        }
        CP_COMMIT();
    }

    const int gid = lane >> 2, tig = lane & 3;

    if (EPI == 2) {
        #pragma unroll
        for (int mt = 0; mt < 4; mt++) {
            #pragma unroll
            for (int nt = 0; nt < 8; nt++) {
                const int col = n0 + wn * 64 + nt * 8 + tig * 2;
                const float bx = bias[col], by = bias[col + 1];
                const int r0 = m0 + wm * 64 + mt * 16 + gid;
                float2 v0 = { acc[mt][nt][0] + bx, acc[mt][nt][1] + by };
                float2 v1 = { acc[mt][nt][2] + bx, acc[mt][nt][3] + by };
                *reinterpret_cast<float2*>(&C[(size_t)r0 * N + col])       = v0;
                *reinterpret_cast<float2*>(&C[(size_t)(r0 + 8) * N + col]) = v1;
            }
        }
    } else {  // EPI == 1: QKV per-head split epilogue (single fp16)
        #pragma unroll
        for (int mt = 0; mt < 4; mt++) {
            #pragma unroll
            for (int nt = 0; nt < 8; nt++) {
                const int col   = n0 + wn * 64 + nt * 8 + tig * 2;
                const int which = col >> 10;            // 0=q 1=k 2=v
                const int hh    = (col >> 6) & 15;
                const int d     = col & 63;
                const float sc  = (which == 0) ? QSCALE : 1.0f;
                __half* p = (which == 0) ? qh : (which == 1) ? kh : vh;
                #pragma unroll
                for (int rr = 0; rr < 2; rr++) {
                    const int r  = m0 + wm * 64 + mt * 16 + gid + rr * 8;
                    const int bb = r >> 11, t = r & 2047;
                    const size_t off = (((size_t)(bb * 16 + hh)) * 2048 + t) * 64 + d;
                    *reinterpret_cast<uint32_t*>(p + off) =
                        pack2(acc[mt][nt][rr * 2 + 0] * sc,
                              acc[mt][nt][rr * 2 + 1] * sc);
                }
            }
        }
    }
}

// ---------------------------------------------------------------------------
// MMA flash attention, single-pass fp16, 3-stage cp.async K/V pipeline.
// Softmax in exp2 domain (q pre-scaled by 1/8*log2e). occ 2.
// smem: Q 16K | 3 x (Kh 8K, Vh 8K) = 64KB
// ---------------------------------------------------------------------------
#define ATT_SMEM (16384 + 3 * 16384)

__device__ __forceinline__ void kv_load(uint32_t sb,
    const __half* __restrict__ kh, const __half* __restrict__ vh,
    size_t hb, int kt, int tid)
{
    const uint32_t stage = sb + 16384 + (kt % 3) * 16384;
    #pragma unroll
    for (int it = 0; it < 4; it++) {
        int i = tid + (it & 1) * 256;            // 0..511
        int row = i >> 3, c = i & 7;
        const __half* g = (it < 2) ? kh : vh;
        uint32_t dst = stage + ((it < 2) ? 0 : 8192)
                     + row * 128 + ((c ^ (row & 7)) << 4);
        CP_ASYNC16(dst, g + hb + (size_t)(kt * 64 + row) * 64 + c * 8);
    }
}

__global__ __launch_bounds__(256, 2)
void attn_mma(const __half* __restrict__ qh,
              const __half* __restrict__ kh, const __half* __restrict__ vh,
              __half* __restrict__ yh)
{
    extern __shared__ char sm[];
    const uint32_t sb = smem_u32(sm);
    const uint32_t sQ = sb;

    const int tid = threadIdx.x, wid = tid >> 5, lane = tid & 31;
    const int qt = gridDim.x - 1 - blockIdx.x;    // heavy q-tiles first
    const int h = blockIdx.y, b = blockIdx.z;
    const size_t hb = ((size_t)(b * H_ + h)) * T_ * 64;
    const int ktmax = 2 * (qt + 1);               // >= 2

    // Stage Q tile (128 rows x 8 x 16B)
    #pragma unroll
    for (int it = 0; it < 4; it++) {
        int i = tid + it * 256;
        int row = i >> 3, c = i & 7;
        uint32_t dst = sQ + row * 128 + ((c ^ (row & 7)) << 4);
        CP_ASYNC16(dst, qh + hb + (size_t)(qt * 128 + row) * 64 + c * 8);
    }
    CP_COMMIT();                                   // g0: Q
    kv_load(sb, kh, vh, hb, 0, tid);
    CP_COMMIT();                                   // g1: KV0
    kv_load(sb, kh, vh, hb, 1, tid);
    CP_COMMIT();                                   // g2: KV1

    const int gid = lane >> 2, tig = lane & 3;
    const int arow   = wid * 16 + (lane & 15);
    const int acadd  = lane >> 4;
    const int kbrow  = (lane & 7) + ((lane >> 4) << 3);
    const int kbcadd = (lane >> 3) & 1;
    const int vbrow  = (lane & 7) + (((lane >> 3) & 1) << 3);
    const int vbcadd = lane >> 4;

    // Q fragments (loop-invariant), hoisted after g0 lands
    CP_WAIT2();
    __syncthreads();
    uint32_t aq[4][4];
    #pragma unroll
    for (int ks = 0; ks < 4; ks++) {
        const int c16 = ks * 2 + acadd;
        uint32_t ad = sQ + arow * 128 + ((c16 ^ (arow & 7)) << 4);
        LDSM_X4(aq[ks][0], aq[ks][1], aq[ks][2], aq[ks][3], ad);
    }

    float m0 = -1e30f, m1 = -1e30f, l0 = 0.f, l1 = 0.f;
    float O[8][4];
    #pragma unroll
    for (int d = 0; d < 8; d++)
        #pragma unroll
        for (int j = 0; j < 4; j++) O[d][j] = 0.f;

    const int rg0 = qt * 128 + wid * 16 + gid;

    for (int kt = 0; kt < ktmax; kt++) {
        CP_WAIT1();
        __syncthreads();

        const uint32_t stage = sb + 16384 + (kt % 3) * 16384;
        const uint32_t sKh = stage, sVh = stage + 8192;

        const bool active = (kt * 64) <= (qt * 128 + wid * 16 + 15);
        if (active) {
            // ---- S = QK^T (exp2 domain) ----
            float S[8][4];
            #pragma unroll
            for (int nt = 0; nt < 8; nt++)
                #pragma unroll
                for (int j = 0; j < 4; j++) S[nt][j] = 0.f;

            #pragma unroll
            for (int ks = 0; ks < 4; ks++) {
                const int c16 = ks * 2;
                uint32_t bh[4][4];
                #pragma unroll
                for (int jn = 0; jn < 4; jn++) {
                    const int row = jn * 16 + kbrow;
                    const int cc  = c16 + kbcadd;
                    uint32_t ad = sKh + row * 128 + ((cc ^ (row & 7)) << 4);
                    LDSM_X4(bh[jn][0], bh[jn][1], bh[jn][2], bh[jn][3], ad);
                }
                #pragma unroll
                for (int nt = 0; nt < 8; nt++)
                    MMAH(S[nt], aq[ks],
                         bh[nt >> 1][(nt & 1) * 2],
                         bh[nt >> 1][(nt & 1) * 2 + 1]);
            }

            // ---- causal mask (diagonal tiles only) ----
            if (kt >= 2 * qt) {
                #pragma unroll
                for (int nt = 0; nt < 8; nt++) {
                    const int jg = kt * 64 + nt * 8 + tig * 2;
                    if (jg     > rg0)     S[nt][0] = -1e30f;
                    if (jg + 1 > rg0)     S[nt][1] = -1e30f;
                    if (jg     > rg0 + 8) S[nt][2] = -1e30f;
                    if (jg + 1 > rg0 + 8) S[nt][3] = -1e30f;
                }
            }

            // ---- online softmax (exp2) ----
            float t0 = -1e30f, t1 = -1e30f;
            #pragma unroll
            for (int nt = 0; nt < 8; nt++) {
                t0 = fmaxf(t0, fmaxf(S[nt][0], S[nt][1]));
                t1 = fmaxf(t1, fmaxf(S[nt][2], S[nt][3]));
            }
            t0 = fmaxf(t0, __shfl_xor_sync(0xffffffffu, t0, 1));
            t0 = fmaxf(t0, __shfl_xor_sync(0xffffffffu, t0, 2));
            t1 = fmaxf(t1, __shfl_xor_sync(0xffffffffu, t1, 1));
            t1 = fmaxf(t1, __shfl_xor_sync(0xffffffffu, t1, 2));
            const float mn0 = fmaxf(m0, t0), mn1 = fmaxf(m1, t1);
            const float a0 = exp2f(m0 - mn0), a1 = exp2f(m1 - mn1);
            m0 = mn0; m1 = mn1;
            l0 *= a0;  l1 *= a1;
            #pragma unroll
            for (int d = 0; d < 8; d++) {
                O[d][0] *= a0; O[d][1] *= a0;
                O[d][2] *= a1; O[d][3] *= a1;
            }

            // ---- P = exp2(S-m), packed-convert fp16 A-fragments ----
            uint32_t pf[4][4];
            #pragma unroll
            for (int nt = 0; nt < 8; nt++) {
                const float p0 = exp2f(S[nt][0] - m0);
                const float p1 = exp2f(S[nt][1] - m0);
                const float p2 = exp2f(S[nt][2] - m1);
                const float p3 = exp2f(S[nt][3] - m1);
                l0 += p0 + p1;
                l1 += p2 + p3;
                const int jb = nt >> 1, o = (nt & 1) * 2;
                pf[jb][o]     = pack2(p0, p1);
                pf[jb][o + 1] = pack2(p2, p3);
            }

            // ---- O += P @ V (single pass) ----
            #pragma unroll
            for (int jb = 0; jb < 4; jb++) {
                #pragma unroll
                for (int dp = 0; dp < 4; dp++) {
                    const int row = jb * 16 + vbrow;
                    const int cc  = dp * 2 + vbcadd;
                    uint32_t vv[4];
                    uint32_t ad = sVh + row * 128 + ((cc ^ (row & 7)) << 4);
                    LDSM_X4T(vv[0], vv[1], vv[2], vv[3], ad);
                    const int d0 = dp * 2;
                    MMAH(O[d0],     pf[jb], vv[0], vv[1]);
                    MMAH(O[d0 + 1], pf[jb], vv[2], vv[3]);
                }
            }
        }

        if (kt + 2 < ktmax)
            kv_load(sb, kh, vh, hb, kt + 2, tid);
        CP_COMMIT();
    }

    // ---- epilogue: normalize + write fp16 ----
    l0 += __shfl_xor_sync(0xffffffffu, l0, 1);
    l0 += __shfl_xor_sync(0xffffffffu, l0, 2);
    l1 += __shfl_xor_sync(0xffffffffu, l1, 1);
    l1 += __shfl_xor_sync(0xffffffffu, l1, 2);
    const float inv0 = 1.f / l0, inv1 = 1.f / l1;

    const size_t row0 = (size_t)(b * T_ + rg0) * C_;
    const size_t row1 = row0 + (size_t)8 * C_;
    #pragma unroll
    for (int d = 0; d < 8; d++) {
        const int c = h * 64 + d * 8 + tig * 2;
        *reinterpret_cast<uint32_t*>(yh + row0 + c) =
            pack2(O[d][0] * inv0, O[d][1] * inv0);
        *reinterpret_cast<uint32_t*>(yh + row1 + c) =
            pack2(O[d][2] * inv1, O[d][3] * inv1);
    }
}

// ---------------------------------------------------------------------------
extern "C" void kernel_launch(void* const* d_in, const int* in_sizes, int n_in,
                              void* d_out, int out_size)
{
    const float* x     = (const float*)d_in[0];
    const float* wkqv  = (const float*)d_in[1];
    const float* wproj = (const float*)d_in[2];
    const float* bproj = (const float*)d_in[3];
    float* out = (float*)d_out;

    __half *xh, *w1h, *yh, *w2h, *qh, *kh, *vh;
    cudaGetSymbolAddress((void**)&xh,  g_xh);
    cudaGetSymbolAddress((void**)&w1h, g_w1h);
    cudaGetSymbolAddress((void**)&yh,  g_yh);
    cudaGetSymbolAddress((void**)&w2h, g_w2h);
    cudaGetSymbolAddress((void**)&qh,  g_qh);
    cudaGetSymbolAddress((void**)&kh,  g_kh);
    cudaGetSymbolAddress((void**)&vh,  g_vh);

    cudaFuncSetAttribute((const void*)gemm_mma<1>,
                         cudaFuncAttributeMaxDynamicSharedMemorySize, SMEM_TOTAL);
    cudaFuncSetAttribute((const void*)gemm_mma<2>,
                         cudaFuncAttributeMaxDynamicSharedMemorySize, SMEM_TOTAL);
    cudaFuncSetAttribute((const void*)attn_mma,
                         cudaFuncAttributeMaxDynamicSharedMemorySize, ATT_SMEM);

    // Prep (x convert + merged weight transposes)
    cvth<<<(BT_ * C_ / 4 + 255) / 256, 256>>>(x, xh, BT_ * C_ / 4);
    tconvh2<<<dim3(128, 32), dim3(32, 8)>>>(wkqv, w1h, wproj, w2h);

    // 1) QKV GEMM (single-pass fp16, 256x128 tile) with fused split epilogue
    {
        dim3 grid(C3_ / GBN, BT_ / GBM);   // (24, 16)
        gemm_mma<1><<<grid, 256, SMEM_TOTAL>>>(
            (const uint16_t*)xh, (const uint16_t*)w1h,
            nullptr, nullptr, qh, kh, vh, BT_, C3_, C_);
    }

    // 2) MMA flash attention (exp2 softmax, occ 2) -> yh
    {
        dim3 grid(T_ / 128, H_, B_);       // (16, 16, 2)
        attn_mma<<<grid, 256, ATT_SMEM>>>(qh, kh, vh, yh);
    }

    // 3) proj GEMM (single-pass fp16, 256x128 tile) + bias -> out
    {
        dim3 grid(C_ / GBN, BT_ / GBM);    // (8, 16)
        gemm_mma<2><<<grid, 256, SMEM_TOTAL>>>(
            (const uint16_t*)yh, (const uint16_t*)w2h,
            bproj, out, nullptr, nullptr, nullptr, BT_, C_, C_);
    }
}

// round 15
// speedup vs baseline: 10.6058x; 1.0226x over previous
#include <cuda_runtime.h>
#include <cuda_bf16.h>
#include <cuda_fp16.h>
#include <cstdint>

// Problem constants (fixed by the reference)
#define B_   2
#define T_   2048
#define C_   1024
#define H_   16
#define HS_  64
#define C3_  3072
#define BT_  (B_*T_)          // 4096 rows

// q pre-scale: 1/sqrt(64) * log2(e)  -> softmax runs in exp2 domain
#define QSCALE 0.18033688011112042f

// ---------------------------------------------------------------------------
// Scratch (device globals — no runtime allocation allowed)
// ---------------------------------------------------------------------------
__device__ __half g_xh [(size_t)BT_ * C_];     // x fp16
__device__ __half g_w1h[(size_t)C3_ * C_];     // W_kqv^T [N,K] fp16
__device__ __half g_yh [(size_t)BT_ * C_];     // attn out fp16
__device__ __half g_w2h[(size_t)C_  * C_];     // W_proj^T [N,K] fp16

// per-head attention operands [B, H, T, 64] fp16
#define NHE ((size_t)B_ * H_ * T_ * 64)
__device__ __half g_qh[NHE];                   // q fp16, pre-scaled QSCALE
__device__ __half g_kh[NHE], g_vh[NHE];        // k, v fp16

// ---------------------------------------------------------------------------
// PTX helpers (no 'a'-gated instructions)
// ---------------------------------------------------------------------------
__device__ __forceinline__ uint32_t smem_u32(const void* p) {
    uint32_t a;
    asm("{ .reg .u64 t; cvta.to.shared.u64 t, %1; cvt.u32.u64 %0, t; }"
        : "=r"(a) : "l"(p));
    return a;
}

#define CP_ASYNC16(dst, src) \
    asm volatile("cp.async.cg.shared.global [%0], [%1], 16;" \
                 :: "r"(dst), "l"(src) : "memory")
#define CP_COMMIT() asm volatile("cp.async.commit_group;" ::: "memory")
#define CP_WAIT1()  asm volatile("cp.async.wait_group 1;" ::: "memory")
#define CP_WAIT2()  asm volatile("cp.async.wait_group 2;" ::: "memory")

#define LDSM_X4(r0, r1, r2, r3, addr) \
    asm volatile("ldmatrix.sync.aligned.m8n8.x4.shared.b16 {%0,%1,%2,%3}, [%4];" \
                 : "=r"(r0), "=r"(r1), "=r"(r2), "=r"(r3) : "r"(addr))
#define LDSM_X4T(r0, r1, r2, r3, addr) \
    asm volatile("ldmatrix.sync.aligned.m8n8.x4.trans.shared.b16 {%0,%1,%2,%3}, [%4];" \
                 : "=r"(r0), "=r"(r1), "=r"(r2), "=r"(r3) : "r"(addr))

#define MMAH(c, a, b0, b1) \
    asm volatile("mma.sync.aligned.m16n8k16.row.col.f32.f16.f16.f32 " \
                 "{%0,%1,%2,%3}, {%4,%5,%6,%7}, {%8,%9}, {%0,%1,%2,%3};" \
                 : "+f"((c)[0]), "+f"((c)[1]), "+f"((c)[2]), "+f"((c)[3]) \
                 : "r"((a)[0]), "r"((a)[1]), "r"((a)[2]), "r"((a)[3]), \
                   "r"(b0), "r"(b1))

__device__ __forceinline__ uint32_t pack2(float a, float b) {
    __half2 t = __floats2half2_rn(a, b);
    return *reinterpret_cast<uint32_t*>(&t);
}

// ---------------------------------------------------------------------------
// Prep 1: x fp32 -> fp16
// ---------------------------------------------------------------------------
__global__ __launch_bounds__(256)
void cvth(const float* __restrict__ in, __half* __restrict__ out, int total4)
{
    int i = blockIdx.x * blockDim.x + threadIdx.x;
    if (i >= total4) return;
    float4 v = reinterpret_cast<const float4*>(in)[i];
    reinterpret_cast<uint2*>(out)[i] =
        make_uint2(pack2(v.x, v.y), pack2(v.z, v.w));
}

// ---------------------------------------------------------------------------
// Prep 2 (merged): both weight transposes in one launch.
// ---------------------------------------------------------------------------
__global__ __launch_bounds__(256)
void tconvh2(const float* __restrict__ W1, __half* __restrict__ O1,
             const float* __restrict__ W2, __half* __restrict__ O2)
{
    __shared__ float t[32][33];
    const bool second = blockIdx.x >= 96;
    const float* W  = second ? W2 : W1;
    __half* out     = second ? O2 : O1;
    const int N     = second ? C_ : C3_;
    const int K     = C_;
    const int n0 = (second ? (blockIdx.x - 96) : blockIdx.x) * 32;
    const int k0 = blockIdx.y * 32;
    const int tx = threadIdx.x, ty = threadIdx.y;
    #pragma unroll
    for (int r = 0; r < 4; r++)
        t[ty + 8 * r][tx] = W[(size_t)(k0 + ty + 8 * r) * N + n0 + tx];
    __syncthreads();
    #pragma unroll
    for (int r = 0; r < 4; r++) {
        const int n = n0 + ty + 8 * r, k = k0 + tx;
        out[(size_t)n * K + k] = __float2half(t[tx][ty + 8 * r]);
    }
}

// ---------------------------------------------------------------------------
// fp16 GEMM: C = A @ B^T. CTA tile 256x128, warp tile 64x64, occ 1,
// 4-stage cp.async pipeline (192KB smem).
// EPI 1: QKV per-head split epilogue (q scaled into exp2 domain).
// EPI 2: bias + fp32 store.
// ---------------------------------------------------------------------------
#define GBM 256
#define GBN 128
#define GBK 64
#define STG_S 49152                   // A 32K + B 16K
#define NSTG 4
#define SMEM_TOTAL (NSTG * STG_S)     // 192KB, 1 CTA/SM

template<int ROWS>
__device__ __forceinline__ void load_tile_async(
    uint32_t s_base, const uint16_t* __restrict__ g,
    int ld, int row0, int k0, int tid)
{
    #pragma unroll
    for (int it = 0; it < ROWS / 32; it++) {
        int i = tid + it * 256;
        int row = i >> 3, c = i & 7;
        uint32_t dst = s_base + row * 128 + (((c ^ (row & 7))) << 4);
        const uint16_t* src = g + (size_t)(row0 + row) * ld + k0 + c * 8;
        CP_ASYNC16(dst, src);
    }
}

template<int EPI>
__global__ __launch_bounds__(256, 1)
void gemm_mma(const uint16_t* __restrict__ A,
              const uint16_t* __restrict__ Bt,
              const float* __restrict__ bias, float* __restrict__ C,
              __half* __restrict__ qh, __half* __restrict__ kh,
              __half* __restrict__ vh,
              int M, int N, int K)
{
    extern __shared__ char sm[];
    const uint32_t sbase = smem_u32(sm);
    const int tid = threadIdx.x;
    const int wid = tid >> 5, lane = tid & 31;
    const int wm = wid >> 1, wn = wid & 1;        // 4 x 2 warp grid
    const int m0 = blockIdx.y * GBM, n0 = blockIdx.x * GBN;

    float acc[4][8][4];                            // 64x64 warp tile
    #pragma unroll
    for (int mt = 0; mt < 4; mt++)
        #pragma unroll
        for (int nt = 0; nt < 8; nt++)
            #pragma unroll
            for (int j = 0; j < 4; j++) acc[mt][nt][j] = 0.f;

    const int nchunks = K / GBK;    // 16

    // Prologue: stages 0,1,2
    #pragma unroll
    for (int s = 0; s < 3; s++) {
        const uint32_t st = sbase + s * STG_S;
        load_tile_async<GBM>(st,         A,  K, m0, s * GBK, tid);
        load_tile_async<GBN>(st + 32768, Bt, K, n0, s * GBK, tid);
        CP_COMMIT();
    }

    const int a_row  = wm * 64 + (lane & 15);
    const int a_cadd = (lane >> 4);
    const int b_row  = wn * 64 + (lane & 7) + ((lane >> 4) << 3);
    const int b_cadd = (lane >> 3) & 1;

    for (int ch = 0; ch < nchunks; ch++) {
        CP_WAIT2();
        __syncthreads();

        const uint32_t st = sbase + (ch % NSTG) * STG_S;
        const uint32_t sA = st, sB = st + 32768;

        #pragma unroll
        for (int ks = 0; ks < 4; ks++) {
            const int c16 = ks * 2;
            uint32_t a[4][4];
            #pragma unroll
            for (int mt = 0; mt < 4; mt++) {
                const int row = a_row + mt * 16;
                const int cc  = c16 + a_cadd;
                const uint32_t ad = sA + row * 128 + ((cc ^ (row & 7)) << 4);
                LDSM_X4(a[mt][0], a[mt][1], a[mt][2], a[mt][3], ad);
            }
            uint32_t b[4][4];
            #pragma unroll
            for (int ntp = 0; ntp < 4; ntp++) {
                const int row = b_row + ntp * 16;
                const int cc  = c16 + b_cadd;
                const uint32_t ad = sB + row * 128 + ((cc ^ (row & 7)) << 4);
                LDSM_X4(b[ntp][0], b[ntp][1], b[ntp][2], b[ntp][3], ad);
            }
            #pragma unroll
            for (int mt = 0; mt < 4; mt++)
                #pragma unroll
                for (int nt = 0; nt < 8; nt++)
                    MMAH(acc[mt][nt], a[mt],
                         b[nt >> 1][(nt & 1) * 2],
                         b[nt >> 1][(nt & 1) * 2 + 1]);
        }

        if (ch + 3 < nchunks) {
            const uint32_t nb = sbase + ((ch + 3) % NSTG) * STG_S;
            load_tile_async<GBM>(nb,         A,  K, m0, (ch + 3) * GBK, tid);
            load_tile_async<GBN>(nb + 32768, Bt, K, n0, (ch + 3) * GBK, tid);
        }
        CP_COMMIT();
    }

    const int gid = lane >> 2, tig = lane & 3;

    if (EPI == 2) {
        #pragma unroll
        for (int mt = 0; mt < 4; mt++) {
            #pragma unroll
            for (int nt = 0; nt < 8; nt++) {
                const int col = n0 + wn * 64 + nt * 8 + tig * 2;
                const float bx = bias[col], by = bias[col + 1];
                const int r0 = m0 + wm * 64 + mt * 16 + gid;
                float2 v0 = { acc[mt][nt][0] + bx, acc[mt][nt][1] + by };
                float2 v1 = { acc[mt][nt][2] + bx, acc[mt][nt][3] + by };
                *reinterpret_cast<float2*>(&C[(size_t)r0 * N + col])       = v0;
                *reinterpret_cast<float2*>(&C[(size_t)(r0 + 8) * N + col]) = v1;
            }
        }
    } else {  // EPI == 1: QKV per-head split epilogue (single fp16)
        #pragma unroll
        for (int mt = 0; mt < 4; mt++) {
            #pragma unroll
            for (int nt = 0; nt < 8; nt++) {
                const int col   = n0 + wn * 64 + nt * 8 + tig * 2;
                const int which = col >> 10;            // 0=q 1=k 2=v
                const int hh    = (col >> 6) & 15;
                const int d     = col & 63;
                const float sc  = (which == 0) ? QSCALE : 1.0f;
                __half* p = (which == 0) ? qh : (which == 1) ? kh : vh;
                #pragma unroll
                for (int rr = 0; rr < 2; rr++) {
                    const int r  = m0 + wm * 64 + mt * 16 + gid + rr * 8;
                    const int bb = r >> 11, t = r & 2047;
                    const size_t off = (((size_t)(bb * 16 + hh)) * 2048 + t) * 64 + d;
                    *reinterpret_cast<uint32_t*>(p + off) =
                        pack2(acc[mt][nt][rr * 2 + 0] * sc,
                              acc[mt][nt][rr * 2 + 1] * sc);
                }
            }
        }
    }
}

// ---------------------------------------------------------------------------
// MMA flash attention, single-pass fp16, 3-stage cp.async K/V pipeline.
// exp2-domain softmax with warp-uniform rescale skipping. occ 2.
// smem: Q 16K | 3 x (Kh 8K, Vh 8K) = 64KB
// ---------------------------------------------------------------------------
#define ATT_SMEM (16384 + 3 * 16384)

__device__ __forceinline__ void kv_load(uint32_t sb,
    const __half* __restrict__ kh, const __half* __restrict__ vh,
    size_t hb, int kt, int tid)
{
    const uint32_t stage = sb + 16384 + (kt % 3) * 16384;
    #pragma unroll
    for (int it = 0; it < 4; it++) {
        int i = tid + (it & 1) * 256;            // 0..511
        int row = i >> 3, c = i & 7;
        const __half* g = (it < 2) ? kh : vh;
        uint32_t dst = stage + ((it < 2) ? 0 : 8192)
                     + row * 128 + ((c ^ (row & 7)) << 4);
        CP_ASYNC16(dst, g + hb + (size_t)(kt * 64 + row) * 64 + c * 8);
    }
}

__global__ __launch_bounds__(256, 2)
void attn_mma(const __half* __restrict__ qh,
              const __half* __restrict__ kh, const __half* __restrict__ vh,
              __half* __restrict__ yh)
{
    extern __shared__ char sm[];
    const uint32_t sb = smem_u32(sm);
    const uint32_t sQ = sb;

    const int tid = threadIdx.x, wid = tid >> 5, lane = tid & 31;
    const int qt = gridDim.x - 1 - blockIdx.x;    // heavy q-tiles first
    const int h = blockIdx.y, b = blockIdx.z;
    const size_t hb = ((size_t)(b * H_ + h)) * T_ * 64;
    const int ktmax = 2 * (qt + 1);               // >= 2

    // Stage Q tile (128 rows x 8 x 16B)
    #pragma unroll
    for (int it = 0; it < 4; it++) {
        int i = tid + it * 256;
        int row = i >> 3, c = i & 7;
        uint32_t dst = sQ + row * 128 + ((c ^ (row & 7)) << 4);
        CP_ASYNC16(dst, qh + hb + (size_t)(qt * 128 + row) * 64 + c * 8);
    }
    CP_COMMIT();                                   // g0: Q
    kv_load(sb, kh, vh, hb, 0, tid);
    CP_COMMIT();                                   // g1: KV0
    kv_load(sb, kh, vh, hb, 1, tid);
    CP_COMMIT();                                   // g2: KV1

    const int gid = lane >> 2, tig = lane & 3;
    const int arow   = wid * 16 + (lane & 15);
    const int acadd  = lane >> 4;
    const int kbrow  = (lane & 7) + ((lane >> 4) << 3);
    const int kbcadd = (lane >> 3) & 1;
    const int vbrow  = (lane & 7) + (((lane >> 3) & 1) << 3);
    const int vbcadd = lane >> 4;

    // Q fragments (loop-invariant), hoisted after g0 lands
    CP_WAIT2();
    __syncthreads();
    uint32_t aq[4][4];
    #pragma unroll
    for (int ks = 0; ks < 4; ks++) {
        const int c16 = ks * 2 + acadd;
        uint32_t ad = sQ + arow * 128 + ((c16 ^ (arow & 7)) << 4);
        LDSM_X4(aq[ks][0], aq[ks][1], aq[ks][2], aq[ks][3], ad);
    }

    float m0 = -1e30f, m1 = -1e30f, l0 = 0.f, l1 = 0.f;
    float O[8][4];
    #pragma unroll
    for (int d = 0; d < 8; d++)
        #pragma unroll
        for (int j = 0; j < 4; j++) O[d][j] = 0.f;

    const int rg0 = qt * 128 + wid * 16 + gid;

    for (int kt = 0; kt < ktmax; kt++) {
        CP_WAIT1();
        __syncthreads();

        const uint32_t stage = sb + 16384 + (kt % 3) * 16384;
        const uint32_t sKh = stage, sVh = stage + 8192;

        const bool active = (kt * 64) <= (qt * 128 + wid * 16 + 15);
        if (active) {
            // ---- S = QK^T (exp2 domain) ----
            float S[8][4];
            #pragma unroll
            for (int nt = 0; nt < 8; nt++)
                #pragma unroll
                for (int j = 0; j < 4; j++) S[nt][j] = 0.f;

            #pragma unroll
            for (int ks = 0; ks < 4; ks++) {
                const int c16 = ks * 2;
                uint32_t bh[4][4];
                #pragma unroll
                for (int jn = 0; jn < 4; jn++) {
                    const int row = jn * 16 + kbrow;
                    const int cc  = c16 + kbcadd;
                    uint32_t ad = sKh + row * 128 + ((cc ^ (row & 7)) << 4);
                    LDSM_X4(bh[jn][0], bh[jn][1], bh[jn][2], bh[jn][3], ad);
                }
                #pragma unroll
                for (int nt = 0; nt < 8; nt++)
                    MMAH(S[nt], aq[ks],
                         bh[nt >> 1][(nt & 1) * 2],
                         bh[nt >> 1][(nt & 1) * 2 + 1]);
            }

            // ---- causal mask (diagonal tiles only) ----
            if (kt >= 2 * qt) {
                #pragma unroll
                for (int nt = 0; nt < 8; nt++) {
                    const int jg = kt * 64 + nt * 8 + tig * 2;
                    if (jg     > rg0)     S[nt][0] = -1e30f;
                    if (jg + 1 > rg0)     S[nt][1] = -1e30f;
                    if (jg     > rg0 + 8) S[nt][2] = -1e30f;
                    if (jg + 1 > rg0 + 8) S[nt][3] = -1e30f;
                }
            }

            // ---- online softmax (exp2), skip rescale when max unchanged ----
            float t0 = -1e30f, t1 = -1e30f;
            #pragma unroll
            for (int nt = 0; nt < 8; nt++) {
                t0 = fmaxf(t0, fmaxf(S[nt][0], S[nt][1]));
                t1 = fmaxf(t1, fmaxf(S[nt][2], S[nt][3]));
            }
            t0 = fmaxf(t0, __shfl_xor_sync(0xffffffffu, t0, 1));
            t0 = fmaxf(t0, __shfl_xor_sync(0xffffffffu, t0, 2));
            t1 = fmaxf(t1, __shfl_xor_sync(0xffffffffu, t1, 1));
            t1 = fmaxf(t1, __shfl_xor_sync(0xffffffffu, t1, 2));
            const float mn0 = fmaxf(m0, t0), mn1 = fmaxf(m1, t1);
            const bool upd = __any_sync(0xffffffffu, (mn0 > m0) | (mn1 > m1));
            if (upd) {
                const float a0 = exp2f(m0 - mn0), a1 = exp2f(m1 - mn1);
                l0 *= a0;  l1 *= a1;
                #pragma unroll
                for (int d = 0; d < 8; d++) {
                    O[d][0] *= a0; O[d][1] *= a0;
                    O[d][2] *= a1; O[d][3] *= a1;
                }
                m0 = mn0; m1 = mn1;
            }

            // ---- P = exp2(S-m), packed-convert fp16 A-fragments ----
            uint32_t pf[4][4];
            #pragma unroll
            for (int nt = 0; nt < 8; nt++) {
                const float p0 = exp2f(S[nt][0] - m0);
                const float p1 = exp2f(S[nt][1] - m0);
                const float p2 = exp2f(S[nt][2] - m1);
                const float p3 = exp2f(S[nt][3] - m1);
                l0 += p0 + p1;
                l1 += p2 + p3;
                const int jb = nt >> 1, o = (nt & 1) * 2;
                pf[jb][o]     = pack2(p0, p1);
                pf[jb][o + 1] = pack2(p2, p3);
            }

            // ---- O += P @ V (single pass) ----
            #pragma unroll
            for (int jb = 0; jb < 4; jb++) {
                #pragma unroll
                for (int dp = 0; dp < 4; dp++) {
                    const int row = jb * 16 + vbrow;
                    const int cc  = dp * 2 + vbcadd;
                    uint32_t vv[4];
                    uint32_t ad = sVh + row * 128 + ((cc ^ (row & 7)) << 4);
                    LDSM_X4T(vv[0], vv[1], vv[2], vv[3], ad);
                    const int d0 = dp * 2;
                    MMAH(O[d0],     pf[jb], vv[0], vv[1]);
                    MMAH(O[d0 + 1], pf[jb], vv[2], vv[3]);
                }
            }
        }

        if (kt + 2 < ktmax)
            kv_load(sb, kh, vh, hb, kt + 2, tid);
        CP_COMMIT();
    }

    // ---- epilogue: normalize + write fp16 ----
    l0 += __shfl_xor_sync(0xffffffffu, l0, 1);
    l0 += __shfl_xor_sync(0xffffffffu, l0, 2);
    l1 += __shfl_xor_sync(0xffffffffu, l1, 1);
    l1 += __shfl_xor_sync(0xffffffffu, l1, 2);
    const float inv0 = 1.f / l0, inv1 = 1.f / l1;

    const size_t row0 = (size_t)(b * T_ + rg0) * C_;
    const size_t row1 = row0 + (size_t)8 * C_;
    #pragma unroll
    for (int d = 0; d < 8; d++) {
        const int c = h * 64 + d * 8 + tig * 2;
        *reinterpret_cast<uint32_t*>(yh + row0 + c) =
            pack2(O[d][0] * inv0, O[d][1] * inv0);
        *reinterpret_cast<uint32_t*>(yh + row1 + c) =
            pack2(O[d][2] * inv1, O[d][3] * inv1);
    }
}

// ---------------------------------------------------------------------------
extern "C" void kernel_launch(void* const* d_in, const int* in_sizes, int n_in,
                              void* d_out, int out_size)
{
    const float* x     = (const float*)d_in[0];
    const float* wkqv  = (const float*)d_in[1];
    const float* wproj = (const float*)d_in[2];
    const float* bproj = (const float*)d_in[3];
    float* out = (float*)d_out;

    __half *xh, *w1h, *yh, *w2h, *qh, *kh, *vh;
    cudaGetSymbolAddress((void**)&xh,  g_xh);
    cudaGetSymbolAddress((void**)&w1h, g_w1h);
    cudaGetSymbolAddress((void**)&yh,  g_yh);
    cudaGetSymbolAddress((void**)&w2h, g_w2h);
    cudaGetSymbolAddress((void**)&qh,  g_qh);
    cudaGetSymbolAddress((void**)&kh,  g_kh);
    cudaGetSymbolAddress((void**)&vh,  g_vh);

    cudaFuncSetAttribute((const void*)gemm_mma<1>,
                         cudaFuncAttributeMaxDynamicSharedMemorySize, SMEM_TOTAL);
    cudaFuncSetAttribute((const void*)gemm_mma<2>,
                         cudaFuncAttributeMaxDynamicSharedMemorySize, SMEM_TOTAL);
    cudaFuncSetAttribute((const void*)attn_mma,
                         cudaFuncAttributeMaxDynamicSharedMemorySize, ATT_SMEM);

    // Prep (x convert + merged weight transposes)
    cvth<<<(BT_ * C_ / 4 + 255) / 256, 256>>>(x, xh, BT_ * C_ / 4);
    tconvh2<<<dim3(128, 32), dim3(32, 8)>>>(wkqv, w1h, wproj, w2h);

    // 1) QKV GEMM (single-pass fp16, 256x128 tile, 4-stage)
    {
        dim3 grid(C3_ / GBN, BT_ / GBM);   // (24, 16)
        gemm_mma<1><<<grid, 256, SMEM_TOTAL>>>(
            (const uint16_t*)xh, (const uint16_t*)w1h,
            nullptr, nullptr, qh, kh, vh, BT_, C3_, C_);
    }

    // 2) MMA flash attention (exp2 softmax + rescale skip, occ 2) -> yh
    {
        dim3 grid(T_ / 128, H_, B_);       // (16, 16, 2)
        attn_mma<<<grid, 256, ATT_SMEM>>>(qh, kh, vh, yh);
    }

    // 3) proj GEMM (single-pass fp16, 256x128 tile, 4-stage) + bias -> out
    {
        dim3 grid(C_ / GBN, BT_ / GBM);    // (8, 16)
        gemm_mma<2><<<grid, 256, SMEM_TOTAL>>>(
            (const uint16_t*)yh, (const uint16_t*)w2h,
            bproj, out, nullptr, nullptr, nullptr, BT_, C_, C_);
    }
}